// round 1
// baseline (speedup 1.0000x reference)
#include <cuda_runtime.h>

#define B_ 8
#define C_ 128
#define N_ 4096

// ---------------- scratch (static device globals; no allocation) ----------------
__device__ float gX[B_ * N_ * C_];    // theta(ref):  [b][n][c]  (queries & values)
__device__ float gY[B_ * N_ * C_];    // phi(cur)^T:  [b][m][c]  (keys, k-major rows)
__device__ float gM[B_ * N_];         // per-column (m) running max of S[:,m]
__device__ float gInvD[B_ * N_];      // 1 / sum_n exp(S[n,m]-M[m])
__device__ float gZ[B_ * N_ * C_];    // attention output [b][n][c]

__device__ __forceinline__ void fma4(float4 &a, float s, const float4 &v) {
    a.x = fmaf(s, v.x, a.x);
    a.y = fmaf(s, v.y, a.y);
    a.z = fmaf(s, v.z, a.z);
    a.w = fmaf(s, v.w, a.w);
}

// ---------------------------------------------------------------------------
// inproj: out[b][n][co] = sum_ci w[co][ci] * in[b][ci][n] + bias[co]
// which==0 -> gX, which==1 -> gY. Block: 32 n-positions x 128 outputs.
// ---------------------------------------------------------------------------
__global__ __launch_bounds__(256) void inproj_kernel(
        const float* __restrict__ in, const float* __restrict__ w,
        const float* __restrict__ bias, int which)
{
    __shared__ float it[C_ * 36];           // it[ci][nl], pad 36 keeps float4 16B-aligned
    float* out = which ? gY : gX;
    int b = blockIdx.y, n0 = blockIdx.x * 32;
    int tid = threadIdx.x;

    for (int i = tid; i < C_ * 32; i += 256) {
        int ci = i >> 5, nl = i & 31;
        it[ci * 36 + nl] = in[(b * C_ + ci) * N_ + n0 + nl];   // coalesced gmem, clean STS
    }
    __syncthreads();

    int co = tid >> 1, nlh = (tid & 1) * 16;   // each thread: 1 co x 16 n
    float bv = bias[co];
    float4 acc[4];
#pragma unroll
    for (int q = 0; q < 4; q++) acc[q] = make_float4(bv, bv, bv, bv);

#pragma unroll 4
    for (int ci = 0; ci < C_; ci++) {
        float wv = __ldg(w + co * C_ + ci);                     // L1-resident weight
        const float4* zr = (const float4*)(it + ci * 36 + nlh); // broadcast LDS.128
#pragma unroll
        for (int q = 0; q < 4; q++) fma4(acc[q], wv, zr[q]);
    }

    float* op = out + (b * N_ + n0 + nlh) * C_ + co;
#pragma unroll
    for (int q = 0; q < 4; q++) {
        op[(4 * q + 0) * C_] = acc[q].x;
        op[(4 * q + 1) * C_] = acc[q].y;
        op[(4 * q + 2) * C_] = acc[q].z;
        op[(4 * q + 3) * C_] = acc[q].w;
    }
}

// ---------------------------------------------------------------------------
// stats: per column m, online max + sum of exp over n.
// Block owns 64 m-columns of batch b; iterates n in 64-tiles.
// S tile 64x64 via 4x4 register blocking, float2-vectorized over k.
// smem row stride 130 floats -> the 16-lane stride-16-row fan-out is bank-free.
// ---------------------------------------------------------------------------
__global__ __launch_bounds__(256) void stats_kernel()
{
    extern __shared__ float sm[];
    float* Ysm = sm;                    // 64*130  (keys, resident)
    float* Xsm = Ysm + 64 * 130;        // 64*130  (queries, per tile)
    float* red = Xsm + 64 * 130;        // 16*64 reduction buffer
    float* cm  = red + 16 * 64;         // 64 current running max

    int b = blockIdx.y, m0 = blockIdx.x * 64;
    int tid = threadIdx.x;
    const float* Yb = gY + b * N_ * C_;
    const float* Xb = gX + b * N_ * C_;

    for (int i = tid; i < 64 * 64; i += 256) {
        int r = i >> 6, c2 = (i & 63) * 2;
        *(float2*)(Ysm + r * 130 + c2) = *(const float2*)(Yb + (m0 + r) * C_ + c2);
    }

    int m16 = tid & 15, n16 = tid >> 4;
    float runM = -3.0e38f, runS = 0.0f;   // threads tid<64 own column m0+tid

    for (int n0 = 0; n0 < N_; n0 += 64) {
        __syncthreads();
        for (int i = tid; i < 64 * 64; i += 256) {
            int r = i >> 6, c2 = (i & 63) * 2;
            *(float2*)(Xsm + r * 130 + c2) = *(const float2*)(Xb + (n0 + r) * C_ + c2);
        }
        __syncthreads();

        float acc[4][4] = {};
#pragma unroll 4
        for (int k2 = 0; k2 < 64; k2++) {
            float2 xv[4], yv[4];
#pragma unroll
            for (int jj = 0; jj < 4; jj++)
                yv[jj] = *(const float2*)(Ysm + (m16 + 16 * jj) * 130 + 2 * k2);
#pragma unroll
            for (int ii = 0; ii < 4; ii++)
                xv[ii] = *(const float2*)(Xsm + (n16 + 16 * ii) * 130 + 2 * k2);
#pragma unroll
            for (int ii = 0; ii < 4; ii++)
#pragma unroll
                for (int jj = 0; jj < 4; jj++)
                    acc[ii][jj] = fmaf(xv[ii].x, yv[jj].x,
                                  fmaf(xv[ii].y, yv[jj].y, acc[ii][jj]));
        }

        // per-thread partial max over its 4 n's, per owned m
#pragma unroll
        for (int jj = 0; jj < 4; jj++)
            red[n16 * 64 + m16 + 16 * jj] =
                fmaxf(fmaxf(acc[0][jj], acc[1][jj]), fmaxf(acc[2][jj], acc[3][jj]));
        __syncthreads();

        if (tid < 64) {
            float tmax = red[tid];
#pragma unroll
            for (int r = 1; r < 16; r++) tmax = fmaxf(tmax, red[r * 64 + tid]);
            if (tmax > runM) { runS *= __expf(runM - tmax); runM = tmax; }
            cm[tid] = runM;
        }
        __syncthreads();

#pragma unroll
        for (int jj = 0; jj < 4; jj++) {
            float mj = cm[m16 + 16 * jj];
            red[n16 * 64 + m16 + 16 * jj] =
                __expf(acc[0][jj] - mj) + __expf(acc[1][jj] - mj) +
                __expf(acc[2][jj] - mj) + __expf(acc[3][jj] - mj);
        }
        __syncthreads();

        if (tid < 64) {
            float s = 0.f;
#pragma unroll
            for (int r = 0; r < 16; r++) s += red[r * 64 + tid];
            runS += s;
        }
    }

    if (tid < 64) {
        gM[b * N_ + m0 + tid]    = runM;
        gInvD[b * N_ + m0 + tid] = 1.0f / runS;
    }
}

// ---------------------------------------------------------------------------
// z: z[n,:] = sum_m exp(S[n,m]-M[m]) * invD[m] * X[m,:]
// Block owns 64 n-rows x all 128 c of batch b; iterates m in 64-tiles.
// Per tile: S GEMM (same layout as stats) -> Psm -> P @ Xv accumulated in regs.
// ---------------------------------------------------------------------------
__global__ __launch_bounds__(256) void z_kernel()
{
    extern __shared__ float sm[];
    float* Xq  = sm;                    // 64*130  queries (resident)
    float* Ym  = Xq + 64 * 130;         // 64*130  keys (per tile)
    float* Xv  = Ym + 64 * 130;         // 64*128  values (per tile, row-major)
    float* Psm = Xv + 64 * 128;         // 64*65   probability tile
    float* mb  = Psm + 64 * 65;         // 64
    float* db  = mb + 64;               // 64

    int b = blockIdx.y, n0 = blockIdx.x * 64;
    int tid = threadIdx.x;
    const float* Xb = gX + b * N_ * C_;
    const float* Yb = gY + b * N_ * C_;

    for (int i = tid; i < 64 * 64; i += 256) {
        int r = i >> 6, c2 = (i & 63) * 2;
        *(float2*)(Xq + r * 130 + c2) = *(const float2*)(Xb + (n0 + r) * C_ + c2);
    }

    int m16 = tid & 15, n16 = tid >> 4;          // S-GEMM mapping
    int c8  = tid & 7,  n2  = tid >> 3;          // accumulation mapping: 2n x 16c
    float4 zac[2][4];
#pragma unroll
    for (int r = 0; r < 2; r++)
#pragma unroll
        for (int q = 0; q < 4; q++) zac[r][q] = make_float4(0.f, 0.f, 0.f, 0.f);

    for (int m0 = 0; m0 < N_; m0 += 64) {
        __syncthreads();
        for (int i = tid; i < 64 * 64; i += 256) {
            int r = i >> 6, c2 = (i & 63) * 2;
            *(float2*)(Ym + r * 130 + c2) = *(const float2*)(Yb + (m0 + r) * C_ + c2);
            *(float2*)(Xv + r * C_  + c2) = *(const float2*)(Xb + (m0 + r) * C_ + c2);
        }
        if (tid < 64) {
            mb[tid] = gM[b * N_ + m0 + tid];
            db[tid] = gInvD[b * N_ + m0 + tid];
        }
        __syncthreads();

        float acc[4][4] = {};
#pragma unroll 4
        for (int k2 = 0; k2 < 64; k2++) {
            float2 xv[4], yv[4];
#pragma unroll
            for (int jj = 0; jj < 4; jj++)
                yv[jj] = *(const float2*)(Ym + (m16 + 16 * jj) * 130 + 2 * k2);
#pragma unroll
            for (int ii = 0; ii < 4; ii++)
                xv[ii] = *(const float2*)(Xq + (n16 + 16 * ii) * 130 + 2 * k2);
#pragma unroll
            for (int ii = 0; ii < 4; ii++)
#pragma unroll
                for (int jj = 0; jj < 4; jj++)
                    acc[ii][jj] = fmaf(xv[ii].x, yv[jj].x,
                                  fmaf(xv[ii].y, yv[jj].y, acc[ii][jj]));
        }

#pragma unroll
        for (int jj = 0; jj < 4; jj++) {
            float mm = mb[m16 + 16 * jj], dd = db[m16 + 16 * jj];
#pragma unroll
            for (int ii = 0; ii < 4; ii++)
                Psm[(n16 + 16 * ii) * 65 + m16 + 16 * jj] =
                    __expf(acc[ii][jj] - mm) * dd;
        }
        __syncthreads();

#pragma unroll 2
        for (int m = 0; m < 64; m++) {
            float p0 = Psm[(2 * n2)     * 65 + m];
            float p1 = Psm[(2 * n2 + 1) * 65 + m];
            const float4* xr = (const float4*)(Xv + m * C_ + c8 * 16);
#pragma unroll
            for (int q = 0; q < 4; q++) {
                float4 x = xr[q];
                fma4(zac[0][q], p0, x);
                fma4(zac[1][q], p1, x);
            }
        }
    }

    float* Zb = gZ + b * N_ * C_;
#pragma unroll
    for (int r = 0; r < 2; r++)
#pragma unroll
        for (int q = 0; q < 4; q++)
            *(float4*)(Zb + (n0 + 2 * n2 + r) * C_ + c8 * 16 + 4 * q) = zac[r][q];
}

// ---------------------------------------------------------------------------
// outproj: out[b][co][n] = sum_ci W[co][ci] * z[b][n][ci] + Wb[co]
// ---------------------------------------------------------------------------
__global__ __launch_bounds__(256) void outproj_kernel(
        const float* __restrict__ w, const float* __restrict__ bias,
        float* __restrict__ out)
{
    __shared__ float zt[C_ * 36];        // zt[ci][nl]
    int b = blockIdx.y, n0 = blockIdx.x * 32;
    int tid = threadIdx.x;
    const float* Zb = gZ + b * N_ * C_;

    for (int i = tid; i < 32 * C_; i += 256) {
        int nl = i >> 7, ci = i & 127;
        zt[ci * 36 + nl] = Zb[(n0 + nl) * C_ + ci];
    }
    __syncthreads();

    int co = tid >> 1, nlh = (tid & 1) * 16;
    float bv = bias[co];
    float4 acc[4];
#pragma unroll
    for (int q = 0; q < 4; q++) acc[q] = make_float4(bv, bv, bv, bv);

#pragma unroll 4
    for (int ci = 0; ci < C_; ci++) {
        float wv = __ldg(w + co * C_ + ci);
        const float4* zr = (const float4*)(zt + ci * 36 + nlh);
#pragma unroll
        for (int q = 0; q < 4; q++) fma4(acc[q], wv, zr[q]);
    }

    float* op = out + (b * C_ + co) * N_ + n0 + nlh;
#pragma unroll
    for (int q = 0; q < 4; q++) *(float4*)(op + 4 * q) = acc[q];
}

// ---------------------------------------------------------------------------
extern "C" void kernel_launch(void* const* d_in, const int* in_sizes, int n_in,
                              void* d_out, int out_size)
{
    const float* cur  = (const float*)d_in[0];
    const float* ref  = (const float*)d_in[1];
    const float* th_w = (const float*)d_in[2];
    const float* th_b = (const float*)d_in[3];
    const float* ph_w = (const float*)d_in[4];
    const float* ph_b = (const float*)d_in[5];
    const float* W_w  = (const float*)d_in[6];
    const float* W_b  = (const float*)d_in[7];
    float* out = (float*)d_out;

    const int stats_smem = (2 * 64 * 130 + 16 * 64 + 64) * (int)sizeof(float);           // ~70.9 KB
    const int z_smem     = (2 * 64 * 130 + 64 * 128 + 64 * 65 + 128) * (int)sizeof(float); // ~116.5 KB
    cudaFuncSetAttribute(stats_kernel, cudaFuncAttributeMaxDynamicSharedMemorySize, stats_smem);
    cudaFuncSetAttribute(z_kernel,     cudaFuncAttributeMaxDynamicSharedMemorySize, z_smem);

    dim3 blk(256);
    inproj_kernel<<<dim3(N_ / 32, B_), blk>>>(ref, th_w, th_b, 0);   // X = theta(ref)
    inproj_kernel<<<dim3(N_ / 32, B_), blk>>>(cur, ph_w, ph_b, 1);   // Y = phi(cur)
    stats_kernel<<<dim3(N_ / 64, B_), blk, stats_smem>>>();
    z_kernel<<<dim3(N_ / 64, B_), blk, z_smem>>>();
    outproj_kernel<<<dim3(N_ / 32, B_), blk>>>(W_w, W_b, out);
}

// round 3
// speedup vs baseline: 2.8745x; 2.8745x over previous
#include <cuda_runtime.h>

#define B_ 8
#define C_ 128
#define N_ 4096

// ---------------- scratch (static device globals; no allocation) ----------------
__device__ float gX[B_ * N_ * C_];          // theta(ref):  [b][n][c]  (queries & values)
__device__ float gY[B_ * N_ * C_];          // phi(cur):    [b][m][c]  (keys, k-major rows)
__device__ float gM[B_ * N_];               // per-column (m) max of S[:,m]
__device__ float gInvD[B_ * N_];            // 1 / sum_n exp(S[n,m]-M[m])
__device__ float gZ[B_ * N_ * C_];          // attention output [b][n][c]
__device__ float gS[(size_t)B_ * N_ * N_];  // scores [b][n][m]  (537 MB, streamed)

// packed fp32x2 FMA: d.lo += a.lo*b.lo ; d.hi += a.hi*b.hi  (full-rate fp32 pipe)
#define FMA2(d, a, b) asm("fma.rn.f32x2 %0, %1, %2, %0;" : "+l"(d) : "l"(a), "l"(b))

__device__ __forceinline__ float pairsum(unsigned long long v) {
    float lo, hi;
    asm("mov.b64 {%0,%1}, %2;" : "=f"(lo), "=f"(hi) : "l"(v));
    return lo + hi;
}
__device__ __forceinline__ unsigned long long pack2(float lo, float hi) {
    unsigned long long r;
    asm("mov.b64 %0, {%1,%2};" : "=l"(r) : "f"(lo), "f"(hi));
    return r;
}
__device__ __forceinline__ void fma4(float4 &a, float s, const float4 &v) {
    a.x = fmaf(s, v.x, a.x);
    a.y = fmaf(s, v.y, a.y);
    a.z = fmaf(s, v.z, a.z);
    a.w = fmaf(s, v.w, a.w);
}

// ---------------------------------------------------------------------------
// inproj: out[b][n][co] = sum_ci w[co][ci] * in[b][ci][n] + bias[co]
// ---------------------------------------------------------------------------
__global__ __launch_bounds__(256) void inproj_kernel(
        const float* __restrict__ in, const float* __restrict__ w,
        const float* __restrict__ bias, int which)
{
    __shared__ float it[C_ * 36];
    float* out = which ? gY : gX;
    int b = blockIdx.y, n0 = blockIdx.x * 32;
    int tid = threadIdx.x;

    for (int i = tid; i < C_ * 32; i += 256) {
        int ci = i >> 5, nl = i & 31;
        it[ci * 36 + nl] = in[(b * C_ + ci) * N_ + n0 + nl];
    }
    __syncthreads();

    int co = tid >> 1, nlh = (tid & 1) * 16;
    float bv = bias[co];
    float4 acc[4];
#pragma unroll
    for (int q = 0; q < 4; q++) acc[q] = make_float4(bv, bv, bv, bv);

#pragma unroll 4
    for (int ci = 0; ci < C_; ci++) {
        float wv = __ldg(w + co * C_ + ci);
        const float4* zr = (const float4*)(it + ci * 36 + nlh);
#pragma unroll
        for (int q = 0; q < 4; q++) fma4(acc[q], wv, zr[q]);
    }

    float* op = out + (b * N_ + n0 + nlh) * C_ + co;
#pragma unroll
    for (int q = 0; q < 4; q++) {
        op[(4 * q + 0) * C_] = acc[q].x;
        op[(4 * q + 1) * C_] = acc[q].y;
        op[(4 * q + 2) * C_] = acc[q].z;
        op[(4 * q + 3) * C_] = acc[q].w;
    }
}

// ---------------------------------------------------------------------------
// stats: S = X @ Y^T tile-wise (packed f32x2 FMA), store S, and per column m
// track online max + exp-sum over n. Block owns 64 m-columns; loops n tiles.
// ---------------------------------------------------------------------------
__global__ __launch_bounds__(256) void stats_kernel()
{
    extern __shared__ float sm[];
    float* Ysm = sm;                    // 64*130 (keys, resident)
    float* Xsm = Ysm + 64 * 130;        // 64*130 (queries, per tile)
    float* red = Xsm + 64 * 130;        // 16*64 reduction buffer
    float* cm  = red + 16 * 64;         // 64 running max

    int b = blockIdx.y, m0 = blockIdx.x * 64;
    int tid = threadIdx.x;
    const float* Yb = gY + b * N_ * C_;
    const float* Xb = gX + b * N_ * C_;
    float* Sb = gS + (size_t)b * N_ * N_;

    for (int i = tid; i < 64 * 64; i += 256) {
        int r = i >> 6, c2 = (i & 63) * 2;
        *(float2*)(Ysm + r * 130 + c2) = *(const float2*)(Yb + (m0 + r) * C_ + c2);
    }

    int m16 = tid & 15, n16 = tid >> 4;
    float runM = -3.0e38f, runS = 0.0f;

    for (int n0 = 0; n0 < N_; n0 += 64) {
        __syncthreads();
        for (int i = tid; i < 64 * 64; i += 256) {
            int r = i >> 6, c2 = (i & 63) * 2;
            *(float2*)(Xsm + r * 130 + c2) = *(const float2*)(Xb + (n0 + r) * C_ + c2);
        }
        __syncthreads();

        unsigned long long acc2[4][4] = {};
#pragma unroll 4
        for (int k2 = 0; k2 < 64; k2++) {
            unsigned long long xv[4], yv[4];
#pragma unroll
            for (int jj = 0; jj < 4; jj++)
                yv[jj] = *(const unsigned long long*)(Ysm + (m16 + 16 * jj) * 130 + 2 * k2);
#pragma unroll
            for (int ii = 0; ii < 4; ii++)
                xv[ii] = *(const unsigned long long*)(Xsm + (n16 + 16 * ii) * 130 + 2 * k2);
#pragma unroll
            for (int ii = 0; ii < 4; ii++)
#pragma unroll
                for (int jj = 0; jj < 4; jj++)
                    FMA2(acc2[ii][jj], xv[ii], yv[jj]);
        }

        float acc[4][4];
#pragma unroll
        for (int ii = 0; ii < 4; ii++)
#pragma unroll
            for (int jj = 0; jj < 4; jj++)
                acc[ii][jj] = pairsum(acc2[ii][jj]);

        // stream S out (evict-first: don't pollute L2 needed for X/Y)
#pragma unroll
        for (int ii = 0; ii < 4; ii++)
#pragma unroll
            for (int jj = 0; jj < 4; jj++)
                __stcs(Sb + (n0 + n16 + 16 * ii) * N_ + m0 + m16 + 16 * jj,
                       acc[ii][jj]);

        // column-max partials
#pragma unroll
        for (int jj = 0; jj < 4; jj++)
            red[n16 * 64 + m16 + 16 * jj] =
                fmaxf(fmaxf(acc[0][jj], acc[1][jj]), fmaxf(acc[2][jj], acc[3][jj]));
        __syncthreads();

        if (tid < 64) {
            float tmax = red[tid];
#pragma unroll
            for (int r = 1; r < 16; r++) tmax = fmaxf(tmax, red[r * 64 + tid]);
            if (tmax > runM) { runS *= __expf(runM - tmax); runM = tmax; }
            cm[tid] = runM;
        }
        __syncthreads();

#pragma unroll
        for (int jj = 0; jj < 4; jj++) {
            float mj = cm[m16 + 16 * jj];
            red[n16 * 64 + m16 + 16 * jj] =
                __expf(acc[0][jj] - mj) + __expf(acc[1][jj] - mj) +
                __expf(acc[2][jj] - mj) + __expf(acc[3][jj] - mj);
        }
        __syncthreads();

        if (tid < 64) {
            float s = 0.f;
#pragma unroll
            for (int r = 0; r < 16; r++) s += red[r * 64 + tid];
            runS += s;
        }
    }

    if (tid < 64) {
        gM[b * N_ + m0 + tid]    = runM;
        gInvD[b * N_ + m0 + tid] = 1.0f / runS;
    }
}

// ---------------------------------------------------------------------------
// z: z[n,:] = sum_m exp(S[n,m]-M[m])*invD[m] * X[m,:]
// Block owns 64 n-rows x 128 c; loops m in 64-chunks. S tile loaded from gS,
// exp'd into Psm. P@X GEMM with packed f32x2 FMA over m-pairs:
//   thread (tx,ty): rows n0+ty*4+r (r<4), cols c = 2*tx+32*j (+0/+1), j<4.
// Xvp holds pair-interleaved values: Xvp[m2*128 + c] = {X[2m2,c], X[2m2+1,c]}.
// ---------------------------------------------------------------------------
__global__ __launch_bounds__(256) void z_kernel()
{
    extern __shared__ float sm[];
    float* Psm = sm;                                            // 64 * 66
    unsigned long long* Xvp = (unsigned long long*)(Psm + 64 * 66); // 32*128 pairs

    int b = blockIdx.y, n0 = blockIdx.x * 64;
    int tid = threadIdx.x;
    const float* Xb = gX + b * N_ * C_;
    const float* Sb = gS + (size_t)b * N_ * N_;
    const float* Mb = gM + b * N_;
    const float* Db = gInvD + b * N_;

    int tx = tid & 15, ty = tid >> 4;

    unsigned long long acc2[4][8];
#pragma unroll
    for (int r = 0; r < 4; r++)
#pragma unroll
        for (int j = 0; j < 8; j++) acc2[r][j] = 0ULL;

    for (int m0 = 0; m0 < N_; m0 += 64) {
        __syncthreads();

        // --- build pair-interleaved X values (32 m-pairs x 128 c) ---
        // 32 pairs x 64 float2-column-groups = 2048 items, 8 per thread
        for (int i = tid; i < 32 * 64; i += 256) {
            int q = i >> 6, cp = (i & 63) * 2;
            float2 v0 = *(const float2*)(Xb + (m0 + 2 * q)     * C_ + cp);
            float2 v1 = *(const float2*)(Xb + (m0 + 2 * q + 1) * C_ + cp);
            ulonglong2 u;
            u.x = pack2(v0.x, v1.x);
            u.y = pack2(v0.y, v1.y);
            *(ulonglong2*)(Xvp + q * 128 + cp) = u;
        }

        // --- load S tile, exp -> Psm (row-major [n][m], stride 66) ---
        for (int i = tid; i < 64 * 16; i += 256) {
            int r = i >> 4, q = (i & 15) * 4;
            float4 s  = __ldcs((const float4*)(Sb + (n0 + r) * N_ + m0 + q));
            float4 mv = *(const float4*)(Mb + m0 + q);
            float4 dv = *(const float4*)(Db + m0 + q);
            float* p = Psm + r * 66 + q;
            p[0] = __expf(s.x - mv.x) * dv.x;
            p[1] = __expf(s.y - mv.y) * dv.y;
            p[2] = __expf(s.z - mv.z) * dv.z;
            p[3] = __expf(s.w - mv.w) * dv.w;
        }
        __syncthreads();

        // --- P @ X over 32 m-pairs ---
#pragma unroll 4
        for (int m2 = 0; m2 < 32; m2++) {
            unsigned long long a[4];
#pragma unroll
            for (int r = 0; r < 4; r++)
                a[r] = *(const unsigned long long*)(Psm + (ty * 4 + r) * 66 + 2 * m2);
            unsigned long long bb[8];
#pragma unroll
            for (int j = 0; j < 4; j++) {
                ulonglong2 bq = *(const ulonglong2*)(Xvp + m2 * 128 + 2 * tx + 32 * j);
                bb[2 * j]     = bq.x;
                bb[2 * j + 1] = bq.y;
            }
#pragma unroll
            for (int r = 0; r < 4; r++)
#pragma unroll
                for (int j = 0; j < 8; j++)
                    FMA2(acc2[r][j], a[r], bb[j]);
        }
    }

    // epilogue: z[n][c] = lo + hi of each pair-accumulator
    float* Zb = gZ + b * N_ * C_;
#pragma unroll
    for (int r = 0; r < 4; r++) {
        int n = n0 + ty * 4 + r;
#pragma unroll
        for (int j = 0; j < 4; j++) {
            float2 o;
            o.x = pairsum(acc2[r][2 * j]);
            o.y = pairsum(acc2[r][2 * j + 1]);
            *(float2*)(Zb + n * C_ + 2 * tx + 32 * j) = o;
        }
    }
}

// ---------------------------------------------------------------------------
// outproj: out[b][co][n] = sum_ci W[co][ci] * z[b][n][ci] + Wb[co]
// ---------------------------------------------------------------------------
__global__ __launch_bounds__(256) void outproj_kernel(
        const float* __restrict__ w, const float* __restrict__ bias,
        float* __restrict__ out)
{
    __shared__ float zt[C_ * 36];
    int b = blockIdx.y, n0 = blockIdx.x * 32;
    int tid = threadIdx.x;
    const float* Zb = gZ + b * N_ * C_;

    for (int i = tid; i < 32 * C_; i += 256) {
        int nl = i >> 7, ci = i & 127;
        zt[ci * 36 + nl] = Zb[(n0 + nl) * C_ + ci];
    }
    __syncthreads();

    int co = tid >> 1, nlh = (tid & 1) * 16;
    float bv = bias[co];
    float4 acc[4];
#pragma unroll
    for (int q = 0; q < 4; q++) acc[q] = make_float4(bv, bv, bv, bv);

#pragma unroll 4
    for (int ci = 0; ci < C_; ci++) {
        float wv = __ldg(w + co * C_ + ci);
        const float4* zr = (const float4*)(zt + ci * 36 + nlh);
#pragma unroll
        for (int q = 0; q < 4; q++) fma4(acc[q], wv, zr[q]);
    }

    float* op = out + (b * C_ + co) * N_ + n0 + nlh;
#pragma unroll
    for (int q = 0; q < 4; q++) *(float4*)(op + 4 * q) = acc[q];
}

// ---------------------------------------------------------------------------
extern "C" void kernel_launch(void* const* d_in, const int* in_sizes, int n_in,
                              void* d_out, int out_size)
{
    const float* cur  = (const float*)d_in[0];
    const float* ref  = (const float*)d_in[1];
    const float* th_w = (const float*)d_in[2];
    const float* th_b = (const float*)d_in[3];
    const float* ph_w = (const float*)d_in[4];
    const float* ph_b = (const float*)d_in[5];
    const float* W_w  = (const float*)d_in[6];
    const float* W_b  = (const float*)d_in[7];
    float* out = (float*)d_out;

    const int stats_smem = (2 * 64 * 130 + 16 * 64 + 64) * (int)sizeof(float);       // ~70.9 KB
    const int z_smem     = 64 * 66 * (int)sizeof(float) + 32 * 128 * 8;              // ~48.5 KB
    cudaFuncSetAttribute(stats_kernel, cudaFuncAttributeMaxDynamicSharedMemorySize, stats_smem);
    cudaFuncSetAttribute(z_kernel,     cudaFuncAttributeMaxDynamicSharedMemorySize, z_smem);

    dim3 blk(256);
    inproj_kernel<<<dim3(N_ / 32, B_), blk>>>(ref, th_w, th_b, 0);   // X = theta(ref)
    inproj_kernel<<<dim3(N_ / 32, B_), blk>>>(cur, ph_w, ph_b, 1);   // Y = phi(cur)
    stats_kernel<<<dim3(N_ / 64, B_), blk, stats_smem>>>();
    z_kernel<<<dim3(N_ / 64, B_), blk, z_smem>>>();
    outproj_kernel<<<dim3(N_ / 32, B_), blk>>>(W_w, W_b, out);
}

// round 4
// speedup vs baseline: 2.8775x; 1.0010x over previous
#include <cuda_runtime.h>

#define B_ 8
#define C_ 128
#define N_ 4096

// ---------------- scratch (static device globals; no allocation) ----------------
__device__ float gX[B_ * N_ * C_];          // theta(ref):  [b][n][c]  (queries & values)
__device__ float gY[B_ * N_ * C_];          // phi(cur):    [b][m][c]  (keys, k-major rows)
__device__ float gM[B_ * N_];               // per-column (m) max of S[:,m]
__device__ float gInvD[B_ * N_];            // 1 / sum_n exp(S[n,m]-M[m])
__device__ float gZ[B_ * N_ * C_];          // attention output [b][n][c]
__device__ float gS[(size_t)B_ * N_ * N_];  // scores [b][n][m]  (537 MB, streamed)

// packed fp32x2 FMA: d.lo += a.lo*b.lo ; d.hi += a.hi*b.hi  (full-rate fp32 pipe)
#define FMA2(d, a, b) asm("fma.rn.f32x2 %0, %1, %2, %0;" : "+l"(d) : "l"(a), "l"(b))

__device__ __forceinline__ float pairsum(unsigned long long v) {
    float lo, hi;
    asm("mov.b64 {%0,%1}, %2;" : "=f"(lo), "=f"(hi) : "l"(v));
    return lo + hi;
}
__device__ __forceinline__ unsigned long long pack2(float lo, float hi) {
    unsigned long long r;
    asm("mov.b64 %0, {%1,%2};" : "=l"(r) : "f"(lo), "f"(hi));
    return r;
}
__device__ __forceinline__ void fma4(float4 &a, float s, const float4 &v) {
    a.x = fmaf(s, v.x, a.x);
    a.y = fmaf(s, v.y, a.y);
    a.z = fmaf(s, v.z, a.z);
    a.w = fmaf(s, v.w, a.w);
}

// ---------------------------------------------------------------------------
// inproj: out[b][n][co] = sum_ci w[co][ci] * in[b][ci][n] + bias[co]
// ---------------------------------------------------------------------------
__global__ __launch_bounds__(256) void inproj_kernel(
        const float* __restrict__ in, const float* __restrict__ w,
        const float* __restrict__ bias, int which)
{
    __shared__ float it[C_ * 36];
    float* out = which ? gY : gX;
    int b = blockIdx.y, n0 = blockIdx.x * 32;
    int tid = threadIdx.x;

    for (int i = tid; i < C_ * 32; i += 256) {
        int ci = i >> 5, nl = i & 31;
        it[ci * 36 + nl] = in[(b * C_ + ci) * N_ + n0 + nl];
    }
    __syncthreads();

    int co = tid >> 1, nlh = (tid & 1) * 16;
    float bv = bias[co];
    float4 acc[4];
#pragma unroll
    for (int q = 0; q < 4; q++) acc[q] = make_float4(bv, bv, bv, bv);

#pragma unroll 4
    for (int ci = 0; ci < C_; ci++) {
        float wv = __ldg(w + co * C_ + ci);
        const float4* zr = (const float4*)(it + ci * 36 + nlh);
#pragma unroll
        for (int q = 0; q < 4; q++) fma4(acc[q], wv, zr[q]);
    }

    float* op = out + (b * N_ + n0 + nlh) * C_ + co;
#pragma unroll
    for (int q = 0; q < 4; q++) {
        op[(4 * q + 0) * C_] = acc[q].x;
        op[(4 * q + 1) * C_] = acc[q].y;
        op[(4 * q + 2) * C_] = acc[q].z;
        op[(4 * q + 3) * C_] = acc[q].w;
    }
}

// ---------------------------------------------------------------------------
// stats: S = X @ Y^T tile-wise (packed f32x2 FMA), store S, and per column m
// track online max + exp-sum over n. Block owns 64 m-columns; loops n tiles.
// ---------------------------------------------------------------------------
__global__ __launch_bounds__(256) void stats_kernel()
{
    extern __shared__ float sm[];
    float* Ysm = sm;                    // 64*130 (keys, resident)
    float* Xsm = Ysm + 64 * 130;        // 64*130 (queries, per tile)
    float* red = Xsm + 64 * 130;        // 16*64 reduction buffer
    float* cm  = red + 16 * 64;         // 64 running max

    int b = blockIdx.y, m0 = blockIdx.x * 64;
    int tid = threadIdx.x;
    const float* Yb = gY + b * N_ * C_;
    const float* Xb = gX + b * N_ * C_;
    float* Sb = gS + (size_t)b * N_ * N_;

    for (int i = tid; i < 64 * 64; i += 256) {
        int r = i >> 6, c2 = (i & 63) * 2;
        *(float2*)(Ysm + r * 130 + c2) = *(const float2*)(Yb + (m0 + r) * C_ + c2);
    }

    int m16 = tid & 15, n16 = tid >> 4;
    float runM = -3.0e38f, runS = 0.0f;

    for (int n0 = 0; n0 < N_; n0 += 64) {
        __syncthreads();
        for (int i = tid; i < 64 * 64; i += 256) {
            int r = i >> 6, c2 = (i & 63) * 2;
            *(float2*)(Xsm + r * 130 + c2) = *(const float2*)(Xb + (n0 + r) * C_ + c2);
        }
        __syncthreads();

        unsigned long long acc2[4][4] = {};
#pragma unroll 4
        for (int k2 = 0; k2 < 64; k2++) {
            unsigned long long xv[4], yv[4];
#pragma unroll
            for (int jj = 0; jj < 4; jj++)
                yv[jj] = *(const unsigned long long*)(Ysm + (m16 + 16 * jj) * 130 + 2 * k2);
#pragma unroll
            for (int ii = 0; ii < 4; ii++)
                xv[ii] = *(const unsigned long long*)(Xsm + (n16 + 16 * ii) * 130 + 2 * k2);
#pragma unroll
            for (int ii = 0; ii < 4; ii++)
#pragma unroll
                for (int jj = 0; jj < 4; jj++)
                    FMA2(acc2[ii][jj], xv[ii], yv[jj]);
        }

        float acc[4][4];
#pragma unroll
        for (int ii = 0; ii < 4; ii++)
#pragma unroll
            for (int jj = 0; jj < 4; jj++)
                acc[ii][jj] = pairsum(acc2[ii][jj]);

        // stream S out (evict-first: don't pollute L2 needed for X/Y)
#pragma unroll
        for (int ii = 0; ii < 4; ii++)
#pragma unroll
            for (int jj = 0; jj < 4; jj++)
                __stcs(Sb + (n0 + n16 + 16 * ii) * N_ + m0 + m16 + 16 * jj,
                       acc[ii][jj]);

        // column-max partials
#pragma unroll
        for (int jj = 0; jj < 4; jj++)
            red[n16 * 64 + m16 + 16 * jj] =
                fmaxf(fmaxf(acc[0][jj], acc[1][jj]), fmaxf(acc[2][jj], acc[3][jj]));
        __syncthreads();

        if (tid < 64) {
            float tmax = red[tid];
#pragma unroll
            for (int r = 1; r < 16; r++) tmax = fmaxf(tmax, red[r * 64 + tid]);
            if (tmax > runM) { runS *= __expf(runM - tmax); runM = tmax; }
            cm[tid] = runM;
        }
        __syncthreads();

#pragma unroll
        for (int jj = 0; jj < 4; jj++) {
            float mj = cm[m16 + 16 * jj];
            red[n16 * 64 + m16 + 16 * jj] =
                __expf(acc[0][jj] - mj) + __expf(acc[1][jj] - mj) +
                __expf(acc[2][jj] - mj) + __expf(acc[3][jj] - mj);
        }
        __syncthreads();

        if (tid < 64) {
            float s = 0.f;
#pragma unroll
            for (int r = 0; r < 16; r++) s += red[r * 64 + tid];
            runS += s;
        }
    }

    if (tid < 64) {
        gM[b * N_ + m0 + tid]    = runM;
        gInvD[b * N_ + m0 + tid] = 1.0f / runS;
    }
}

// ---------------------------------------------------------------------------
// z: z[n,:] = sum_m exp(S[n,m]-M[m])*invD[m] * X[m,:]
// Block owns 64 n-rows x 128 c; loops m in 64-chunks. S tile loaded from gS,
// exp'd into Psm. P@X GEMM with packed f32x2 FMA over m-pairs:
//   thread (tx,ty): rows n0+ty*4+r (r<4), cols c = 2*tx+32*j (+0/+1), j<4.
// Xvp holds pair-interleaved values: Xvp[m2*128 + c] = {X[2m2,c], X[2m2+1,c]}.
// ---------------------------------------------------------------------------
__global__ __launch_bounds__(256) void z_kernel()
{
    extern __shared__ float sm[];
    float* Psm = sm;                                            // 64 * 66
    unsigned long long* Xvp = (unsigned long long*)(Psm + 64 * 66); // 32*128 pairs

    int b = blockIdx.y, n0 = blockIdx.x * 64;
    int tid = threadIdx.x;
    const float* Xb = gX + b * N_ * C_;
    const float* Sb = gS + (size_t)b * N_ * N_;
    const float* Mb = gM + b * N_;
    const float* Db = gInvD + b * N_;

    int tx = tid & 15, ty = tid >> 4;

    unsigned long long acc2[4][8];
#pragma unroll
    for (int r = 0; r < 4; r++)
#pragma unroll
        for (int j = 0; j < 8; j++) acc2[r][j] = 0ULL;

    for (int m0 = 0; m0 < N_; m0 += 64) {
        __syncthreads();

        // --- build pair-interleaved X values (32 m-pairs x 128 c) ---
        // 32 pairs x 64 float2-column-groups = 2048 items, 8 per thread
        for (int i = tid; i < 32 * 64; i += 256) {
            int q = i >> 6, cp = (i & 63) * 2;
            float2 v0 = *(const float2*)(Xb + (m0 + 2 * q)     * C_ + cp);
            float2 v1 = *(const float2*)(Xb + (m0 + 2 * q + 1) * C_ + cp);
            ulonglong2 u;
            u.x = pack2(v0.x, v1.x);
            u.y = pack2(v0.y, v1.y);
            *(ulonglong2*)(Xvp + q * 128 + cp) = u;
        }

        // --- load S tile, exp -> Psm (row-major [n][m], stride 66) ---
        for (int i = tid; i < 64 * 16; i += 256) {
            int r = i >> 4, q = (i & 15) * 4;
            float4 s  = __ldcs((const float4*)(Sb + (n0 + r) * N_ + m0 + q));
            float4 mv = *(const float4*)(Mb + m0 + q);
            float4 dv = *(const float4*)(Db + m0 + q);
            float* p = Psm + r * 66 + q;
            p[0] = __expf(s.x - mv.x) * dv.x;
            p[1] = __expf(s.y - mv.y) * dv.y;
            p[2] = __expf(s.z - mv.z) * dv.z;
            p[3] = __expf(s.w - mv.w) * dv.w;
        }
        __syncthreads();

        // --- P @ X over 32 m-pairs ---
#pragma unroll 4
        for (int m2 = 0; m2 < 32; m2++) {
            unsigned long long a[4];
#pragma unroll
            for (int r = 0; r < 4; r++)
                a[r] = *(const unsigned long long*)(Psm + (ty * 4 + r) * 66 + 2 * m2);
            unsigned long long bb[8];
#pragma unroll
            for (int j = 0; j < 4; j++) {
                ulonglong2 bq = *(const ulonglong2*)(Xvp + m2 * 128 + 2 * tx + 32 * j);
                bb[2 * j]     = bq.x;
                bb[2 * j + 1] = bq.y;
            }
#pragma unroll
            for (int r = 0; r < 4; r++)
#pragma unroll
                for (int j = 0; j < 8; j++)
                    FMA2(acc2[r][j], a[r], bb[j]);
        }
    }

    // epilogue: z[n][c] = lo + hi of each pair-accumulator
    float* Zb = gZ + b * N_ * C_;
#pragma unroll
    for (int r = 0; r < 4; r++) {
        int n = n0 + ty * 4 + r;
#pragma unroll
        for (int j = 0; j < 4; j++) {
            float2 o;
            o.x = pairsum(acc2[r][2 * j]);
            o.y = pairsum(acc2[r][2 * j + 1]);
            *(float2*)(Zb + n * C_ + 2 * tx + 32 * j) = o;
        }
    }
}

// ---------------------------------------------------------------------------
// outproj: out[b][co][n] = sum_ci W[co][ci] * z[b][n][ci] + Wb[co]
// ---------------------------------------------------------------------------
__global__ __launch_bounds__(256) void outproj_kernel(
        const float* __restrict__ w, const float* __restrict__ bias,
        float* __restrict__ out)
{
    __shared__ float zt[C_ * 36];
    int b = blockIdx.y, n0 = blockIdx.x * 32;
    int tid = threadIdx.x;
    const float* Zb = gZ + b * N_ * C_;

    for (int i = tid; i < 32 * C_; i += 256) {
        int nl = i >> 7, ci = i & 127;
        zt[ci * 36 + nl] = Zb[(n0 + nl) * C_ + ci];
    }
    __syncthreads();

    int co = tid >> 1, nlh = (tid & 1) * 16;
    float bv = bias[co];
    float4 acc[4];
#pragma unroll
    for (int q = 0; q < 4; q++) acc[q] = make_float4(bv, bv, bv, bv);

#pragma unroll 4
    for (int ci = 0; ci < C_; ci++) {
        float wv = __ldg(w + co * C_ + ci);
        const float4* zr = (const float4*)(zt + ci * 36 + nlh);
#pragma unroll
        for (int q = 0; q < 4; q++) fma4(acc[q], wv, zr[q]);
    }

    float* op = out + (b * C_ + co) * N_ + n0 + nlh;
#pragma unroll
    for (int q = 0; q < 4; q++) *(float4*)(op + 4 * q) = acc[q];
}

// ---------------------------------------------------------------------------
extern "C" void kernel_launch(void* const* d_in, const int* in_sizes, int n_in,
                              void* d_out, int out_size)
{
    const float* cur  = (const float*)d_in[0];
    const float* ref  = (const float*)d_in[1];
    const float* th_w = (const float*)d_in[2];
    const float* th_b = (const float*)d_in[3];
    const float* ph_w = (const float*)d_in[4];
    const float* ph_b = (const float*)d_in[5];
    const float* W_w  = (const float*)d_in[6];
    const float* W_b  = (const float*)d_in[7];
    float* out = (float*)d_out;

    const int stats_smem = (2 * 64 * 130 + 16 * 64 + 64) * (int)sizeof(float);       // ~70.9 KB
    const int z_smem     = 64 * 66 * (int)sizeof(float) + 32 * 128 * 8;              // ~48.5 KB
    cudaFuncSetAttribute(stats_kernel, cudaFuncAttributeMaxDynamicSharedMemorySize, stats_smem);
    cudaFuncSetAttribute(z_kernel,     cudaFuncAttributeMaxDynamicSharedMemorySize, z_smem);

    dim3 blk(256);
    inproj_kernel<<<dim3(N_ / 32, B_), blk>>>(ref, th_w, th_b, 0);   // X = theta(ref)
    inproj_kernel<<<dim3(N_ / 32, B_), blk>>>(cur, ph_w, ph_b, 1);   // Y = phi(cur)
    stats_kernel<<<dim3(N_ / 64, B_), blk, stats_smem>>>();
    z_kernel<<<dim3(N_ / 64, B_), blk, z_smem>>>();
    outproj_kernel<<<dim3(N_ / 32, B_), blk>>>(W_w, W_b, out);
}

// round 6
// speedup vs baseline: 4.7867x; 1.6635x over previous
#include <cuda_runtime.h>
#include <cuda_bf16.h>
#include <cstdint>

#define B_ 8
#define C_ 128
#define N_ 4096
#define TS 136                    // smem tile row stride in bf16 elems (272B = 17*16B)
#define TILE_B (128 * TS * 2)     // 34816 bytes per 128x128 bf16 tile

// ---------------- scratch (static device globals; no allocation) ----------------
__device__ uint32_t gXp [B_ * N_ * C_];     // theta(ref) packed bf16 hi|lo<<16, [b][n][c]
__device__ uint32_t gYp [B_ * N_ * C_];     // phi(cur) packed, [b][m][c]
__device__ uint32_t gXtp[B_ * C_ * N_];     // theta(ref)^T packed, [b][c][n]
__device__ float gM[B_ * N_];               // per-column (m) max of S[:,m]
__device__ float gInvD[B_ * N_];            // 1 / sum_n exp(S[n,m]-M[m])
__device__ float gZ[B_ * N_ * C_];          // attention out [b][n][c] fp32
__device__ float gS[(size_t)B_ * N_ * N_];  // scores [b][n][m] fp32 (537MB, streamed)

// ---------------- fast exp on the FMA pipe (MUFU is the old bottleneck) ----------
__device__ __forceinline__ float fexp(float x) {
    x = fmaxf(x, -87.0f);                                // keep 2^k exponent in range
    float t = fmaf(x, 1.4426950408889634f, 12582912.0f); // 1.5*2^23 magic
    float k = t - 12582912.0f;                           // round(x*log2e)
    float f = fmaf(x, 1.4426950408889634f, -k);          // f in [-0.5, 0.5]
    float p = 1.3333558146e-3f;
    p = fmaf(p, f, 9.6181291076e-3f);
    p = fmaf(p, f, 5.5504108664e-2f);
    p = fmaf(p, f, 2.4022650696e-1f);
    p = fmaf(p, f, 6.9314718056e-1f);
    p = fmaf(p, f, 1.0f);
    int ki = __float_as_int(t) - 0x4B400000;             // integer k
    float sc = __int_as_float((ki + 127) << 23);         // 2^k
    return p * sc;
}

__device__ __forceinline__ uint32_t pksplit(float f) {
    __nv_bfloat16 h = __float2bfloat16(f);
    __nv_bfloat16 l = __float2bfloat16(f - __bfloat162float(h));
    return (uint32_t)__bfloat16_as_ushort(h) | ((uint32_t)__bfloat16_as_ushort(l) << 16);
}
__device__ __forceinline__ void fma4(float4 &a, float s, const float4 &v) {
    a.x = fmaf(s, v.x, a.x); a.y = fmaf(s, v.y, a.y);
    a.z = fmaf(s, v.z, a.z); a.w = fmaf(s, v.w, a.w);
}
__device__ __forceinline__ uint32_t smem_u32(const void* p) {
    uint32_t a;
    asm("{ .reg .u64 t; cvta.to.shared.u64 t, %1; cvt.u32.u64 %0, t; }" : "=r"(a) : "l"(p));
    return a;
}

// ---------------- HMMA + ldmatrix (base ISA, compiles for sm_103) ----------------
#define LDM_X4(R0, R1, R2, R3, ADDR) \
    asm volatile("ldmatrix.sync.aligned.m8n8.x4.shared.b16 {%0,%1,%2,%3}, [%4];" \
        : "=r"(R0), "=r"(R1), "=r"(R2), "=r"(R3) : "r"(ADDR))
#define LDM_X2(R0, R1, ADDR) \
    asm volatile("ldmatrix.sync.aligned.m8n8.x2.shared.b16 {%0,%1}, [%2];" \
        : "=r"(R0), "=r"(R1) : "r"(ADDR))
#define MMA(D, A, B0, B1) \
    asm volatile("mma.sync.aligned.m16n8k16.row.col.f32.bf16.bf16.f32 " \
        "{%0,%1,%2,%3}, {%4,%5,%6,%7}, {%8,%9}, {%0,%1,%2,%3};" \
        : "+f"((D)[0]), "+f"((D)[1]), "+f"((D)[2]), "+f"((D)[3]) \
        : "r"((A)[0]), "r"((A)[1]), "r"((A)[2]), "r"((A)[3]), "r"(B0), "r"(B1))

// stage a 128x128 packed-u32 gmem block into separate hi/lo bf16 smem tiles
__device__ __forceinline__ void stage128(const uint4* __restrict__ src, int strideU4,
                                         __nv_bfloat16* hi, __nv_bfloat16* lo, int tid) {
    for (int i = tid; i < 128 * 32; i += 256) {
        int row = i >> 5, j = i & 31;
        uint4 v = __ldg(src + row * strideU4 + j);
        uint32_t hA = __byte_perm(v.x, v.y, 0x5410), lA = __byte_perm(v.x, v.y, 0x7632);
        uint32_t hB = __byte_perm(v.z, v.w, 0x5410), lB = __byte_perm(v.z, v.w, 0x7632);
        *(uint2*)(hi + row * TS + j * 4) = make_uint2(hA, hB);
        *(uint2*)(lo + row * TS + j * 4) = make_uint2(lA, lB);
    }
}

// ---------------- proj: 1x1 conv -> packed bf16 split ----------------
__global__ __launch_bounds__(256) void proj_kernel(
        const float* __restrict__ in, const float* __restrict__ w,
        const float* __restrict__ bias, int which)
{
    __shared__ float it[C_ * 36];
    int b = blockIdx.y, n0 = blockIdx.x * 32;
    int tid = threadIdx.x;
    for (int i = tid; i < C_ * 32; i += 256) {
        int ci = i >> 5, nl = i & 31;
        it[ci * 36 + nl] = in[(b * C_ + ci) * N_ + n0 + nl];
    }
    __syncthreads();
    int co = tid >> 1, nlh = (tid & 1) * 16;
    float bv = bias[co];
    float4 acc[4];
#pragma unroll
    for (int q = 0; q < 4; q++) acc[q] = make_float4(bv, bv, bv, bv);
#pragma unroll 4
    for (int ci = 0; ci < C_; ci++) {
        float wv = __ldg(w + co * C_ + ci);
        const float4* zr = (const float4*)(it + ci * 36 + nlh);
#pragma unroll
        for (int q = 0; q < 4; q++) fma4(acc[q], wv, zr[q]);
    }
    uint32_t pk[16];
#pragma unroll
    for (int q = 0; q < 4; q++) {
        pk[4 * q + 0] = pksplit(acc[q].x);
        pk[4 * q + 1] = pksplit(acc[q].y);
        pk[4 * q + 2] = pksplit(acc[q].z);
        pk[4 * q + 3] = pksplit(acc[q].w);
    }
    if (which) {
#pragma unroll
        for (int i = 0; i < 16; i++)
            gYp[(size_t)(b * N_ + n0 + nlh + i) * C_ + co] = pk[i];
    } else {
#pragma unroll
        for (int i = 0; i < 16; i++)
            gXp[(size_t)(b * N_ + n0 + nlh + i) * C_ + co] = pk[i];
        uint4* t = (uint4*)(gXtp + (size_t)(b * C_ + co) * N_ + n0 + nlh);
#pragma unroll
        for (int q = 0; q < 4; q++)
            t[q] = make_uint4(pk[4 * q], pk[4 * q + 1], pk[4 * q + 2], pk[4 * q + 3]);
    }
}

// ---------------------------------------------------------------------------
// stats: CTA owns 128 m-columns; loops 32 n-chunks. Per chunk: S[n][m] via
// HMMA bf16 split (3 passes), store S fp32 to gS, online per-m max/expsum.
// Warp(8) grid 2(n) x 4(m): warp tile 64n x 32m -> frags 4(M) x 4(N).
// ---------------------------------------------------------------------------
__global__ __launch_bounds__(256) void stats_kernel()
{
    extern __shared__ char sm[];
    __nv_bfloat16* Yhi = (__nv_bfloat16*)(sm);
    __nv_bfloat16* Ylo = (__nv_bfloat16*)(sm + TILE_B);
    __nv_bfloat16* Xhi = (__nv_bfloat16*)(sm + 2 * TILE_B);
    __nv_bfloat16* Xlo = (__nv_bfloat16*)(sm + 3 * TILE_B);
    float* red = (float*)(sm + 4 * TILE_B);   // 256
    float* cm  = red + 256;                   // 128 running max
    float* cs  = cm + 128;                    // 128 running sum
    float* csc = cs + 128;                    // 128 rescale factors

    int tid = threadIdx.x, wid = tid >> 5, lane = tid & 31;
    int gid = lane >> 2, tig = lane & 3;
    int wn = wid >> 2, wm = wid & 3;
    int b = blockIdx.y, m0 = blockIdx.x * 128;

    stage128((const uint4*)(gYp + (size_t)(b * N_ + m0) * C_), C_ / 4, Yhi, Ylo, tid);
    if (tid < 128) { cm[tid] = -3.0e38f; cs[tid] = 0.0f; }

    uint32_t smb = smem_u32(sm);
    // ldmatrix per-lane base addresses
    int aR = wn * 64 + (lane & 15), aC = (lane >> 4) << 3;
    int bR = wm * 32 + (lane & 7),  bC = ((lane >> 3) & 1) << 3;
    uint32_t aHi = smb + 2 * TILE_B + (uint32_t)(aR * TS + aC) * 2;  // X hi
    uint32_t aLo = aHi + TILE_B;
    uint32_t bHi = smb + (uint32_t)(bR * TS + bC) * 2;               // Y hi
    uint32_t bLo = bHi + TILE_B;

    for (int nc = 0; nc < 32; nc++) {
        __syncthreads();
        stage128((const uint4*)(gXp + (size_t)(b * N_ + nc * 128) * C_), C_ / 4,
                 Xhi, Xlo, tid);
        __syncthreads();

        float sf[4][4][4];
#pragma unroll
        for (int mt = 0; mt < 4; mt++)
#pragma unroll
            for (int nt = 0; nt < 4; nt++)
#pragma unroll
                for (int q = 0; q < 4; q++) sf[mt][nt][q] = 0.0f;

#pragma unroll
        for (int k = 0; k < 8; k++) {
            uint32_t bh[4][2], bl[4][2];
#pragma unroll
            for (int nt = 0; nt < 4; nt++) {
                LDM_X2(bh[nt][0], bh[nt][1], bHi + nt * (8 * TS * 2) + k * 32);
                LDM_X2(bl[nt][0], bl[nt][1], bLo + nt * (8 * TS * 2) + k * 32);
            }
#pragma unroll
            for (int mt = 0; mt < 4; mt++) {
                uint32_t ah[4], al[4];
                LDM_X4(ah[0], ah[1], ah[2], ah[3], aHi + mt * (16 * TS * 2) + k * 32);
                LDM_X4(al[0], al[1], al[2], al[3], aLo + mt * (16 * TS * 2) + k * 32);
#pragma unroll
                for (int nt = 0; nt < 4; nt++) {
                    MMA(sf[mt][nt], ah, bh[nt][0], bh[nt][1]);
                    MMA(sf[mt][nt], ah, bl[nt][0], bl[nt][1]);
                    MMA(sf[mt][nt], al, bh[nt][0], bh[nt][1]);
                }
            }
        }

        // store S fp32 (32B sectors via float2 across tig lanes)
        float* Sb = gS + (size_t)(b * N_ + nc * 128) * N_ + m0;
#pragma unroll
        for (int mt = 0; mt < 4; mt++) {
            int r = wn * 64 + mt * 16 + gid;
#pragma unroll
            for (int nt = 0; nt < 4; nt++) {
                int c = wm * 32 + nt * 8 + 2 * tig;
                __stcs((float2*)(Sb + (size_t)r * N_ + c),
                       make_float2(sf[mt][nt][0], sf[mt][nt][1]));
                __stcs((float2*)(Sb + (size_t)(r + 8) * N_ + c),
                       make_float2(sf[mt][nt][2], sf[mt][nt][3]));
            }
        }

        // per-column max partials
        float mx[4][2];
#pragma unroll
        for (int nt = 0; nt < 4; nt++)
#pragma unroll
            for (int j = 0; j < 2; j++) {
                float v = -3.0e38f;
#pragma unroll
                for (int mt = 0; mt < 4; mt++)
                    v = fmaxf(v, fmaxf(sf[mt][nt][j], sf[mt][nt][2 + j]));
#pragma unroll
                for (int o = 4; o < 32; o <<= 1)
                    v = fmaxf(v, __shfl_xor_sync(0xFFFFFFFFu, v, o));
                mx[nt][j] = v;
            }
        if (gid == 0)
#pragma unroll
            for (int nt = 0; nt < 4; nt++)
#pragma unroll
                for (int j = 0; j < 2; j++)
                    red[wn * 128 + wm * 32 + nt * 8 + 2 * tig + j] = mx[nt][j];
        __syncthreads();

        if (tid < 128) {
            float tm = fmaxf(red[tid], red[128 + tid]);
            float om = cm[tid], nm = fmaxf(om, tm);
            csc[tid] = fexp(om - nm);
            cm[tid] = nm;
        }
        __syncthreads();

        // per-column expsum partials (FMA-pipe exp)
#pragma unroll
        for (int nt = 0; nt < 4; nt++)
#pragma unroll
            for (int j = 0; j < 2; j++) {
                float mcol = cm[wm * 32 + nt * 8 + 2 * tig + j];
                float v = 0.0f;
#pragma unroll
                for (int mt = 0; mt < 4; mt++)
                    v += fexp(sf[mt][nt][j] - mcol) + fexp(sf[mt][nt][2 + j] - mcol);
#pragma unroll
                for (int o = 4; o < 32; o <<= 1)
                    v += __shfl_xor_sync(0xFFFFFFFFu, v, o);
                mx[nt][j] = v;
            }
        __syncthreads();   // red reads from max phase done
        if (gid == 0)
#pragma unroll
            for (int nt = 0; nt < 4; nt++)
#pragma unroll
                for (int j = 0; j < 2; j++)
                    red[wn * 128 + wm * 32 + nt * 8 + 2 * tig + j] = mx[nt][j];
        __syncthreads();
        if (tid < 128)
            cs[tid] = cs[tid] * csc[tid] + red[tid] + red[128 + tid];
    }

    __syncthreads();
    if (tid < 128) {
        gM[b * N_ + m0 + tid]    = cm[tid];
        gInvD[b * N_ + m0 + tid] = 1.0f / cs[tid];
    }
}

// ---------------------------------------------------------------------------
// z: CTA owns 128 n-rows x 128 c. Loops 32 m-chunks: load S fp32, P=exp(S-M)
// *invD (FMA exp), bf16-split P into smem; HMMA P @ Xt^T accumulating
// z[n][c] in registers over all chunks. Warp grid 2(n) x 4(c).
// ---------------------------------------------------------------------------
__global__ __launch_bounds__(256) void z_kernel()
{
    extern __shared__ char sm[];
    __nv_bfloat16* Phi  = (__nv_bfloat16*)(sm);
    __nv_bfloat16* Plo  = (__nv_bfloat16*)(sm + TILE_B);
    __nv_bfloat16* Xthi = (__nv_bfloat16*)(sm + 2 * TILE_B);
    __nv_bfloat16* Xtlo = (__nv_bfloat16*)(sm + 3 * TILE_B);
    float* Msm = (float*)(sm + 4 * TILE_B);   // 128
    float* Dsm = Msm + 128;                   // 128

    int tid = threadIdx.x, wid = tid >> 5, lane = tid & 31;
    int gid = lane >> 2, tig = lane & 3;
    int wn = wid >> 2, wm = wid & 3;
    int b = blockIdx.y, n0 = blockIdx.x * 128;

    uint32_t smb = smem_u32(sm);
    int aR = wn * 64 + (lane & 15), aC = (lane >> 4) << 3;
    int bR = wm * 32 + (lane & 7),  bC = ((lane >> 3) & 1) << 3;
    uint32_t aHi = smb + (uint32_t)(aR * TS + aC) * 2;                // P hi
    uint32_t aLo = aHi + TILE_B;
    uint32_t bHi = smb + 2 * TILE_B + (uint32_t)(bR * TS + bC) * 2;   // Xt hi
    uint32_t bLo = bHi + TILE_B;

    float zf[4][4][4];
#pragma unroll
    for (int mt = 0; mt < 4; mt++)
#pragma unroll
        for (int nt = 0; nt < 4; nt++)
#pragma unroll
            for (int q = 0; q < 4; q++) zf[mt][nt][q] = 0.0f;

    int prow = tid >> 1, phalf = (tid & 1) * 64;

    for (int mc = 0; mc < 32; mc++) {
        __syncthreads();
        int m0 = mc * 128;
        stage128((const uint4*)(gXtp + (size_t)b * C_ * N_ + m0), N_ / 4,
                 Xthi, Xtlo, tid);
        if (tid < 128) {
            Msm[tid] = gM[b * N_ + m0 + tid];
            Dsm[tid] = gInvD[b * N_ + m0 + tid];
        }
        __syncthreads();

        // P build: thread -> row prow, m in [phalf, phalf+64)
        const float4* Srow = (const float4*)(gS + (size_t)(b * N_ + n0 + prow) * N_
                                             + m0 + phalf);
#pragma unroll 4
        for (int q = 0; q < 16; q++) {
            float4 s = __ldcs(Srow + q);
            int ml = phalf + q * 4;
            float p0 = fexp(s.x - Msm[ml])     * Dsm[ml];
            float p1 = fexp(s.y - Msm[ml + 1]) * Dsm[ml + 1];
            float p2 = fexp(s.z - Msm[ml + 2]) * Dsm[ml + 2];
            float p3 = fexp(s.w - Msm[ml + 3]) * Dsm[ml + 3];
            __nv_bfloat16 h0 = __float2bfloat16(p0), h1 = __float2bfloat16(p1);
            __nv_bfloat16 h2 = __float2bfloat16(p2), h3 = __float2bfloat16(p3);
            __nv_bfloat16 l0 = __float2bfloat16(p0 - __bfloat162float(h0));
            __nv_bfloat16 l1 = __float2bfloat16(p1 - __bfloat162float(h1));
            __nv_bfloat16 l2 = __float2bfloat16(p2 - __bfloat162float(h2));
            __nv_bfloat16 l3 = __float2bfloat16(p3 - __bfloat162float(h3));
            uint32_t h01 = (uint32_t)__bfloat16_as_ushort(h0) |
                           ((uint32_t)__bfloat16_as_ushort(h1) << 16);
            uint32_t h23 = (uint32_t)__bfloat16_as_ushort(h2) |
                           ((uint32_t)__bfloat16_as_ushort(h3) << 16);
            uint32_t l01 = (uint32_t)__bfloat16_as_ushort(l0) |
                           ((uint32_t)__bfloat16_as_ushort(l1) << 16);
            uint32_t l23 = (uint32_t)__bfloat16_as_ushort(l2) |
                           ((uint32_t)__bfloat16_as_ushort(l3) << 16);
            *(uint2*)(Phi + prow * TS + ml) = make_uint2(h01, h23);
            *(uint2*)(Plo + prow * TS + ml) = make_uint2(l01, l23);
        }
        __syncthreads();

        // z[n][c] += P @ Xt^T over K=128 m
#pragma unroll
        for (int k = 0; k < 8; k++) {
            uint32_t bh[4][2], bl[4][2];
#pragma unroll
            for (int nt = 0; nt < 4; nt++) {
                LDM_X2(bh[nt][0], bh[nt][1], bHi + nt * (8 * TS * 2) + k * 32);
                LDM_X2(bl[nt][0], bl[nt][1], bLo + nt * (8 * TS * 2) + k * 32);
            }
#pragma unroll
            for (int mt = 0; mt < 4; mt++) {
                uint32_t ah[4], al[4];
                LDM_X4(ah[0], ah[1], ah[2], ah[3], aHi + mt * (16 * TS * 2) + k * 32);
                LDM_X4(al[0], al[1], al[2], al[3], aLo + mt * (16 * TS * 2) + k * 32);
#pragma unroll
                for (int nt = 0; nt < 4; nt++) {
                    MMA(zf[mt][nt], ah, bh[nt][0], bh[nt][1]);
                    MMA(zf[mt][nt], ah, bl[nt][0], bl[nt][1]);
                    MMA(zf[mt][nt], al, bh[nt][0], bh[nt][1]);
                }
            }
        }
    }

    // epilogue -> gZ[b][n][c]
#pragma unroll
    for (int mt = 0; mt < 4; mt++) {
        int n = n0 + wn * 64 + mt * 16 + gid;
#pragma unroll
        for (int nt = 0; nt < 4; nt++) {
            int c = wm * 32 + nt * 8 + 2 * tig;
            *(float2*)(gZ + (size_t)(b * N_ + n) * C_ + c) =
                make_float2(zf[mt][nt][0], zf[mt][nt][1]);
            *(float2*)(gZ + (size_t)(b * N_ + n + 8) * C_ + c) =
                make_float2(zf[mt][nt][2], zf[mt][nt][3]);
        }
    }
}

// ---------------- outproj ----------------
__global__ __launch_bounds__(256) void outproj_kernel(
        const float* __restrict__ w, const float* __restrict__ bias,
        float* __restrict__ out)
{
    __shared__ float zt[C_ * 36];
    int b = blockIdx.y, n0 = blockIdx.x * 32;
    int tid = threadIdx.x;
    const float* Zb = gZ + (size_t)b * N_ * C_;
    for (int i = tid; i < 32 * C_; i += 256) {
        int nl = i >> 7, ci = i & 127;
        zt[ci * 36 + nl] = Zb[(n0 + nl) * C_ + ci];
    }
    __syncthreads();
    int co = tid >> 1, nlh = (tid & 1) * 16;
    float bv = bias[co];
    float4 acc[4];
#pragma unroll
    for (int q = 0; q < 4; q++) acc[q] = make_float4(bv, bv, bv, bv);
#pragma unroll 4
    for (int ci = 0; ci < C_; ci++) {
        float wv = __ldg(w + co * C_ + ci);
        const float4* zr = (const float4*)(zt + ci * 36 + nlh);
#pragma unroll
        for (int q = 0; q < 4; q++) fma4(acc[q], wv, zr[q]);
    }
    float* op = out + (b * C_ + co) * N_ + n0 + nlh;
#pragma unroll
    for (int q = 0; q < 4; q++) *(float4*)(op + 4 * q) = acc[q];
}

// ---------------------------------------------------------------------------
extern "C" void kernel_launch(void* const* d_in, const int* in_sizes, int n_in,
                              void* d_out, int out_size)
{
    const float* cur  = (const float*)d_in[0];
    const float* ref  = (const float*)d_in[1];
    const float* th_w = (const float*)d_in[2];
    const float* th_b = (const float*)d_in[3];
    const float* ph_w = (const float*)d_in[4];
    const float* ph_b = (const float*)d_in[5];
    const float* W_w  = (const float*)d_in[6];
    const float* W_b  = (const float*)d_in[7];
    float* out = (float*)d_out;

    const int stats_smem = 4 * TILE_B + (256 + 3 * 128) * (int)sizeof(float); // 141824
    const int z_smem     = 4 * TILE_B + 256 * (int)sizeof(float);             // 140288
    cudaFuncSetAttribute(stats_kernel, cudaFuncAttributeMaxDynamicSharedMemorySize, stats_smem);
    cudaFuncSetAttribute(z_kernel,     cudaFuncAttributeMaxDynamicSharedMemorySize, z_smem);

    dim3 blk(256);
    proj_kernel<<<dim3(N_ / 32, B_), blk>>>(ref, th_w, th_b, 0);   // X (+ X^T)
    proj_kernel<<<dim3(N_ / 32, B_), blk>>>(cur, ph_w, ph_b, 1);   // Y
    stats_kernel<<<dim3(N_ / 128, B_), blk, stats_smem>>>();
    z_kernel<<<dim3(N_ / 128, B_), blk, z_smem>>>();
    outproj_kernel<<<dim3(N_ / 32, B_), blk>>>(W_w, W_b, out);
}

// round 7
// speedup vs baseline: 5.6183x; 1.1737x over previous
#include <cuda_runtime.h>
#include <cuda_bf16.h>
#include <cstdint>

#define B_ 8
#define C_ 128
#define N_ 4096
#define TS 136                    // smem tile row stride in bf16 (272B = 17*16B)
#define TILE_B (128 * TS * 2)     // 34816 bytes per 128x128 bf16 tile

// ---------------- scratch (static device globals; no allocation) ----------------
__device__ __nv_bfloat16 gXhi [B_ * N_ * C_];   // theta(ref) hi, [b][n][c]
__device__ __nv_bfloat16 gXlo [B_ * N_ * C_];
__device__ __nv_bfloat16 gYhi [B_ * N_ * C_];   // phi(cur) hi, [b][m][c]
__device__ __nv_bfloat16 gYlo [B_ * N_ * C_];
__device__ __nv_bfloat16 gXthi[B_ * C_ * N_];   // theta(ref)^T hi, [b][c][n]
__device__ __nv_bfloat16 gXtlo[B_ * C_ * N_];
__device__ float gInvD[B_ * N_];                // 1 / sum_n exp(S[n,m])
__device__ float gZ[B_ * N_ * C_];              // attention out [b][n][c]
__device__ float gS[(size_t)B_ * N_ * N_];      // scores fp32 (537MB, streamed)

// ---------------- fast exp on the FMA pipe ----------------
__device__ __forceinline__ float fexp(float x) {
    x = fmaxf(x, -87.0f);
    float t = fmaf(x, 1.4426950408889634f, 12582912.0f);
    float k = t - 12582912.0f;
    float f = fmaf(x, 1.4426950408889634f, -k);
    float p = 1.3333558146e-3f;
    p = fmaf(p, f, 9.6181291076e-3f);
    p = fmaf(p, f, 5.5504108664e-2f);
    p = fmaf(p, f, 2.4022650696e-1f);
    p = fmaf(p, f, 6.9314718056e-1f);
    p = fmaf(p, f, 1.0f);
    int ki = __float_as_int(t) - 0x4B400000;
    float sc = __int_as_float((ki + 127) << 23);
    return p * sc;
}

__device__ __forceinline__ void fma4(float4 &a, float s, const float4 &v) {
    a.x = fmaf(s, v.x, a.x); a.y = fmaf(s, v.y, a.y);
    a.z = fmaf(s, v.z, a.z); a.w = fmaf(s, v.w, a.w);
}
__device__ __forceinline__ uint32_t smem_u32(const void* p) {
    uint32_t a;
    asm("{ .reg .u64 t; cvta.to.shared.u64 t, %1; cvt.u32.u64 %0, t; }" : "=r"(a) : "l"(p));
    return a;
}

// ---------------- HMMA + ldmatrix + cp.async (base ISA) ----------------
#define LDM_X4(R0, R1, R2, R3, ADDR) \
    asm volatile("ldmatrix.sync.aligned.m8n8.x4.shared.b16 {%0,%1,%2,%3}, [%4];" \
        : "=r"(R0), "=r"(R1), "=r"(R2), "=r"(R3) : "r"(ADDR))
#define LDM_X2(R0, R1, ADDR) \
    asm volatile("ldmatrix.sync.aligned.m8n8.x2.shared.b16 {%0,%1}, [%2];" \
        : "=r"(R0), "=r"(R1) : "r"(ADDR))
#define MMA(D, A, B0, B1) \
    asm volatile("mma.sync.aligned.m16n8k16.row.col.f32.bf16.bf16.f32 " \
        "{%0,%1,%2,%3}, {%4,%5,%6,%7}, {%8,%9}, {%0,%1,%2,%3};" \
        : "+f"((D)[0]), "+f"((D)[1]), "+f"((D)[2]), "+f"((D)[3]) \
        : "r"((A)[0]), "r"((A)[1]), "r"((A)[2]), "r"((A)[3]), "r"(B0), "r"(B1))
#define CP16(dst, src) \
    asm volatile("cp.async.cg.shared.global [%0], [%1], 16;" :: "r"(dst), "l"(src))
#define CP_COMMIT() asm volatile("cp.async.commit_group;" ::: "memory")
#define CP_WAIT0()  asm volatile("cp.async.wait_group 0;" ::: "memory")

// async-copy a 128x128 bf16 tile pair (hi,lo) into smem (row stride TS)
__device__ __forceinline__ void copy_tile(uint32_t dhi, uint32_t dlo,
        const __nv_bfloat16* __restrict__ shi, const __nv_bfloat16* __restrict__ slo,
        int stride, int tid) {
    for (int i = tid; i < 2048; i += 256) {
        int row = i >> 4, seg = i & 15;
        uint32_t doff = (uint32_t)(row * TS * 2 + seg * 16);
        CP16(dhi + doff, shi + row * stride + seg * 8);
        CP16(dlo + doff, slo + row * stride + seg * 8);
    }
}

// ---------------- proj: 1x1 conv -> split bf16 hi/lo arrays ----------------
__global__ __launch_bounds__(256) void proj_kernel(
        const float* __restrict__ in, const float* __restrict__ w,
        const float* __restrict__ bias, int which)
{
    __shared__ float it[C_ * 36];
    int b = blockIdx.y, n0 = blockIdx.x * 32;
    int tid = threadIdx.x;
    for (int i = tid; i < C_ * 32; i += 256) {
        int ci = i >> 5, nl = i & 31;
        it[ci * 36 + nl] = in[(b * C_ + ci) * N_ + n0 + nl];
    }
    __syncthreads();
    int co = tid >> 1, nlh = (tid & 1) * 16;
    float bv = bias[co];
    float4 acc[4];
#pragma unroll
    for (int q = 0; q < 4; q++) acc[q] = make_float4(bv, bv, bv, bv);
#pragma unroll 4
    for (int ci = 0; ci < C_; ci++) {
        float wv = __ldg(w + co * C_ + ci);
        const float4* zr = (const float4*)(it + ci * 36 + nlh);
#pragma unroll
        for (int q = 0; q < 4; q++) fma4(acc[q], wv, zr[q]);
    }
    float av[16];
#pragma unroll
    for (int q = 0; q < 4; q++) {
        av[4 * q] = acc[q].x; av[4 * q + 1] = acc[q].y;
        av[4 * q + 2] = acc[q].z; av[4 * q + 3] = acc[q].w;
    }
    __nv_bfloat16 h[16], l[16];
#pragma unroll
    for (int i = 0; i < 16; i++) {
        h[i] = __float2bfloat16(av[i]);
        l[i] = __float2bfloat16(av[i] - __bfloat162float(h[i]));
    }
    if (which) {
#pragma unroll
        for (int i = 0; i < 16; i++) {
            size_t idx = (size_t)(b * N_ + n0 + nlh + i) * C_ + co;
            gYhi[idx] = h[i]; gYlo[idx] = l[i];
        }
    } else {
#pragma unroll
        for (int i = 0; i < 16; i++) {
            size_t idx = (size_t)(b * N_ + n0 + nlh + i) * C_ + co;
            gXhi[idx] = h[i]; gXlo[idx] = l[i];
        }
        // transposed copy, 16 consecutive n per thread -> 2 x uint4
        uint32_t ph[8], pl[8];
#pragma unroll
        for (int j = 0; j < 8; j++) {
            ph[j] = (uint32_t)__bfloat16_as_ushort(h[2 * j]) |
                    ((uint32_t)__bfloat16_as_ushort(h[2 * j + 1]) << 16);
            pl[j] = (uint32_t)__bfloat16_as_ushort(l[2 * j]) |
                    ((uint32_t)__bfloat16_as_ushort(l[2 * j + 1]) << 16);
        }
        size_t tidx = (size_t)(b * C_ + co) * N_ + n0 + nlh;
        *(uint4*)(gXthi + tidx)     = make_uint4(ph[0], ph[1], ph[2], ph[3]);
        *(uint4*)(gXthi + tidx + 8) = make_uint4(ph[4], ph[5], ph[6], ph[7]);
        *(uint4*)(gXtlo + tidx)     = make_uint4(pl[0], pl[1], pl[2], pl[3]);
        *(uint4*)(gXtlo + tidx + 8) = make_uint4(pl[4], pl[5], pl[6], pl[7]);
    }
}

// ---------------------------------------------------------------------------
// stats: CTA owns 128 m; loops 32 n-chunks (double-buffered cp.async).
// Per chunk: S = X@Y^T (3-pass bf16-split HMMA), store S fp32, column expsum
// (no max subtraction: logits bounded ~70 < 88).
// ---------------------------------------------------------------------------
__global__ __launch_bounds__(256) void stats_kernel()
{
    extern __shared__ char sm[];
    const int OY = 0, OX0 = 2 * TILE_B, OX1 = 4 * TILE_B;
    float* red = (float*)(sm + 6 * TILE_B);   // 256
    float* cs  = red + 256;                   // 128

    int tid = threadIdx.x, wid = tid >> 5, lane = tid & 31;
    int gid = lane >> 2, tig = lane & 3;
    int wn = wid >> 2, wm = wid & 3;
    int b = blockIdx.y, m0 = blockIdx.x * 128;
    uint32_t smb = smem_u32(sm);

    // prologue: Y resident tiles + X chunk 0
    copy_tile(smb + OY, smb + OY + TILE_B,
              gYhi + (size_t)(b * N_ + m0) * C_, gYlo + (size_t)(b * N_ + m0) * C_,
              C_, tid);
    copy_tile(smb + OX0, smb + OX0 + TILE_B,
              gXhi + (size_t)b * N_ * C_, gXlo + (size_t)b * N_ * C_, C_, tid);
    CP_COMMIT();
    if (tid < 128) cs[tid] = 0.0f;

    int aR = wn * 64 + (lane & 15), aC = (lane >> 4) << 3;
    int bR = wm * 32 + (lane & 7),  bC = ((lane >> 3) & 1) << 3;
    uint32_t aOff = (uint32_t)(aR * TS + aC) * 2;
    uint32_t bHi  = smb + OY + (uint32_t)(bR * TS + bC) * 2;
    uint32_t bLo  = bHi + TILE_B;

    for (int nc = 0; nc < 32; nc++) {
        CP_WAIT0();
        __syncthreads();
        int buf = nc & 1;
        if (nc + 1 < 32) {
            int nb = OX0 + (2 * TILE_B) * ((nc + 1) & 1);
            copy_tile(smb + nb, smb + nb + TILE_B,
                      gXhi + (size_t)(b * N_ + (nc + 1) * 128) * C_,
                      gXlo + (size_t)(b * N_ + (nc + 1) * 128) * C_, C_, tid);
            CP_COMMIT();
        }

        uint32_t aHi = smb + OX0 + (2 * TILE_B) * buf + aOff;
        uint32_t aLo = aHi + TILE_B;

        float sf[4][4][4];
#pragma unroll
        for (int mt = 0; mt < 4; mt++)
#pragma unroll
            for (int nt = 0; nt < 4; nt++)
#pragma unroll
                for (int q = 0; q < 4; q++) sf[mt][nt][q] = 0.0f;

#pragma unroll
        for (int k = 0; k < 8; k++) {
            uint32_t bh[4][2], bl[4][2];
#pragma unroll
            for (int nt = 0; nt < 4; nt++) {
                LDM_X2(bh[nt][0], bh[nt][1], bHi + nt * (8 * TS * 2) + k * 32);
                LDM_X2(bl[nt][0], bl[nt][1], bLo + nt * (8 * TS * 2) + k * 32);
            }
#pragma unroll
            for (int mt = 0; mt < 4; mt++) {
                uint32_t ah[4], al[4];
                LDM_X4(ah[0], ah[1], ah[2], ah[3], aHi + mt * (16 * TS * 2) + k * 32);
                LDM_X4(al[0], al[1], al[2], al[3], aLo + mt * (16 * TS * 2) + k * 32);
#pragma unroll
                for (int nt = 0; nt < 4; nt++) {
                    MMA(sf[mt][nt], ah, bh[nt][0], bh[nt][1]);
                    MMA(sf[mt][nt], ah, bl[nt][0], bl[nt][1]);
                    MMA(sf[mt][nt], al, bh[nt][0], bh[nt][1]);
                }
            }
        }

        // stream S out
        float* Sb = gS + (size_t)(b * N_ + nc * 128) * N_ + m0;
#pragma unroll
        for (int mt = 0; mt < 4; mt++) {
            int r = wn * 64 + mt * 16 + gid;
#pragma unroll
            for (int nt = 0; nt < 4; nt++) {
                int c = wm * 32 + nt * 8 + 2 * tig;
                __stcs((float2*)(Sb + (size_t)r * N_ + c),
                       make_float2(sf[mt][nt][0], sf[mt][nt][1]));
                __stcs((float2*)(Sb + (size_t)(r + 8) * N_ + c),
                       make_float2(sf[mt][nt][2], sf[mt][nt][3]));
            }
        }

        // column expsum partials (no max)
#pragma unroll
        for (int nt = 0; nt < 4; nt++)
#pragma unroll
            for (int j = 0; j < 2; j++) {
                float v = 0.0f;
#pragma unroll
                for (int mt = 0; mt < 4; mt++)
                    v += fexp(sf[mt][nt][j]) + fexp(sf[mt][nt][2 + j]);
#pragma unroll
                for (int o = 4; o < 32; o <<= 1)
                    v += __shfl_xor_sync(0xFFFFFFFFu, v, o);
                if (gid == 0)
                    red[wn * 128 + wm * 32 + nt * 8 + 2 * tig + j] = v;
            }
        __syncthreads();
        if (tid < 128) cs[tid] += red[tid] + red[128 + tid];
    }

    __syncthreads();
    if (tid < 128) gInvD[b * N_ + m0 + tid] = 1.0f / cs[tid];
}

// ---------------------------------------------------------------------------
// z: CTA owns 128 n x 128 c; loops 32 m-chunks (Xt double-buffered cp.async).
// Per chunk: P = exp(S)*invD -> split bf16 smem; z += P @ Xt^T (3-pass HMMA).
// ---------------------------------------------------------------------------
__global__ __launch_bounds__(256) void z_kernel()
{
    extern __shared__ char sm[];
    const int OP = 0, OT0 = 2 * TILE_B, OT1 = 4 * TILE_B;
    float* Dsm = (float*)(sm + 6 * TILE_B);   // 128

    int tid = threadIdx.x, wid = tid >> 5, lane = tid & 31;
    int gid = lane >> 2, tig = lane & 3;
    int wn = wid >> 2, wm = wid & 3;
    int b = blockIdx.y, n0 = blockIdx.x * 128;
    uint32_t smb = smem_u32(sm);

    copy_tile(smb + OT0, smb + OT0 + TILE_B,
              gXthi + (size_t)b * C_ * N_, gXtlo + (size_t)b * C_ * N_, N_, tid);
    CP_COMMIT();

    int aR = wn * 64 + (lane & 15), aC = (lane >> 4) << 3;
    int bR = wm * 32 + (lane & 7),  bC = ((lane >> 3) & 1) << 3;
    uint32_t aHi = smb + OP + (uint32_t)(aR * TS + aC) * 2;
    uint32_t aLo = aHi + TILE_B;
    uint32_t bOff = (uint32_t)(bR * TS + bC) * 2;

    float zf[4][4][4];
#pragma unroll
    for (int mt = 0; mt < 4; mt++)
#pragma unroll
        for (int nt = 0; nt < 4; nt++)
#pragma unroll
            for (int q = 0; q < 4; q++) zf[mt][nt][q] = 0.0f;

    int prow = tid >> 1, phalf = (tid & 1) * 64;
    __nv_bfloat16* Phi = (__nv_bfloat16*)(sm + OP);
    __nv_bfloat16* Plo = (__nv_bfloat16*)(sm + OP + TILE_B);

    for (int mc = 0; mc < 32; mc++) {
        CP_WAIT0();
        if (tid < 128) Dsm[tid] = gInvD[b * N_ + mc * 128 + tid];
        __syncthreads();
        int buf = mc & 1;
        if (mc + 1 < 32) {
            int nb = OT0 + (2 * TILE_B) * ((mc + 1) & 1);
            copy_tile(smb + nb, smb + nb + TILE_B,
                      gXthi + (size_t)b * C_ * N_ + (mc + 1) * 128,
                      gXtlo + (size_t)b * C_ * N_ + (mc + 1) * 128, N_, tid);
            CP_COMMIT();
        }

        // build P tile
        const float4* Srow = (const float4*)(gS + (size_t)(b * N_ + n0 + prow) * N_
                                             + mc * 128 + phalf);
#pragma unroll 4
        for (int q = 0; q < 16; q++) {
            float4 s = __ldcs(Srow + q);
            int ml = phalf + q * 4;
            float p0 = fexp(s.x) * Dsm[ml];
            float p1 = fexp(s.y) * Dsm[ml + 1];
            float p2 = fexp(s.z) * Dsm[ml + 2];
            float p3 = fexp(s.w) * Dsm[ml + 3];
            __nv_bfloat16 h0 = __float2bfloat16(p0), h1 = __float2bfloat16(p1);
            __nv_bfloat16 h2 = __float2bfloat16(p2), h3 = __float2bfloat16(p3);
            __nv_bfloat16 l0 = __float2bfloat16(p0 - __bfloat162float(h0));
            __nv_bfloat16 l1 = __float2bfloat16(p1 - __bfloat162float(h1));
            __nv_bfloat16 l2 = __float2bfloat16(p2 - __bfloat162float(h2));
            __nv_bfloat16 l3 = __float2bfloat16(p3 - __bfloat162float(h3));
            uint32_t h01 = (uint32_t)__bfloat16_as_ushort(h0) |
                           ((uint32_t)__bfloat16_as_ushort(h1) << 16);
            uint32_t h23 = (uint32_t)__bfloat16_as_ushort(h2) |
                           ((uint32_t)__bfloat16_as_ushort(h3) << 16);
            uint32_t l01 = (uint32_t)__bfloat16_as_ushort(l0) |
                           ((uint32_t)__bfloat16_as_ushort(l1) << 16);
            uint32_t l23 = (uint32_t)__bfloat16_as_ushort(l2) |
                           ((uint32_t)__bfloat16_as_ushort(l3) << 16);
            *(uint2*)(Phi + prow * TS + ml) = make_uint2(h01, h23);
            *(uint2*)(Plo + prow * TS + ml) = make_uint2(l01, l23);
        }
        __syncthreads();

        uint32_t bHi = smb + OT0 + (2 * TILE_B) * buf + bOff;
        uint32_t bLo = bHi + TILE_B;
#pragma unroll
        for (int k = 0; k < 8; k++) {
            uint32_t bh[4][2], bl[4][2];
#pragma unroll
            for (int nt = 0; nt < 4; nt++) {
                LDM_X2(bh[nt][0], bh[nt][1], bHi + nt * (8 * TS * 2) + k * 32);
                LDM_X2(bl[nt][0], bl[nt][1], bLo + nt * (8 * TS * 2) + k * 32);
            }
#pragma unroll
            for (int mt = 0; mt < 4; mt++) {
                uint32_t ah[4], al[4];
                LDM_X4(ah[0], ah[1], ah[2], ah[3], aHi + mt * (16 * TS * 2) + k * 32);
                LDM_X4(al[0], al[1], al[2], al[3], aLo + mt * (16 * TS * 2) + k * 32);
#pragma unroll
                for (int nt = 0; nt < 4; nt++) {
                    MMA(zf[mt][nt], ah, bh[nt][0], bh[nt][1]);
                    MMA(zf[mt][nt], ah, bl[nt][0], bl[nt][1]);
                    MMA(zf[mt][nt], al, bh[nt][0], bh[nt][1]);
                }
            }
        }
    }

    // epilogue -> gZ[b][n][c]
#pragma unroll
    for (int mt = 0; mt < 4; mt++) {
        int n = n0 + wn * 64 + mt * 16 + gid;
#pragma unroll
        for (int nt = 0; nt < 4; nt++) {
            int c = wm * 32 + nt * 8 + 2 * tig;
            *(float2*)(gZ + (size_t)(b * N_ + n) * C_ + c) =
                make_float2(zf[mt][nt][0], zf[mt][nt][1]);
            *(float2*)(gZ + (size_t)(b * N_ + n + 8) * C_ + c) =
                make_float2(zf[mt][nt][2], zf[mt][nt][3]);
        }
    }
}

// ---------------- outproj ----------------
__global__ __launch_bounds__(256) void outproj_kernel(
        const float* __restrict__ w, const float* __restrict__ bias,
        float* __restrict__ out)
{
    __shared__ float zt[C_ * 36];
    int b = blockIdx.y, n0 = blockIdx.x * 32;
    int tid = threadIdx.x;
    const float* Zb = gZ + (size_t)b * N_ * C_;
    for (int i = tid; i < 32 * C_; i += 256) {
        int nl = i >> 7, ci = i & 127;
        zt[ci * 36 + nl] = Zb[(n0 + nl) * C_ + ci];
    }
    __syncthreads();
    int co = tid >> 1, nlh = (tid & 1) * 16;
    float bv = bias[co];
    float4 acc[4];
#pragma unroll
    for (int q = 0; q < 4; q++) acc[q] = make_float4(bv, bv, bv, bv);
#pragma unroll 4
    for (int ci = 0; ci < C_; ci++) {
        float wv = __ldg(w + co * C_ + ci);
        const float4* zr = (const float4*)(zt + ci * 36 + nlh);
#pragma unroll
        for (int q = 0; q < 4; q++) fma4(acc[q], wv, zr[q]);
    }
    float* op = out + (b * C_ + co) * N_ + n0 + nlh;
#pragma unroll
    for (int q = 0; q < 4; q++) *(float4*)(op + 4 * q) = acc[q];
}

// ---------------------------------------------------------------------------
extern "C" void kernel_launch(void* const* d_in, const int* in_sizes, int n_in,
                              void* d_out, int out_size)
{
    const float* cur  = (const float*)d_in[0];
    const float* ref  = (const float*)d_in[1];
    const float* th_w = (const float*)d_in[2];
    const float* th_b = (const float*)d_in[3];
    const float* ph_w = (const float*)d_in[4];
    const float* ph_b = (const float*)d_in[5];
    const float* W_w  = (const float*)d_in[6];
    const float* W_b  = (const float*)d_in[7];
    float* out = (float*)d_out;

    const int stats_smem = 6 * TILE_B + (256 + 128) * (int)sizeof(float); // 210432
    const int z_smem     = 6 * TILE_B + 128 * (int)sizeof(float);         // 209408
    cudaFuncSetAttribute(stats_kernel, cudaFuncAttributeMaxDynamicSharedMemorySize, stats_smem);
    cudaFuncSetAttribute(z_kernel,     cudaFuncAttributeMaxDynamicSharedMemorySize, z_smem);

    dim3 blk(256);
    proj_kernel<<<dim3(N_ / 32, B_), blk>>>(ref, th_w, th_b, 0);   // X (+ X^T)
    proj_kernel<<<dim3(N_ / 32, B_), blk>>>(cur, ph_w, ph_b, 1);   // Y
    stats_kernel<<<dim3(N_ / 128, B_), blk, stats_smem>>>();
    z_kernel<<<dim3(N_ / 128, B_), blk, z_smem>>>();
    outproj_kernel<<<dim3(N_ / 32, B_), blk>>>(W_w, W_b, out);
}

// round 8
// speedup vs baseline: 6.1979x; 1.1032x over previous
#include <cuda_runtime.h>
#include <cuda_bf16.h>
#include <cstdint>

#define B_ 8
#define C_ 128
#define N_ 4096
#define TS 136                    // 128-col tile row stride in bf16 (272B)
#define TILE_B (128 * TS * 2)     // 34816 B per 128x128 bf16 tile
#define TSK 72                    // 64-col tile row stride in bf16 (144B)
#define T64B (128 * TSK * 2)      // 18432 B per 128x64 bf16 tile
#define ZBUF (4 * T64B)           // 73728 B per z pipeline buffer

// ---------------- scratch (static device globals; no allocation) ----------------
__device__ __nv_bfloat16 gXhi [B_ * N_ * C_];   // theta(ref) hi, [b][n][c]
__device__ __nv_bfloat16 gXlo [B_ * N_ * C_];
__device__ __nv_bfloat16 gYhi [B_ * N_ * C_];   // phi(cur) hi, [b][m][c]
__device__ __nv_bfloat16 gYlo [B_ * N_ * C_];
__device__ __nv_bfloat16 gXthi[B_ * C_ * N_];   // theta(ref)^T hi, [b][c][n]
__device__ __nv_bfloat16 gXtlo[B_ * C_ * N_];
__device__ __nv_bfloat16 gXshi[B_ * C_ * N_];   // invD-scaled X^T hi, [b][c][m]
__device__ __nv_bfloat16 gXslo[B_ * C_ * N_];
__device__ float gInvD[B_ * N_];                // 1 / sum_n exp(S[n,m])
__device__ float gZ[B_ * N_ * C_];              // attention out [b][n][c]
__device__ __nv_bfloat16 gEhi[(size_t)B_ * N_ * N_];  // exp(S) hi, [b][n][m]
__device__ __nv_bfloat16 gElo[(size_t)B_ * N_ * N_];  // exp(S) lo

// ---------------- fast exp on the FMA pipe ----------------
__device__ __forceinline__ float fexp(float x) {
    x = fmaxf(x, -87.0f);
    float t = fmaf(x, 1.4426950408889634f, 12582912.0f);
    float k = t - 12582912.0f;
    float f = fmaf(x, 1.4426950408889634f, -k);
    float p = 1.3333558146e-3f;
    p = fmaf(p, f, 9.6181291076e-3f);
    p = fmaf(p, f, 5.5504108664e-2f);
    p = fmaf(p, f, 2.4022650696e-1f);
    p = fmaf(p, f, 6.9314718056e-1f);
    p = fmaf(p, f, 1.0f);
    int ki = __float_as_int(t) - 0x4B400000;
    float sc = __int_as_float((ki + 127) << 23);
    return p * sc;
}
__device__ __forceinline__ void fma4(float4 &a, float s, const float4 &v) {
    a.x = fmaf(s, v.x, a.x); a.y = fmaf(s, v.y, a.y);
    a.z = fmaf(s, v.z, a.z); a.w = fmaf(s, v.w, a.w);
}
__device__ __forceinline__ uint32_t smem_u32(const void* p) {
    uint32_t a;
    asm("{ .reg .u64 t; cvta.to.shared.u64 t, %1; cvt.u32.u64 %0, t; }" : "=r"(a) : "l"(p));
    return a;
}
__device__ __forceinline__ uint32_t pack_bf2(float a, float b) {
    __nv_bfloat16 ha = __float2bfloat16(a), hb = __float2bfloat16(b);
    return (uint32_t)__bfloat16_as_ushort(ha) | ((uint32_t)__bfloat16_as_ushort(hb) << 16);
}

// ---------------- HMMA + ldmatrix + cp.async (base ISA) ----------------
#define LDM_X4(R0, R1, R2, R3, ADDR) \
    asm volatile("ldmatrix.sync.aligned.m8n8.x4.shared.b16 {%0,%1,%2,%3}, [%4];" \
        : "=r"(R0), "=r"(R1), "=r"(R2), "=r"(R3) : "r"(ADDR))
#define LDM_X2(R0, R1, ADDR) \
    asm volatile("ldmatrix.sync.aligned.m8n8.x2.shared.b16 {%0,%1}, [%2];" \
        : "=r"(R0), "=r"(R1) : "r"(ADDR))
#define MMA(D, A, B0, B1) \
    asm volatile("mma.sync.aligned.m16n8k16.row.col.f32.bf16.bf16.f32 " \
        "{%0,%1,%2,%3}, {%4,%5,%6,%7}, {%8,%9}, {%0,%1,%2,%3};" \
        : "+f"((D)[0]), "+f"((D)[1]), "+f"((D)[2]), "+f"((D)[3]) \
        : "r"((A)[0]), "r"((A)[1]), "r"((A)[2]), "r"((A)[3]), "r"(B0), "r"(B1))
#define CP16(dst, src) \
    asm volatile("cp.async.cg.shared.global [%0], [%1], 16;" :: "r"(dst), "l"(src))
#define CP_COMMIT() asm volatile("cp.async.commit_group;" ::: "memory")
#define CP_WAIT0()  asm volatile("cp.async.wait_group 0;" ::: "memory")
#define CP_WAIT1()  asm volatile("cp.async.wait_group 1;" ::: "memory")
#define BAR_WG(id)  asm volatile("bar.sync %0, 128;" :: "r"(id) : "memory")

// async-copy a 128x128 bf16 tile pair (hi,lo) into smem (row stride TS)
__device__ __forceinline__ void copy_tile(uint32_t dhi, uint32_t dlo,
        const __nv_bfloat16* __restrict__ shi, const __nv_bfloat16* __restrict__ slo,
        int stride, int tid) {
    for (int i = tid; i < 2048; i += 256) {
        int row = i >> 4, seg = i & 15;
        uint32_t doff = (uint32_t)(row * TS * 2 + seg * 16);
        CP16(dhi + doff, shi + row * stride + seg * 8);
        CP16(dlo + doff, slo + row * stride + seg * 8);
    }
}
// async-copy 4 x (128x64) bf16 tiles into one z pipeline buffer
__device__ __forceinline__ void copy_zbuf(uint32_t dst,
        const __nv_bfloat16* __restrict__ eh, const __nv_bfloat16* __restrict__ el,
        const __nv_bfloat16* __restrict__ xh, const __nv_bfloat16* __restrict__ xl,
        int tid) {
    for (int i = tid; i < 1024; i += 256) {
        int row = i >> 3, seg = i & 7;
        uint32_t d = dst + (uint32_t)(row * TSK * 2 + seg * 16);
        const size_t g = (size_t)row * N_ + seg * 8;
        CP16(d,            eh + g);
        CP16(d + T64B,     el + g);
        CP16(d + 2 * T64B, xh + g);
        CP16(d + 3 * T64B, xl + g);
    }
}

// ---------------- proj: 1x1 conv -> split bf16 hi/lo arrays ----------------
__global__ __launch_bounds__(256) void proj_kernel(
        const float* __restrict__ in, const float* __restrict__ w,
        const float* __restrict__ bias, int which)
{
    __shared__ float it[C_ * 36];
    int b = blockIdx.y, n0 = blockIdx.x * 32;
    int tid = threadIdx.x;
    for (int i = tid; i < C_ * 32; i += 256) {
        int ci = i >> 5, nl = i & 31;
        it[ci * 36 + nl] = in[(b * C_ + ci) * N_ + n0 + nl];
    }
    __syncthreads();
    int co = tid >> 1, nlh = (tid & 1) * 16;
    float bv = bias[co];
    float4 acc[4];
#pragma unroll
    for (int q = 0; q < 4; q++) acc[q] = make_float4(bv, bv, bv, bv);
#pragma unroll 4
    for (int ci = 0; ci < C_; ci++) {
        float wv = __ldg(w + co * C_ + ci);
        const float4* zr = (const float4*)(it + ci * 36 + nlh);
#pragma unroll
        for (int q = 0; q < 4; q++) fma4(acc[q], wv, zr[q]);
    }
    float av[16];
#pragma unroll
    for (int q = 0; q < 4; q++) {
        av[4 * q] = acc[q].x; av[4 * q + 1] = acc[q].y;
        av[4 * q + 2] = acc[q].z; av[4 * q + 3] = acc[q].w;
    }
    __nv_bfloat16 h[16], l[16];
#pragma unroll
    for (int i = 0; i < 16; i++) {
        h[i] = __float2bfloat16(av[i]);
        l[i] = __float2bfloat16(av[i] - __bfloat162float(h[i]));
    }
    if (which) {
#pragma unroll
        for (int i = 0; i < 16; i++) {
            size_t idx = (size_t)(b * N_ + n0 + nlh + i) * C_ + co;
            gYhi[idx] = h[i]; gYlo[idx] = l[i];
        }
    } else {
#pragma unroll
        for (int i = 0; i < 16; i++) {
            size_t idx = (size_t)(b * N_ + n0 + nlh + i) * C_ + co;
            gXhi[idx] = h[i]; gXlo[idx] = l[i];
        }
        uint32_t ph[8], pl[8];
#pragma unroll
        for (int j = 0; j < 8; j++) {
            ph[j] = (uint32_t)__bfloat16_as_ushort(h[2 * j]) |
                    ((uint32_t)__bfloat16_as_ushort(h[2 * j + 1]) << 16);
            pl[j] = (uint32_t)__bfloat16_as_ushort(l[2 * j]) |
                    ((uint32_t)__bfloat16_as_ushort(l[2 * j + 1]) << 16);
        }
        size_t tidx = (size_t)(b * C_ + co) * N_ + n0 + nlh;
        *(uint4*)(gXthi + tidx)     = make_uint4(ph[0], ph[1], ph[2], ph[3]);
        *(uint4*)(gXthi + tidx + 8) = make_uint4(ph[4], ph[5], ph[6], ph[7]);
        *(uint4*)(gXtlo + tidx)     = make_uint4(pl[0], pl[1], pl[2], pl[3]);
        *(uint4*)(gXtlo + tidx + 8) = make_uint4(pl[4], pl[5], pl[6], pl[7]);
    }
}

// ---------------------------------------------------------------------------
// stats: CTA owns 128 m; loops 32 n-chunks (double-buffered cp.async).
// Per chunk: S = X@Y^T (3-pass bf16-split HMMA); E = exp(S) -> split bf16
// stored to gEhi/gElo; per-warpgroup column expsums (named barriers only).
// ---------------------------------------------------------------------------
__global__ __launch_bounds__(256) void stats_kernel()
{
    extern __shared__ char sm[];
    const int OY = 0, OX0 = 2 * TILE_B;
    float* red = (float*)(sm + 6 * TILE_B);   // [2][128]
    float* cs  = red + 256;                   // [2][128]

    int tid = threadIdx.x, wid = tid >> 5, lane = tid & 31;
    int gid = lane >> 2, tig = lane & 3;
    int wn = wid >> 2, wm = wid & 3;
    int b = blockIdx.y, m0 = blockIdx.x * 128;
    uint32_t smb = smem_u32(sm);

    copy_tile(smb + OY, smb + OY + TILE_B,
              gYhi + (size_t)(b * N_ + m0) * C_, gYlo + (size_t)(b * N_ + m0) * C_,
              C_, tid);
    copy_tile(smb + OX0, smb + OX0 + TILE_B,
              gXhi + (size_t)b * N_ * C_, gXlo + (size_t)b * N_ * C_, C_, tid);
    CP_COMMIT();
    if (tid < 256) cs[tid] = 0.0f;

    int aR = wn * 64 + (lane & 15), aC = (lane >> 4) << 3;
    int bR = wm * 32 + (lane & 7),  bC = ((lane >> 3) & 1) << 3;
    uint32_t aOff = (uint32_t)(aR * TS + aC) * 2;
    uint32_t bHi  = smb + OY + (uint32_t)(bR * TS + bC) * 2;
    uint32_t bLo  = bHi + TILE_B;

    for (int nc = 0; nc < 32; nc++) {
        CP_WAIT0();
        __syncthreads();
        int buf = nc & 1;
        if (nc + 1 < 32) {
            int nb = OX0 + (2 * TILE_B) * ((nc + 1) & 1);
            copy_tile(smb + nb, smb + nb + TILE_B,
                      gXhi + (size_t)(b * N_ + (nc + 1) * 128) * C_,
                      gXlo + (size_t)(b * N_ + (nc + 1) * 128) * C_, C_, tid);
            CP_COMMIT();
        }

        uint32_t aHi = smb + OX0 + (2 * TILE_B) * buf + aOff;
        uint32_t aLo = aHi + TILE_B;

        float sf[4][4][4];
#pragma unroll
        for (int mt = 0; mt < 4; mt++)
#pragma unroll
            for (int nt = 0; nt < 4; nt++)
#pragma unroll
                for (int q = 0; q < 4; q++) sf[mt][nt][q] = 0.0f;

#pragma unroll
        for (int k = 0; k < 8; k++) {
            uint32_t bh[4][2], bl[4][2];
#pragma unroll
            for (int nt = 0; nt < 4; nt++) {
                LDM_X2(bh[nt][0], bh[nt][1], bHi + nt * (8 * TS * 2) + k * 32);
                LDM_X2(bl[nt][0], bl[nt][1], bLo + nt * (8 * TS * 2) + k * 32);
            }
#pragma unroll
            for (int mt = 0; mt < 4; mt++) {
                uint32_t ah[4], al[4];
                LDM_X4(ah[0], ah[1], ah[2], ah[3], aHi + mt * (16 * TS * 2) + k * 32);
                LDM_X4(al[0], al[1], al[2], al[3], aLo + mt * (16 * TS * 2) + k * 32);
#pragma unroll
                for (int nt = 0; nt < 4; nt++) {
                    MMA(sf[mt][nt], ah, bh[nt][0], bh[nt][1]);
                    MMA(sf[mt][nt], ah, bl[nt][0], bl[nt][1]);
                    MMA(sf[mt][nt], al, bh[nt][0], bh[nt][1]);
                }
            }
        }

        // epilogue (warpgroup-local): exp, split-store to gE, column sums
        float csum[4][2];
#pragma unroll
        for (int nt = 0; nt < 4; nt++) { csum[nt][0] = 0.f; csum[nt][1] = 0.f; }

        __nv_bfloat16* Eh = gEhi + (size_t)(b * N_ + nc * 128) * N_ + m0;
        __nv_bfloat16* El = gElo + (size_t)(b * N_ + nc * 128) * N_ + m0;
#pragma unroll
        for (int mt = 0; mt < 4; mt++) {
            int r = wn * 64 + mt * 16 + gid;
#pragma unroll
            for (int nt = 0; nt < 4; nt++) {
                int c = wm * 32 + nt * 8 + 2 * tig;
                float e0 = fexp(sf[mt][nt][0]), e1 = fexp(sf[mt][nt][1]);
                float e2 = fexp(sf[mt][nt][2]), e3 = fexp(sf[mt][nt][3]);
                __nv_bfloat16 h0 = __float2bfloat16(e0), h1 = __float2bfloat16(e1);
                __nv_bfloat16 h2 = __float2bfloat16(e2), h3 = __float2bfloat16(e3);
                float r0 = e0 - __bfloat162float(h0), r1 = e1 - __bfloat162float(h1);
                float r2 = e2 - __bfloat162float(h2), r3 = e3 - __bfloat162float(h3);
                uint32_t hu0 = (uint32_t)__bfloat16_as_ushort(h0) |
                               ((uint32_t)__bfloat16_as_ushort(h1) << 16);
                uint32_t hu1 = (uint32_t)__bfloat16_as_ushort(h2) |
                               ((uint32_t)__bfloat16_as_ushort(h3) << 16);
                __stcs((uint32_t*)(Eh + (size_t)r * N_ + c), hu0);
                __stcs((uint32_t*)(Eh + (size_t)(r + 8) * N_ + c), hu1);
                __stcs((uint32_t*)(El + (size_t)r * N_ + c), pack_bf2(r0, r1));
                __stcs((uint32_t*)(El + (size_t)(r + 8) * N_ + c), pack_bf2(r2, r3));
                csum[nt][0] += e0 + e2;
                csum[nt][1] += e1 + e3;
            }
        }
#pragma unroll
        for (int nt = 0; nt < 4; nt++)
#pragma unroll
            for (int j = 0; j < 2; j++) {
                float v = csum[nt][j];
#pragma unroll
                for (int o = 4; o < 32; o <<= 1)
                    v += __shfl_xor_sync(0xFFFFFFFFu, v, o);
                if (gid == 0)
                    red[wn * 128 + wm * 32 + nt * 8 + 2 * tig + j] = v;
            }
        BAR_WG(wn + 1);
        {
            int loc = tid & 127;
            cs[wn * 128 + loc] += red[wn * 128 + loc];
        }
        // (loop-top __syncthreads joins the warpgroups before buffer reuse)
    }

    __syncthreads();
    if (tid < 128)
        gInvD[b * N_ + m0 + tid] = 1.0f / (cs[tid] + cs[128 + tid]);
}

// ---------------- xscale: Xs[c][m] = (Xt_hi+Xt_lo)[c][m] * invD[m], re-split ----
__global__ __launch_bounds__(256) void xscale_kernel()
{
    __shared__ float dv[128];
    int b = blockIdx.y, m0 = blockIdx.x * 128;
    int tid = threadIdx.x;
    if (tid < 128) dv[tid] = gInvD[b * N_ + m0 + tid];
    __syncthreads();
    for (int i = tid; i < 128 * 64; i += 256) {
        int c = i >> 6, mp = (i & 63) * 2;
        size_t idx = (size_t)(b * C_ + c) * N_ + m0 + mp;
        uint32_t hw = *(const uint32_t*)(gXthi + idx);
        uint32_t lw = *(const uint32_t*)(gXtlo + idx);
        float v0 = __bfloat162float(__ushort_as_bfloat16((unsigned short)(hw & 0xFFFF))) +
                   __bfloat162float(__ushort_as_bfloat16((unsigned short)(lw & 0xFFFF)));
        float v1 = __bfloat162float(__ushort_as_bfloat16((unsigned short)(hw >> 16))) +
                   __bfloat162float(__ushort_as_bfloat16((unsigned short)(lw >> 16)));
        v0 *= dv[mp]; v1 *= dv[mp + 1];
        __nv_bfloat16 h0 = __float2bfloat16(v0), h1 = __float2bfloat16(v1);
        float r0 = v0 - __bfloat162float(h0), r1 = v1 - __bfloat162float(h1);
        *(uint32_t*)(gXshi + idx) = (uint32_t)__bfloat16_as_ushort(h0) |
                                    ((uint32_t)__bfloat16_as_ushort(h1) << 16);
        *(uint32_t*)(gXslo + idx) = pack_bf2(r0, r1);
    }
}

// ---------------------------------------------------------------------------
// z: pure copy-fed split-GEMM. z[n][c] = sum_m E[n][m] * Xs[c][m].
// 64 chunks of K=64, 3-deep cp.async ring, 4 tiles per buffer, no scalar math.
// ---------------------------------------------------------------------------
__global__ __launch_bounds__(256) void z_kernel()
{
    extern __shared__ char sm[];
    int tid = threadIdx.x, wid = tid >> 5, lane = tid & 31;
    int gid = lane >> 2, tig = lane & 3;
    int wn = wid >> 2, wm = wid & 3;
    int b = blockIdx.y, n0 = blockIdx.x * 128;
    uint32_t smb = smem_u32(sm);

    const __nv_bfloat16* Eh = gEhi + (size_t)(b * N_ + n0) * N_;
    const __nv_bfloat16* El = gElo + (size_t)(b * N_ + n0) * N_;
    const __nv_bfloat16* Xh = gXshi + (size_t)b * C_ * N_;
    const __nv_bfloat16* Xl = gXslo + (size_t)b * C_ * N_;

    // prologue: chunks 0 and 1
    copy_zbuf(smb, Eh, El, Xh, Xl, tid);
    CP_COMMIT();
    copy_zbuf(smb + ZBUF, Eh + 64, El + 64, Xh + 64, Xl + 64, tid);
    CP_COMMIT();

    int aR = wn * 64 + (lane & 15), aC = (lane >> 4) << 3;
    int bR = wm * 32 + (lane & 7),  bC = ((lane >> 3) & 1) << 3;
    uint32_t aOff = (uint32_t)(aR * TSK + aC) * 2;
    uint32_t bOff = (uint32_t)(bR * TSK + bC) * 2 + 2 * T64B;

    float zf[4][4][4];
#pragma unroll
    for (int mt = 0; mt < 4; mt++)
#pragma unroll
        for (int nt = 0; nt < 4; nt++)
#pragma unroll
            for (int q = 0; q < 4; q++) zf[mt][nt][q] = 0.0f;

    int buf = 0;
    for (int mc = 0; mc < 64; mc++) {
        if (mc < 63) CP_WAIT1(); else CP_WAIT0();
        __syncthreads();   // buf(mc) fully staged; everyone done with buf(mc-1)
        if (mc + 2 < 64) {
            int nb = (buf + 2 >= 3) ? buf - 1 : buf + 2;
            copy_zbuf(smb + nb * ZBUF, Eh + (mc + 2) * 64, El + (mc + 2) * 64,
                      Xh + (mc + 2) * 64, Xl + (mc + 2) * 64, tid);
            CP_COMMIT();
        }

        uint32_t base = smb + buf * ZBUF;
        uint32_t aHi = base + aOff, aLo = aHi + T64B;
        uint32_t bHi = base + bOff, bLo = bHi + T64B;
#pragma unroll
        for (int k = 0; k < 4; k++) {
            uint32_t bh[4][2], bl[4][2];
#pragma unroll
            for (int nt = 0; nt < 4; nt++) {
                LDM_X2(bh[nt][0], bh[nt][1], bHi + nt * (8 * TSK * 2) + k * 32);
                LDM_X2(bl[nt][0], bl[nt][1], bLo + nt * (8 * TSK * 2) + k * 32);
            }
#pragma unroll
            for (int mt = 0; mt < 4; mt++) {
                uint32_t ah[4], al[4];
                LDM_X4(ah[0], ah[1], ah[2], ah[3], aHi + mt * (16 * TSK * 2) + k * 32);
                LDM_X4(al[0], al[1], al[2], al[3], aLo + mt * (16 * TSK * 2) + k * 32);
#pragma unroll
                for (int nt = 0; nt < 4; nt++) {
                    MMA(zf[mt][nt], ah, bh[nt][0], bh[nt][1]);
                    MMA(zf[mt][nt], ah, bl[nt][0], bl[nt][1]);
                    MMA(zf[mt][nt], al, bh[nt][0], bh[nt][1]);
                }
            }
        }
        buf = (buf + 1 >= 3) ? 0 : buf + 1;
    }

    // epilogue -> gZ[b][n][c]
#pragma unroll
    for (int mt = 0; mt < 4; mt++) {
        int n = n0 + wn * 64 + mt * 16 + gid;
#pragma unroll
        for (int nt = 0; nt < 4; nt++) {
            int c = wm * 32 + nt * 8 + 2 * tig;
            *(float2*)(gZ + (size_t)(b * N_ + n) * C_ + c) =
                make_float2(zf[mt][nt][0], zf[mt][nt][1]);
            *(float2*)(gZ + (size_t)(b * N_ + n + 8) * C_ + c) =
                make_float2(zf[mt][nt][2], zf[mt][nt][3]);
        }
    }
}

// ---------------- outproj ----------------
__global__ __launch_bounds__(256) void outproj_kernel(
        const float* __restrict__ w, const float* __restrict__ bias,
        float* __restrict__ out)
{
    __shared__ float zt[C_ * 36];
    int b = blockIdx.y, n0 = blockIdx.x * 32;
    int tid = threadIdx.x;
    const float* Zb = gZ + (size_t)b * N_ * C_;
    for (int i = tid; i < 32 * C_; i += 256) {
        int nl = i >> 7, ci = i & 127;
        zt[ci * 36 + nl] = Zb[(n0 + nl) * C_ + ci];
    }
    __syncthreads();
    int co = tid >> 1, nlh = (tid & 1) * 16;
    float bv = bias[co];
    float4 acc[4];
#pragma unroll
    for (int q = 0; q < 4; q++) acc[q] = make_float4(bv, bv, bv, bv);
#pragma unroll 4
    for (int ci = 0; ci < C_; ci++) {
        float wv = __ldg(w + co * C_ + ci);
        const float4* zr = (const float4*)(zt + ci * 36 + nlh);
#pragma unroll
        for (int q = 0; q < 4; q++) fma4(acc[q], wv, zr[q]);
    }
    float* op = out + (b * C_ + co) * N_ + n0 + nlh;
#pragma unroll
    for (int q = 0; q < 4; q++) *(float4*)(op + 4 * q) = acc[q];
}

// ---------------------------------------------------------------------------
extern "C" void kernel_launch(void* const* d_in, const int* in_sizes, int n_in,
                              void* d_out, int out_size)
{
    const float* cur  = (const float*)d_in[0];
    const float* ref  = (const float*)d_in[1];
    const float* th_w = (const float*)d_in[2];
    const float* th_b = (const float*)d_in[3];
    const float* ph_w = (const float*)d_in[4];
    const float* ph_b = (const float*)d_in[5];
    const float* W_w  = (const float*)d_in[6];
    const float* W_b  = (const float*)d_in[7];
    float* out = (float*)d_out;

    const int stats_smem = 6 * TILE_B + 512 * (int)sizeof(float);  // 210944
    const int z_smem     = 3 * ZBUF;                               // 221184
    cudaFuncSetAttribute(stats_kernel, cudaFuncAttributeMaxDynamicSharedMemorySize, stats_smem);
    cudaFuncSetAttribute(z_kernel,     cudaFuncAttributeMaxDynamicSharedMemorySize, z_smem);

    dim3 blk(256);
    proj_kernel<<<dim3(N_ / 32, B_), blk>>>(ref, th_w, th_b, 0);   // X (+ X^T)
    proj_kernel<<<dim3(N_ / 32, B_), blk>>>(cur, ph_w, ph_b, 1);   // Y
    stats_kernel<<<dim3(N_ / 128, B_), blk, stats_smem>>>();
    xscale_kernel<<<dim3(N_ / 128, B_), blk>>>();
    z_kernel<<<dim3(N_ / 128, B_), blk, z_smem>>>();
    outproj_kernel<<<dim3(N_ / 32, B_), blk>>>(W_w, W_b, out);
}

// round 9
// speedup vs baseline: 6.3620x; 1.0265x over previous
#include <cuda_runtime.h>
#include <cuda_bf16.h>
#include <cstdint>

#define B_ 8
#define C_ 128
#define N_ 4096
#define TS 136                    // stats 128-col tile row stride in bf16 (272B)
#define TILE_B (128 * TS * 2)     // 34816 B per 128x128 bf16 tile
#define TSK 72                    // z 64-col tile row stride in bf16 (144B)
#define EPL (256 * TSK * 2)       // 36864 B: one 256x64 E plane tile
#define XPL (128 * TSK * 2)       // 18432 B: one 128x64 Xs plane tile
#define ZBUF (2 * EPL + 2 * XPL)  // 110592 B per z pipeline buffer

// ---------------- scratch (static device globals; no allocation) ----------------
__device__ __nv_bfloat16 gXhi [B_ * N_ * C_];   // theta(ref) hi, [b][n][c]
__device__ __nv_bfloat16 gXlo [B_ * N_ * C_];
__device__ __nv_bfloat16 gYhi [B_ * N_ * C_];   // phi(cur) hi, [b][m][c]
__device__ __nv_bfloat16 gYlo [B_ * N_ * C_];
__device__ __nv_bfloat16 gXthi[B_ * C_ * N_];   // theta(ref)^T hi, [b][c][n]
__device__ __nv_bfloat16 gXtlo[B_ * C_ * N_];
__device__ __nv_bfloat16 gXshi[B_ * C_ * N_];   // invD-scaled X^T hi, [b][c][m]
__device__ __nv_bfloat16 gXslo[B_ * C_ * N_];
__device__ float gInvD[B_ * N_];                // 1 / sum_n exp(S[n,m])
__device__ float gZ[B_ * N_ * C_];              // attention out [b][n][c]
// exp(S) in PATCH layout: [b][nc][mb][P][gid*8+tj], P=(((wn*4+wm)*4+mt)*4+nt)*2+half
__device__ __nv_bfloat16 gEhi[(size_t)B_ * N_ * N_];
__device__ __nv_bfloat16 gElo[(size_t)B_ * N_ * N_];

// ---------------- fast exp on the FMA pipe ----------------
__device__ __forceinline__ float fexp(float x) {
    x = fmaxf(x, -87.0f);
    float t = fmaf(x, 1.4426950408889634f, 12582912.0f);
    float k = t - 12582912.0f;
    float f = fmaf(x, 1.4426950408889634f, -k);
    float p = 1.3333558146e-3f;
    p = fmaf(p, f, 9.6181291076e-3f);
    p = fmaf(p, f, 5.5504108664e-2f);
    p = fmaf(p, f, 2.4022650696e-1f);
    p = fmaf(p, f, 6.9314718056e-1f);
    p = fmaf(p, f, 1.0f);
    int ki = __float_as_int(t) - 0x4B400000;
    float sc = __int_as_float((ki + 127) << 23);
    return p * sc;
}
__device__ __forceinline__ void fma4(float4 &a, float s, const float4 &v) {
    a.x = fmaf(s, v.x, a.x); a.y = fmaf(s, v.y, a.y);
    a.z = fmaf(s, v.z, a.z); a.w = fmaf(s, v.w, a.w);
}
__device__ __forceinline__ uint32_t smem_u32(const void* p) {
    uint32_t a;
    asm("{ .reg .u64 t; cvta.to.shared.u64 t, %1; cvt.u32.u64 %0, t; }" : "=r"(a) : "l"(p));
    return a;
}
__device__ __forceinline__ uint32_t pack_bf2(float a, float b) {
    __nv_bfloat16 ha = __float2bfloat16(a), hb = __float2bfloat16(b);
    return (uint32_t)__bfloat16_as_ushort(ha) | ((uint32_t)__bfloat16_as_ushort(hb) << 16);
}

// ---------------- HMMA + ldmatrix + cp.async (base ISA) ----------------
#define LDM_X4(R0, R1, R2, R3, ADDR) \
    asm volatile("ldmatrix.sync.aligned.m8n8.x4.shared.b16 {%0,%1,%2,%3}, [%4];" \
        : "=r"(R0), "=r"(R1), "=r"(R2), "=r"(R3) : "r"(ADDR))
#define LDM_X2(R0, R1, ADDR) \
    asm volatile("ldmatrix.sync.aligned.m8n8.x2.shared.b16 {%0,%1}, [%2];" \
        : "=r"(R0), "=r"(R1) : "r"(ADDR))
#define MMA(D, A, B0, B1) \
    asm volatile("mma.sync.aligned.m16n8k16.row.col.f32.bf16.bf16.f32 " \
        "{%0,%1,%2,%3}, {%4,%5,%6,%7}, {%8,%9}, {%0,%1,%2,%3};" \
        : "+f"((D)[0]), "+f"((D)[1]), "+f"((D)[2]), "+f"((D)[3]) \
        : "r"((A)[0]), "r"((A)[1]), "r"((A)[2]), "r"((A)[3]), "r"(B0), "r"(B1))
#define CP16(dst, src) \
    asm volatile("cp.async.cg.shared.global [%0], [%1], 16;" :: "r"(dst), "l"(src))
#define CP_COMMIT() asm volatile("cp.async.commit_group;" ::: "memory")
#define CP_WAIT0()  asm volatile("cp.async.wait_group 0;" ::: "memory")
#define BAR_WG(id)  asm volatile("bar.sync %0, 128;" :: "r"(id) : "memory")

// async-copy a 128x128 bf16 tile pair (hi,lo) into smem (row stride TS)
__device__ __forceinline__ void copy_tile(uint32_t dhi, uint32_t dlo,
        const __nv_bfloat16* __restrict__ shi, const __nv_bfloat16* __restrict__ slo,
        int stride, int tid) {
    for (int i = tid; i < 2048; i += 256) {
        int row = i >> 4, seg = i & 15;
        uint32_t doff = (uint32_t)(row * TS * 2 + seg * 16);
        CP16(dhi + doff, shi + row * stride + seg * 8);
        CP16(dlo + doff, slo + row * stride + seg * 8);
    }
}

// z chunk copy: E (patch layout) + Xs (row-major) -> one pipeline buffer
__device__ __forceinline__ void z_copy_chunk(uint32_t dst, int b, int ncBase, int mc,
                                             int tid) {
    int mb = mc >> 1, wmSel = (mc & 1) << 1;
    // E: 2 planes x 2 ncLoc x 128 patches x 8 rows = 4096 cp16
    for (int i = tid; i < 4096; i += 256) {
        int gid  = i & 7;
        int half = (i >> 3) & 1;
        int nt   = (i >> 4) & 3;
        int mt   = (i >> 6) & 3;
        int wmi  = (i >> 8) & 1;
        int wn   = (i >> 9) & 1;
        int ncL  = (i >> 10) & 1;
        int pl   = i >> 11;
        int P = (((wn * 4 + (wmSel + wmi)) * 4 + mt) * 4 + nt) * 2 + half;
        size_t src = ((((size_t)(b * 32 + ncBase + ncL) * 32 + mb) << 8) + P) * 64
                     + gid * 8;
        int lr = ncL * 128 + wn * 64 + mt * 16 + half * 8 + gid;
        int lc = wmi * 32 + nt * 8;
        uint32_t d = dst + (uint32_t)(pl * EPL + lr * (TSK * 2) + lc * 2);
        CP16(d, (pl ? gElo : gEhi) + src);
    }
    // Xs: 2 planes x 128 c-rows x 8 segs = 2048 cp16
    const __nv_bfloat16* xh = gXshi + (size_t)b * C_ * N_ + mc * 64;
    const __nv_bfloat16* xl = gXslo + (size_t)b * C_ * N_ + mc * 64;
    for (int i = tid; i < 2048; i += 256) {
        int seg = i & 7, cr = (i >> 3) & 127, pl = i >> 10;
        uint32_t d = dst + (uint32_t)(2 * EPL + pl * XPL + cr * (TSK * 2) + seg * 16);
        CP16(d, (pl ? xl : xh) + (size_t)cr * N_ + seg * 8);
    }
}

// ---------------- proj: 1x1 conv -> split bf16 hi/lo arrays ----------------
__global__ __launch_bounds__(256) void proj_kernel(
        const float* __restrict__ in, const float* __restrict__ w,
        const float* __restrict__ bias, int which)
{
    __shared__ float it[C_ * 36];
    int b = blockIdx.y, n0 = blockIdx.x * 32;
    int tid = threadIdx.x;
    for (int i = tid; i < C_ * 32; i += 256) {
        int ci = i >> 5, nl = i & 31;
        it[ci * 36 + nl] = in[(b * C_ + ci) * N_ + n0 + nl];
    }
    __syncthreads();
    int co = tid >> 1, nlh = (tid & 1) * 16;
    float bv = bias[co];
    float4 acc[4];
#pragma unroll
    for (int q = 0; q < 4; q++) acc[q] = make_float4(bv, bv, bv, bv);
#pragma unroll 4
    for (int ci = 0; ci < C_; ci++) {
        float wv = __ldg(w + co * C_ + ci);
        const float4* zr = (const float4*)(it + ci * 36 + nlh);
#pragma unroll
        for (int q = 0; q < 4; q++) fma4(acc[q], wv, zr[q]);
    }
    float av[16];
#pragma unroll
    for (int q = 0; q < 4; q++) {
        av[4 * q] = acc[q].x; av[4 * q + 1] = acc[q].y;
        av[4 * q + 2] = acc[q].z; av[4 * q + 3] = acc[q].w;
    }
    __nv_bfloat16 h[16], l[16];
#pragma unroll
    for (int i = 0; i < 16; i++) {
        h[i] = __float2bfloat16(av[i]);
        l[i] = __float2bfloat16(av[i] - __bfloat162float(h[i]));
    }
    if (which) {
#pragma unroll
        for (int i = 0; i < 16; i++) {
            size_t idx = (size_t)(b * N_ + n0 + nlh + i) * C_ + co;
            gYhi[idx] = h[i]; gYlo[idx] = l[i];
        }
    } else {
#pragma unroll
        for (int i = 0; i < 16; i++) {
            size_t idx = (size_t)(b * N_ + n0 + nlh + i) * C_ + co;
            gXhi[idx] = h[i]; gXlo[idx] = l[i];
        }
        uint32_t ph[8], pl[8];
#pragma unroll
        for (int j = 0; j < 8; j++) {
            ph[j] = (uint32_t)__bfloat16_as_ushort(h[2 * j]) |
                    ((uint32_t)__bfloat16_as_ushort(h[2 * j + 1]) << 16);
            pl[j] = (uint32_t)__bfloat16_as_ushort(l[2 * j]) |
                    ((uint32_t)__bfloat16_as_ushort(l[2 * j + 1]) << 16);
        }
        size_t tidx = (size_t)(b * C_ + co) * N_ + n0 + nlh;
        *(uint4*)(gXthi + tidx)     = make_uint4(ph[0], ph[1], ph[2], ph[3]);
        *(uint4*)(gXthi + tidx + 8) = make_uint4(ph[4], ph[5], ph[6], ph[7]);
        *(uint4*)(gXtlo + tidx)     = make_uint4(pl[0], pl[1], pl[2], pl[3]);
        *(uint4*)(gXtlo + tidx + 8) = make_uint4(pl[4], pl[5], pl[6], pl[7]);
    }
}

// ---------------------------------------------------------------------------
// stats: CTA owns 128 m (mblk); loops 32 n-chunks (double-buffered cp.async).
// Per chunk: S = X@Y^T (3-pass bf16-split HMMA); E = exp(S) -> split bf16
// stored COALESCED in patch layout; per-warpgroup column expsums.
// ---------------------------------------------------------------------------
__global__ __launch_bounds__(256) void stats_kernel()
{
    extern __shared__ char sm[];
    const int OY = 0, OX0 = 2 * TILE_B;
    float* red = (float*)(sm + 6 * TILE_B);   // [2][128]
    float* cs  = red + 256;                   // [2][128]

    int tid = threadIdx.x, wid = tid >> 5, lane = tid & 31;
    int gid = lane >> 2, tig = lane & 3;
    int wn = wid >> 2, wm = wid & 3;
    int b = blockIdx.y, mblk = blockIdx.x, m0 = mblk * 128;
    uint32_t smb = smem_u32(sm);

    copy_tile(smb + OY, smb + OY + TILE_B,
              gYhi + (size_t)(b * N_ + m0) * C_, gYlo + (size_t)(b * N_ + m0) * C_,
              C_, tid);
    copy_tile(smb + OX0, smb + OX0 + TILE_B,
              gXhi + (size_t)b * N_ * C_, gXlo + (size_t)b * N_ * C_, C_, tid);
    CP_COMMIT();
    if (tid < 256) cs[tid] = 0.0f;

    int aR = wn * 64 + (lane & 15), aC = (lane >> 4) << 3;
    int bR = wm * 32 + (lane & 7),  bC = ((lane >> 3) & 1) << 3;
    uint32_t aOff = (uint32_t)(aR * TS + aC) * 2;
    uint32_t bHi  = smb + OY + (uint32_t)(bR * TS + bC) * 2;
    uint32_t bLo  = bHi + TILE_B;

    for (int nc = 0; nc < 32; nc++) {
        CP_WAIT0();
        __syncthreads();
        int buf = nc & 1;
        if (nc + 1 < 32) {
            int nb = OX0 + (2 * TILE_B) * ((nc + 1) & 1);
            copy_tile(smb + nb, smb + nb + TILE_B,
                      gXhi + (size_t)(b * N_ + (nc + 1) * 128) * C_,
                      gXlo + (size_t)(b * N_ + (nc + 1) * 128) * C_, C_, tid);
            CP_COMMIT();
        }

        uint32_t aHi = smb + OX0 + (2 * TILE_B) * buf + aOff;
        uint32_t aLo = aHi + TILE_B;

        float sf[4][4][4];
#pragma unroll
        for (int mt = 0; mt < 4; mt++)
#pragma unroll
            for (int nt = 0; nt < 4; nt++)
#pragma unroll
                for (int q = 0; q < 4; q++) sf[mt][nt][q] = 0.0f;

#pragma unroll
        for (int k = 0; k < 8; k++) {
            uint32_t bh[4][2], bl[4][2];
#pragma unroll
            for (int nt = 0; nt < 4; nt++) {
                LDM_X2(bh[nt][0], bh[nt][1], bHi + nt * (8 * TS * 2) + k * 32);
                LDM_X2(bl[nt][0], bl[nt][1], bLo + nt * (8 * TS * 2) + k * 32);
            }
#pragma unroll
            for (int mt = 0; mt < 4; mt++) {
                uint32_t ah[4], al[4];
                LDM_X4(ah[0], ah[1], ah[2], ah[3], aHi + mt * (16 * TS * 2) + k * 32);
                LDM_X4(al[0], al[1], al[2], al[3], aLo + mt * (16 * TS * 2) + k * 32);
#pragma unroll
                for (int nt = 0; nt < 4; nt++) {
                    MMA(sf[mt][nt], ah, bh[nt][0], bh[nt][1]);
                    MMA(sf[mt][nt], ah, bl[nt][0], bl[nt][1]);
                    MMA(sf[mt][nt], al, bh[nt][0], bh[nt][1]);
                }
            }
        }

        // epilogue: exp, split, coalesced patch stores, column sums
        float csum[4][2];
#pragma unroll
        for (int nt = 0; nt < 4; nt++) { csum[nt][0] = 0.f; csum[nt][1] = 0.f; }

        size_t ebase = ((((size_t)(b * 32 + nc) * 32 + mblk) << 8)) * 64;
#pragma unroll
        for (int mt = 0; mt < 4; mt++) {
#pragma unroll
            for (int nt = 0; nt < 4; nt++) {
                float e0 = fexp(sf[mt][nt][0]), e1 = fexp(sf[mt][nt][1]);
                float e2 = fexp(sf[mt][nt][2]), e3 = fexp(sf[mt][nt][3]);
                __nv_bfloat16 h0 = __float2bfloat16(e0), h1 = __float2bfloat16(e1);
                __nv_bfloat16 h2 = __float2bfloat16(e2), h3 = __float2bfloat16(e3);
                float r0 = e0 - __bfloat162float(h0), r1 = e1 - __bfloat162float(h1);
                float r2 = e2 - __bfloat162float(h2), r3 = e3 - __bfloat162float(h3);
                uint32_t hu0 = (uint32_t)__bfloat16_as_ushort(h0) |
                               ((uint32_t)__bfloat16_as_ushort(h1) << 16);
                uint32_t hu1 = (uint32_t)__bfloat16_as_ushort(h2) |
                               ((uint32_t)__bfloat16_as_ushort(h3) << 16);
                int P0 = (((wn * 4 + wm) * 4 + mt) * 4 + nt) * 2;
                size_t o0 = ebase + (size_t)P0 * 64 + gid * 8 + 2 * tig;
                __stcs((uint32_t*)(gEhi + o0), hu0);
                __stcs((uint32_t*)(gEhi + o0 + 64), hu1);
                __stcs((uint32_t*)(gElo + o0), pack_bf2(r0, r1));
                __stcs((uint32_t*)(gElo + o0 + 64), pack_bf2(r2, r3));
                csum[nt][0] += e0 + e2;
                csum[nt][1] += e1 + e3;
            }
        }
#pragma unroll
        for (int nt = 0; nt < 4; nt++)
#pragma unroll
            for (int j = 0; j < 2; j++) {
                float v = csum[nt][j];
#pragma unroll
                for (int o = 4; o < 32; o <<= 1)
                    v += __shfl_xor_sync(0xFFFFFFFFu, v, o);
                if (gid == 0)
                    red[wn * 128 + wm * 32 + nt * 8 + 2 * tig + j] = v;
            }
        BAR_WG(wn + 1);
        {
            int loc = tid & 127;
            cs[wn * 128 + loc] += red[wn * 128 + loc];
        }
    }

    __syncthreads();
    if (tid < 128)
        gInvD[b * N_ + m0 + tid] = 1.0f / (cs[tid] + cs[128 + tid]);
}

// ---------------- xscale: Xs[c][m] = (Xt_hi+Xt_lo)[c][m] * invD[m], re-split ----
__global__ __launch_bounds__(256) void xscale_kernel()
{
    __shared__ float dv[128];
    int b = blockIdx.y, m0 = blockIdx.x * 128;
    int tid = threadIdx.x;
    if (tid < 128) dv[tid] = gInvD[b * N_ + m0 + tid];
    __syncthreads();
    for (int i = tid; i < 128 * 64; i += 256) {
        int c = i >> 6, mp = (i & 63) * 2;
        size_t idx = (size_t)(b * C_ + c) * N_ + m0 + mp;
        uint32_t hw = *(const uint32_t*)(gXthi + idx);
        uint32_t lw = *(const uint32_t*)(gXtlo + idx);
        float v0 = __bfloat162float(__ushort_as_bfloat16((unsigned short)(hw & 0xFFFF))) +
                   __bfloat162float(__ushort_as_bfloat16((unsigned short)(lw & 0xFFFF)));
        float v1 = __bfloat162float(__ushort_as_bfloat16((unsigned short)(hw >> 16))) +
                   __bfloat162float(__ushort_as_bfloat16((unsigned short)(lw >> 16)));
        v0 *= dv[mp]; v1 *= dv[mp + 1];
        __nv_bfloat16 h0 = __float2bfloat16(v0), h1 = __float2bfloat16(v1);
        float r0 = v0 - __bfloat162float(h0), r1 = v1 - __bfloat162float(h1);
        *(uint32_t*)(gXshi + idx) = (uint32_t)__bfloat16_as_ushort(h0) |
                                    ((uint32_t)__bfloat16_as_ushort(h1) << 16);
        *(uint32_t*)(gXslo + idx) = pack_bf2(r0, r1);
    }
}

// ---------------------------------------------------------------------------
// z: pure copy-fed split-GEMM, 256n x 128c CTA tile, 64x64 warp tiles.
// z[n][c] = sum_m E[n][m] * Xs[c][m]; 64 chunks of K=64, depth-2 ring.
// ---------------------------------------------------------------------------
__global__ __launch_bounds__(256) void z_kernel()
{
    extern __shared__ char sm[];
    int tid = threadIdx.x, wid = tid >> 5, lane = tid & 31;
    int gid = lane >> 2, tig = lane & 3;
    int wn2 = wid >> 1, wm2 = wid & 1;
    int b = blockIdx.y, n0 = blockIdx.x * 256, ncBase = blockIdx.x * 2;
    uint32_t smb = smem_u32(sm);

    z_copy_chunk(smb, b, ncBase, 0, tid);
    CP_COMMIT();

    uint32_t aOff = (uint32_t)((wn2 * 64 + (lane & 15)) * (TSK * 2) +
                               (((lane >> 4) << 3) << 1));
    uint32_t bOff = (uint32_t)(2 * EPL + (wm2 * 64 + (lane & 7)) * (TSK * 2) +
                               ((((lane >> 3) & 1) << 3) << 1));

    float zf[4][8][4];
#pragma unroll
    for (int mt = 0; mt < 4; mt++)
#pragma unroll
        for (int nt = 0; nt < 8; nt++)
#pragma unroll
            for (int q = 0; q < 4; q++) zf[mt][nt][q] = 0.0f;

    for (int mc = 0; mc < 64; mc++) {
        CP_WAIT0();
        __syncthreads();
        if (mc + 1 < 64) {
            z_copy_chunk(smb + ((mc + 1) & 1) * ZBUF, b, ncBase, mc + 1, tid);
            CP_COMMIT();
        }

        uint32_t base = smb + (mc & 1) * ZBUF;
        uint32_t aHi = base + aOff, aLo = aHi + EPL;
        uint32_t bHi = base + bOff, bLo = bHi + XPL;
#pragma unroll
        for (int k = 0; k < 4; k++) {
            uint32_t bh[8][2], bl[8][2];
#pragma unroll
            for (int nt = 0; nt < 8; nt++) {
                LDM_X2(bh[nt][0], bh[nt][1], bHi + nt * (8 * TSK * 2) + k * 32);
                LDM_X2(bl[nt][0], bl[nt][1], bLo + nt * (8 * TSK * 2) + k * 32);
            }
#pragma unroll
            for (int mt = 0; mt < 4; mt++) {
                uint32_t ah[4], al[4];
                LDM_X4(ah[0], ah[1], ah[2], ah[3], aHi + mt * (16 * TSK * 2) + k * 32);
                LDM_X4(al[0], al[1], al[2], al[3], aLo + mt * (16 * TSK * 2) + k * 32);
#pragma unroll
                for (int nt = 0; nt < 8; nt++) {
                    MMA(zf[mt][nt], ah, bh[nt][0], bh[nt][1]);
                    MMA(zf[mt][nt], ah, bl[nt][0], bl[nt][1]);
                    MMA(zf[mt][nt], al, bh[nt][0], bh[nt][1]);
                }
            }
        }
    }

    // epilogue -> gZ[b][n][c]
#pragma unroll
    for (int mt = 0; mt < 4; mt++) {
        int n = n0 + wn2 * 64 + mt * 16 + gid;
#pragma unroll
        for (int nt = 0; nt < 8; nt++) {
            int c = wm2 * 64 + nt * 8 + 2 * tig;
            *(float2*)(gZ + (size_t)(b * N_ + n) * C_ + c) =
                make_float2(zf[mt][nt][0], zf[mt][nt][1]);
            *(float2*)(gZ + (size_t)(b * N_ + n + 8) * C_ + c) =
                make_float2(zf[mt][nt][2], zf[mt][nt][3]);
        }
    }
}

// ---------------- outproj ----------------
__global__ __launch_bounds__(256) void outproj_kernel(
        const float* __restrict__ w, const float* __restrict__ bias,
        float* __restrict__ out)
{
    __shared__ float zt[C_ * 36];
    int b = blockIdx.y, n0 = blockIdx.x * 32;
    int tid = threadIdx.x;
    const float* Zb = gZ + (size_t)b * N_ * C_;
    for (int i = tid; i < 32 * C_; i += 256) {
        int nl = i >> 7, ci = i & 127;
        zt[ci * 36 + nl] = Zb[(n0 + nl) * C_ + ci];
    }
    __syncthreads();
    int co = tid >> 1, nlh = (tid & 1) * 16;
    float bv = bias[co];
    float4 acc[4];
#pragma unroll
    for (int q = 0; q < 4; q++) acc[q] = make_float4(bv, bv, bv, bv);
#pragma unroll 4
    for (int ci = 0; ci < C_; ci++) {
        float wv = __ldg(w + co * C_ + ci);
        const float4* zr = (const float4*)(zt + ci * 36 + nlh);
#pragma unroll
        for (int q = 0; q < 4; q++) fma4(acc[q], wv, zr[q]);
    }
    float* op = out + (b * C_ + co) * N_ + n0 + nlh;
#pragma unroll
    for (int q = 0; q < 4; q++) *(float4*)(op + 4 * q) = acc[q];
}

// ---------------------------------------------------------------------------
extern "C" void kernel_launch(void* const* d_in, const int* in_sizes, int n_in,
                              void* d_out, int out_size)
{
    const float* cur  = (const float*)d_in[0];
    const float* ref  = (const float*)d_in[1];
    const float* th_w = (const float*)d_in[2];
    const float* th_b = (const float*)d_in[3];
    const float* ph_w = (const float*)d_in[4];
    const float* ph_b = (const float*)d_in[5];
    const float* W_w  = (const float*)d_in[6];
    const float* W_b  = (const float*)d_in[7];
    float* out = (float*)d_out;

    const int stats_smem = 6 * TILE_B + 512 * (int)sizeof(float);  // 210944
    const int z_smem     = 2 * ZBUF;                               // 221184
    cudaFuncSetAttribute(stats_kernel, cudaFuncAttributeMaxDynamicSharedMemorySize, stats_smem);
    cudaFuncSetAttribute(z_kernel,     cudaFuncAttributeMaxDynamicSharedMemorySize, z_smem);

    dim3 blk(256);
    proj_kernel<<<dim3(N_ / 32, B_), blk>>>(ref, th_w, th_b, 0);   // X (+ X^T)
    proj_kernel<<<dim3(N_ / 32, B_), blk>>>(cur, ph_w, ph_b, 1);   // Y
    stats_kernel<<<dim3(N_ / 128, B_), blk, stats_smem>>>();
    xscale_kernel<<<dim3(N_ / 128, B_), blk>>>();
    z_kernel<<<dim3(N_ / 256, B_), blk, z_smem>>>();
    outproj_kernel<<<dim3(N_ / 32, B_), blk>>>(W_w, W_b, out);
}

// round 10
// speedup vs baseline: 6.4201x; 1.0091x over previous
#include <cuda_runtime.h>
#include <cuda_bf16.h>
#include <cstdint>

#define B_ 8
#define C_ 128
#define N_ 4096
#define TS 136                     // 128-col tile row stride in bf16 (272B)
#define YPL (64 * TS * 2)          // 17408 B: 64x128 bf16 plane (stats Y)
#define XPL (128 * TS * 2)         // 34816 B: 128x128 bf16 plane (stats X)
#define TSK2 40                    // z 32-col tile row stride in bf16 (80B)
#define EPL2 (128 * TSK2 * 2)      // 10240 B: one 128x32 plane
#define ZBUF2 (4 * EPL2)           // 40960 B per z chunk buffer (Ehi,Elo,Xhi,Xlo)
#define EBLK (16 * 512 * 64)       // elems of gE per (b, nc): 128 x 4096

// ---------------- scratch (static device globals; no allocation) ----------------
__device__ __nv_bfloat16 gXhi [B_ * N_ * C_];   // theta(ref) hi, [b][n][c]
__device__ __nv_bfloat16 gXlo [B_ * N_ * C_];
__device__ __nv_bfloat16 gYhi [B_ * N_ * C_];   // phi(cur) hi, [b][m][c]
__device__ __nv_bfloat16 gYlo [B_ * N_ * C_];
__device__ __nv_bfloat16 gXthi[B_ * C_ * N_];   // theta(ref)^T hi, [b][c][n]
__device__ __nv_bfloat16 gXtlo[B_ * C_ * N_];
__device__ __nv_bfloat16 gXshi[B_ * C_ * N_];   // invD-scaled X^T hi, [b][c][m]
__device__ __nv_bfloat16 gXslo[B_ * C_ * N_];
__device__ float gInvD[B_ * N_];                // 1 / sum_n exp(S[n,m])
__device__ float gZ[B_ * N_ * C_];              // attention out [b][n][c]
// exp(S) in 8x8-block layout: elem (b,nc, n_local, m):
//   br=n_local>>3, bc=m>>3 -> (b*32+nc)*EBLK + (br*512+bc)*64 + (n&7)*8 + (m&7)
__device__ __nv_bfloat16 gEhi[(size_t)B_ * N_ * N_];
__device__ __nv_bfloat16 gElo[(size_t)B_ * N_ * N_];

// ---------------- fast exp on the FMA pipe ----------------
__device__ __forceinline__ float fexp(float x) {
    x = fmaxf(x, -87.0f);
    float t = fmaf(x, 1.4426950408889634f, 12582912.0f);
    float k = t - 12582912.0f;
    float f = fmaf(x, 1.4426950408889634f, -k);
    float p = 1.3333558146e-3f;
    p = fmaf(p, f, 9.6181291076e-3f);
    p = fmaf(p, f, 5.5504108664e-2f);
    p = fmaf(p, f, 2.4022650696e-1f);
    p = fmaf(p, f, 6.9314718056e-1f);
    p = fmaf(p, f, 1.0f);
    int ki = __float_as_int(t) - 0x4B400000;
    float sc = __int_as_float((ki + 127) << 23);
    return p * sc;
}
__device__ __forceinline__ void fma4(float4 &a, float s, const float4 &v) {
    a.x = fmaf(s, v.x, a.x); a.y = fmaf(s, v.y, a.y);
    a.z = fmaf(s, v.z, a.z); a.w = fmaf(s, v.w, a.w);
}
__device__ __forceinline__ uint32_t smem_u32(const void* p) {
    uint32_t a;
    asm("{ .reg .u64 t; cvta.to.shared.u64 t, %1; cvt.u32.u64 %0, t; }" : "=r"(a) : "l"(p));
    return a;
}
__device__ __forceinline__ uint32_t pack_bf2(float a, float b) {
    __nv_bfloat16 ha = __float2bfloat16(a), hb = __float2bfloat16(b);
    return (uint32_t)__bfloat16_as_ushort(ha) | ((uint32_t)__bfloat16_as_ushort(hb) << 16);
}

// ---------------- HMMA + ldmatrix + cp.async (base ISA) ----------------
#define LDM_X4(R0, R1, R2, R3, ADDR) \
    asm volatile("ldmatrix.sync.aligned.m8n8.x4.shared.b16 {%0,%1,%2,%3}, [%4];" \
        : "=r"(R0), "=r"(R1), "=r"(R2), "=r"(R3) : "r"(ADDR))
#define LDM_X2(R0, R1, ADDR) \
    asm volatile("ldmatrix.sync.aligned.m8n8.x2.shared.b16 {%0,%1}, [%2];" \
        : "=r"(R0), "=r"(R1) : "r"(ADDR))
#define MMA(D, A, B0, B1) \
    asm volatile("mma.sync.aligned.m16n8k16.row.col.f32.bf16.bf16.f32 " \
        "{%0,%1,%2,%3}, {%4,%5,%6,%7}, {%8,%9}, {%0,%1,%2,%3};" \
        : "+f"((D)[0]), "+f"((D)[1]), "+f"((D)[2]), "+f"((D)[3]) \
        : "r"((A)[0]), "r"((A)[1]), "r"((A)[2]), "r"((A)[3]), "r"(B0), "r"(B1))
#define CP16(dst, src) \
    asm volatile("cp.async.cg.shared.global [%0], [%1], 16;" :: "r"(dst), "l"(src))
#define CP_COMMIT() asm volatile("cp.async.commit_group;" ::: "memory")
#define CP_WAIT0()  asm volatile("cp.async.wait_group 0;" ::: "memory")

// z chunk copy: E (8x8 block layout) + Xs (row-major) -> one pipeline buffer
__device__ __forceinline__ void z_copy(uint32_t dst, int b, int nc, int mc, int tid) {
    size_t ebase = (size_t)(b * 32 + nc) * EBLK;
    // E: 2 planes x 16 br x 4 bc x 8 rows = 1024 cp16
    for (int i = tid; i < 1024; i += 256) {
        int r8 = i & 7, bcL = (i >> 3) & 3, br = (i >> 5) & 15, pl = i >> 9;
        size_t src = ebase + ((size_t)br * 512 + mc * 4 + bcL) * 64 + r8 * 8;
        uint32_t d = dst + (uint32_t)(pl * EPL2 + (br * 8 + r8) * (TSK2 * 2) + bcL * 16);
        CP16(d, (pl ? gElo : gEhi) + src);
    }
    // Xs: 2 planes x 128 c-rows x 4 segs = 1024 cp16
    for (int i = tid; i < 1024; i += 256) {
        int seg = i & 3, cr = (i >> 2) & 127, pl = i >> 9;
        const __nv_bfloat16* xs = pl ? gXslo : gXshi;
        uint32_t d = dst + (uint32_t)(2 * EPL2 + pl * EPL2 + cr * (TSK2 * 2) + seg * 16);
        CP16(d, xs + (size_t)(b * C_ + cr) * N_ + mc * 32 + seg * 8);
    }
}

// ---------------- proj: 1x1 conv -> split bf16 hi/lo arrays ----------------
__global__ __launch_bounds__(256) void proj_kernel(
        const float* __restrict__ in, const float* __restrict__ w,
        const float* __restrict__ bias, int which)
{
    __shared__ float it[C_ * 36];
    int b = blockIdx.y, n0 = blockIdx.x * 32;
    int tid = threadIdx.x;
    for (int i = tid; i < C_ * 32; i += 256) {
        int ci = i >> 5, nl = i & 31;
        it[ci * 36 + nl] = in[(b * C_ + ci) * N_ + n0 + nl];
    }
    __syncthreads();
    int co = tid >> 1, nlh = (tid & 1) * 16;
    float bv = bias[co];
    float4 acc[4];
#pragma unroll
    for (int q = 0; q < 4; q++) acc[q] = make_float4(bv, bv, bv, bv);
#pragma unroll 4
    for (int ci = 0; ci < C_; ci++) {
        float wv = __ldg(w + co * C_ + ci);
        const float4* zr = (const float4*)(it + ci * 36 + nlh);
#pragma unroll
        for (int q = 0; q < 4; q++) fma4(acc[q], wv, zr[q]);
    }
    float av[16];
#pragma unroll
    for (int q = 0; q < 4; q++) {
        av[4 * q] = acc[q].x; av[4 * q + 1] = acc[q].y;
        av[4 * q + 2] = acc[q].z; av[4 * q + 3] = acc[q].w;
    }
    __nv_bfloat16 h[16], l[16];
#pragma unroll
    for (int i = 0; i < 16; i++) {
        h[i] = __float2bfloat16(av[i]);
        l[i] = __float2bfloat16(av[i] - __bfloat162float(h[i]));
    }
    if (which) {
#pragma unroll
        for (int i = 0; i < 16; i++) {
            size_t idx = (size_t)(b * N_ + n0 + nlh + i) * C_ + co;
            gYhi[idx] = h[i]; gYlo[idx] = l[i];
        }
    } else {
#pragma unroll
        for (int i = 0; i < 16; i++) {
            size_t idx = (size_t)(b * N_ + n0 + nlh + i) * C_ + co;
            gXhi[idx] = h[i]; gXlo[idx] = l[i];
        }
        uint32_t ph[8], pl[8];
#pragma unroll
        for (int j = 0; j < 8; j++) {
            ph[j] = (uint32_t)__bfloat16_as_ushort(h[2 * j]) |
                    ((uint32_t)__bfloat16_as_ushort(h[2 * j + 1]) << 16);
            pl[j] = (uint32_t)__bfloat16_as_ushort(l[2 * j]) |
                    ((uint32_t)__bfloat16_as_ushort(l[2 * j + 1]) << 16);
        }
        size_t tidx = (size_t)(b * C_ + co) * N_ + n0 + nlh;
        *(uint4*)(gXthi + tidx)     = make_uint4(ph[0], ph[1], ph[2], ph[3]);
        *(uint4*)(gXthi + tidx + 8) = make_uint4(ph[4], ph[5], ph[6], ph[7]);
        *(uint4*)(gXtlo + tidx)     = make_uint4(pl[0], pl[1], pl[2], pl[3]);
        *(uint4*)(gXtlo + tidx + 8) = make_uint4(pl[4], pl[5], pl[6], pl[7]);
    }
}

// ---------------------------------------------------------------------------
// stats: CTA owns 64 m; loops 32 n-chunks (single-buffered X, 2 CTAs/SM).
// Warp grid 4(n) x 2(m): warp tile 32n x 32m -> frags mt=2, nt=4.
// S = X@Y^T (3-pass split HMMA); E=exp(S) -> split bf16, 8x8-block stores;
// per-column expsums.
// ---------------------------------------------------------------------------
__global__ __launch_bounds__(256, 2) void stats_kernel()
{
    extern __shared__ char sm[];
    const int OX = 2 * YPL;
    float* red = (float*)(sm + OX + 2 * XPL);  // [4][64]
    float* cs  = red + 256;                    // [64]

    int tid = threadIdx.x, wid = tid >> 5, lane = tid & 31;
    int gid = lane >> 2, tig = lane & 3;
    int wn = wid >> 1, wm = wid & 1;
    int b = blockIdx.y, mblk = blockIdx.x, m0 = mblk * 64;
    uint32_t smb = smem_u32(sm);

    // prologue: Y resident (64 rows x 128 c, hi+lo)
    for (int i = tid; i < 1024; i += 256) {
        int row = i >> 4, seg = i & 15;
        uint32_t doff = (uint32_t)(row * TS * 2 + seg * 16);
        CP16(smb + doff,       gYhi + (size_t)(b * N_ + m0 + row) * C_ + seg * 8);
        CP16(smb + YPL + doff, gYlo + (size_t)(b * N_ + m0 + row) * C_ + seg * 8);
    }
    CP_COMMIT();
    if (tid < 64) cs[tid] = 0.0f;

    uint32_t aOff = (uint32_t)(((wn * 32 + (lane & 15)) * TS + ((lane >> 4) << 3)) * 2);
    uint32_t bHi  = smb + (uint32_t)(((wm * 32 + (lane & 7)) * TS +
                                      (((lane >> 3) & 1) << 3)) * 2);
    uint32_t bLo  = bHi + YPL;

    for (int nc = 0; nc < 32; nc++) {
        // X chunk (buffer free: prev iter ended with __syncthreads)
        for (int i = tid; i < 2048; i += 256) {
            int row = i >> 4, seg = i & 15;
            uint32_t doff = (uint32_t)(OX + row * TS * 2 + seg * 16);
            CP16(smb + doff,       gXhi + (size_t)(b * N_ + nc * 128 + row) * C_ + seg * 8);
            CP16(smb + XPL + doff, gXlo + (size_t)(b * N_ + nc * 128 + row) * C_ + seg * 8);
        }
        CP_COMMIT(); CP_WAIT0();
        __syncthreads();

        uint32_t aHi = smb + OX + aOff, aLo = aHi + XPL;
        float sf[2][4][4];
#pragma unroll
        for (int mt = 0; mt < 2; mt++)
#pragma unroll
            for (int nt = 0; nt < 4; nt++)
#pragma unroll
                for (int q = 0; q < 4; q++) sf[mt][nt][q] = 0.0f;

#pragma unroll
        for (int k = 0; k < 8; k++) {
            uint32_t bh[4][2], bl[4][2];
#pragma unroll
            for (int nt = 0; nt < 4; nt++) {
                LDM_X2(bh[nt][0], bh[nt][1], bHi + nt * (8 * TS * 2) + k * 32);
                LDM_X2(bl[nt][0], bl[nt][1], bLo + nt * (8 * TS * 2) + k * 32);
            }
#pragma unroll
            for (int mt = 0; mt < 2; mt++) {
                uint32_t ah[4], al[4];
                LDM_X4(ah[0], ah[1], ah[2], ah[3], aHi + mt * (16 * TS * 2) + k * 32);
                LDM_X4(al[0], al[1], al[2], al[3], aLo + mt * (16 * TS * 2) + k * 32);
#pragma unroll
                for (int nt = 0; nt < 4; nt++) {
                    MMA(sf[mt][nt], ah, bh[nt][0], bh[nt][1]);
                    MMA(sf[mt][nt], ah, bl[nt][0], bl[nt][1]);
                    MMA(sf[mt][nt], al, bh[nt][0], bh[nt][1]);
                }
            }
        }

        // epilogue: exp, split, 8x8-block stores, column sums
        size_t ebase = (size_t)(b * 32 + nc) * EBLK;
        float csum[4][2];
#pragma unroll
        for (int nt = 0; nt < 4; nt++) { csum[nt][0] = 0.f; csum[nt][1] = 0.f; }
#pragma unroll
        for (int mt = 0; mt < 2; mt++) {
#pragma unroll
            for (int nt = 0; nt < 4; nt++) {
                float e0 = fexp(sf[mt][nt][0]), e1 = fexp(sf[mt][nt][1]);
                float e2 = fexp(sf[mt][nt][2]), e3 = fexp(sf[mt][nt][3]);
                __nv_bfloat16 h0 = __float2bfloat16(e0), h1 = __float2bfloat16(e1);
                __nv_bfloat16 h2 = __float2bfloat16(e2), h3 = __float2bfloat16(e3);
                float r0 = e0 - __bfloat162float(h0), r1 = e1 - __bfloat162float(h1);
                float r2 = e2 - __bfloat162float(h2), r3 = e3 - __bfloat162float(h3);
                uint32_t hu0 = (uint32_t)__bfloat16_as_ushort(h0) |
                               ((uint32_t)__bfloat16_as_ushort(h1) << 16);
                uint32_t hu1 = (uint32_t)__bfloat16_as_ushort(h2) |
                               ((uint32_t)__bfloat16_as_ushort(h3) << 16);
                int br = wn * 4 + mt * 2;
                int bc = mblk * 8 + wm * 4 + nt;
                size_t o0 = ebase + ((size_t)br * 512 + bc) * 64 + gid * 8 + 2 * tig;
                __stcs((uint32_t*)(gEhi + o0), hu0);
                __stcs((uint32_t*)(gEhi + o0 + 32768), hu1);   // br+1 block
                __stcs((uint32_t*)(gElo + o0), pack_bf2(r0, r1));
                __stcs((uint32_t*)(gElo + o0 + 32768), pack_bf2(r2, r3));
                csum[nt][0] += e0 + e2;
                csum[nt][1] += e1 + e3;
            }
        }
#pragma unroll
        for (int nt = 0; nt < 4; nt++)
#pragma unroll
            for (int j = 0; j < 2; j++) {
                float v = csum[nt][j];
#pragma unroll
                for (int o = 4; o < 32; o <<= 1)
                    v += __shfl_xor_sync(0xFFFFFFFFu, v, o);
                if (gid == 0)
                    red[wn * 64 + wm * 32 + nt * 8 + 2 * tig + j] = v;
            }
        __syncthreads();   // red ready; X-buffer reads done
        if (tid < 64)
            cs[tid] += red[tid] + red[64 + tid] + red[128 + tid] + red[192 + tid];
    }

    __syncthreads();
    if (tid < 64) gInvD[b * N_ + m0 + tid] = 1.0f / cs[tid];
}

// ---------------- xscale: Xs[c][m] = (Xt_hi+Xt_lo)[c][m] * invD[m], re-split ----
__global__ __launch_bounds__(256) void xscale_kernel()
{
    __shared__ float dv[128];
    int b = blockIdx.y, m0 = blockIdx.x * 128;
    int tid = threadIdx.x;
    if (tid < 128) dv[tid] = gInvD[b * N_ + m0 + tid];
    __syncthreads();
    for (int i = tid; i < 128 * 64; i += 256) {
        int c = i >> 6, mp = (i & 63) * 2;
        size_t idx = (size_t)(b * C_ + c) * N_ + m0 + mp;
        uint32_t hw = *(const uint32_t*)(gXthi + idx);
        uint32_t lw = *(const uint32_t*)(gXtlo + idx);
        float v0 = __bfloat162float(__ushort_as_bfloat16((unsigned short)(hw & 0xFFFF))) +
                   __bfloat162float(__ushort_as_bfloat16((unsigned short)(lw & 0xFFFF)));
        float v1 = __bfloat162float(__ushort_as_bfloat16((unsigned short)(hw >> 16))) +
                   __bfloat162float(__ushort_as_bfloat16((unsigned short)(lw >> 16)));
        v0 *= dv[mp]; v1 *= dv[mp + 1];
        __nv_bfloat16 h0 = __float2bfloat16(v0), h1 = __float2bfloat16(v1);
        float r0 = v0 - __bfloat162float(h0), r1 = v1 - __bfloat162float(h1);
        *(uint32_t*)(gXshi + idx) = (uint32_t)__bfloat16_as_ushort(h0) |
                                    ((uint32_t)__bfloat16_as_ushort(h1) << 16);
        *(uint32_t*)(gXslo + idx) = pack_bf2(r0, r1);
    }
}

// ---------------------------------------------------------------------------
// z: pure copy-fed split-GEMM, 128n x 128c CTA tile, 2 CTAs/SM.
// z[n][c] = sum_m E[n][m] * Xs[c][m]; 128 chunks of K=32, depth-2 ring.
// Warp grid 2(n) x 4(c): warp tile 64n x 32c -> frags mt=4, nt=4.
// ---------------------------------------------------------------------------
__global__ __launch_bounds__(256, 2) void z_kernel()
{
    extern __shared__ char sm[];
    int tid = threadIdx.x, wid = tid >> 5, lane = tid & 31;
    int gid = lane >> 2, tig = lane & 3;
    int wn = wid >> 2, wm = wid & 3;
    int b = blockIdx.y, nc = blockIdx.x, n0 = nc * 128;
    uint32_t smb = smem_u32(sm);

    z_copy(smb, b, nc, 0, tid);
    CP_COMMIT();

    uint32_t aOff = (uint32_t)(((wn * 64 + (lane & 15)) * TSK2 +
                                ((lane >> 4) << 3)) * 2);
    uint32_t bOff = (uint32_t)(2 * EPL2 + ((wm * 32 + (lane & 7)) * TSK2 +
                                           (((lane >> 3) & 1) << 3)) * 2);

    float zf[4][4][4];
#pragma unroll
    for (int mt = 0; mt < 4; mt++)
#pragma unroll
        for (int nt = 0; nt < 4; nt++)
#pragma unroll
            for (int q = 0; q < 4; q++) zf[mt][nt][q] = 0.0f;

    for (int mc = 0; mc < 128; mc++) {
        CP_WAIT0();
        __syncthreads();
        if (mc + 1 < 128) {
            z_copy(smb + ((mc + 1) & 1) * ZBUF2, b, nc, mc + 1, tid);
            CP_COMMIT();
        }

        uint32_t base = smb + (mc & 1) * ZBUF2;
        uint32_t aHi = base + aOff, aLo = aHi + EPL2;
        uint32_t bHi = base + bOff, bLo = bHi + EPL2;
#pragma unroll
        for (int k = 0; k < 2; k++) {
            uint32_t bh[4][2], bl[4][2];
#pragma unroll
            for (int nt = 0; nt < 4; nt++) {
                LDM_X2(bh[nt][0], bh[nt][1], bHi + nt * (8 * TSK2 * 2) + k * 32);
                LDM_X2(bl[nt][0], bl[nt][1], bLo + nt * (8 * TSK2 * 2) + k * 32);
            }
#pragma unroll
            for (int mt = 0; mt < 4; mt++) {
                uint32_t ah[4], al[4];
                LDM_X4(ah[0], ah[1], ah[2], ah[3], aHi + mt * (16 * TSK2 * 2) + k * 32);
                LDM_X4(al[0], al[1], al[2], al[3], aLo + mt * (16 * TSK2 * 2) + k * 32);
#pragma unroll
                for (int nt = 0; nt < 4; nt++) {
                    MMA(zf[mt][nt], ah, bh[nt][0], bh[nt][1]);
                    MMA(zf[mt][nt], ah, bl[nt][0], bl[nt][1]);
                    MMA(zf[mt][nt], al, bh[nt][0], bh[nt][1]);
                }
            }
        }
    }

    // epilogue -> gZ[b][n][c]
#pragma unroll
    for (int mt = 0; mt < 4; mt++) {
        int n = n0 + wn * 64 + mt * 16 + gid;
#pragma unroll
        for (int nt = 0; nt < 4; nt++) {
            int c = wm * 32 + nt * 8 + 2 * tig;
            *(float2*)(gZ + (size_t)(b * N_ + n) * C_ + c) =
                make_float2(zf[mt][nt][0], zf[mt][nt][1]);
            *(float2*)(gZ + (size_t)(b * N_ + n + 8) * C_ + c) =
                make_float2(zf[mt][nt][2], zf[mt][nt][3]);
        }
    }
}

// ---------------- outproj ----------------
__global__ __launch_bounds__(256) void outproj_kernel(
        const float* __restrict__ w, const float* __restrict__ bias,
        float* __restrict__ out)
{
    __shared__ float zt[C_ * 36];
    int b = blockIdx.y, n0 = blockIdx.x * 32;
    int tid = threadIdx.x;
    const float* Zb = gZ + (size_t)b * N_ * C_;
    for (int i = tid; i < 32 * C_; i += 256) {
        int nl = i >> 7, ci = i & 127;
        zt[ci * 36 + nl] = Zb[(n0 + nl) * C_ + ci];
    }
    __syncthreads();
    int co = tid >> 1, nlh = (tid & 1) * 16;
    float bv = bias[co];
    float4 acc[4];
#pragma unroll
    for (int q = 0; q < 4; q++) acc[q] = make_float4(bv, bv, bv, bv);
#pragma unroll 4
    for (int ci = 0; ci < C_; ci++) {
        float wv = __ldg(w + co * C_ + ci);
        const float4* zr = (const float4*)(zt + ci * 36 + nlh);
#pragma unroll
        for (int q = 0; q < 4; q++) fma4(acc[q], wv, zr[q]);
    }
    float* op = out + (b * C_ + co) * N_ + n0 + nlh;
#pragma unroll
    for (int q = 0; q < 4; q++) *(float4*)(op + 4 * q) = acc[q];
}

// ---------------------------------------------------------------------------
extern "C" void kernel_launch(void* const* d_in, const int* in_sizes, int n_in,
                              void* d_out, int out_size)
{
    const float* cur  = (const float*)d_in[0];
    const float* ref  = (const float*)d_in[1];
    const float* th_w = (const float*)d_in[2];
    const float* th_b = (const float*)d_in[3];
    const float* ph_w = (const float*)d_in[4];
    const float* ph_b = (const float*)d_in[5];
    const float* W_w  = (const float*)d_in[6];
    const float* W_b  = (const float*)d_in[7];
    float* out = (float*)d_out;

    const int stats_smem = 2 * YPL + 2 * XPL + 320 * (int)sizeof(float); // 105728
    const int z_smem     = 2 * ZBUF2;                                    // 81920
    cudaFuncSetAttribute(stats_kernel, cudaFuncAttributeMaxDynamicSharedMemorySize, stats_smem);
    cudaFuncSetAttribute(z_kernel,     cudaFuncAttributeMaxDynamicSharedMemorySize, z_smem);

    dim3 blk(256);
    proj_kernel<<<dim3(N_ / 32, B_), blk>>>(ref, th_w, th_b, 0);   // X (+ X^T)
    proj_kernel<<<dim3(N_ / 32, B_), blk>>>(cur, ph_w, ph_b, 1);   // Y
    stats_kernel<<<dim3(N_ / 64, B_), blk, stats_smem>>>();
    xscale_kernel<<<dim3(N_ / 128, B_), blk>>>();
    z_kernel<<<dim3(N_ / 128, B_), blk, z_smem>>>();
    outproj_kernel<<<dim3(N_ / 32, B_), blk>>>(W_w, W_b, out);
}

// round 11
// speedup vs baseline: 7.2244x; 1.1253x over previous
#include <cuda_runtime.h>
#include <cuda_bf16.h>
#include <cuda_fp16.h>
#include <cstdint>

#define B_ 8
#define C_ 128
#define N_ 4096
#define TS 136                     // bf16 128-col tile row stride (272B)
#define YPL (64 * TS * 2)          // 17408 B: 64x128 bf16 plane
#define XPL (128 * TS * 2)         // 34816 B: 128x128 bf16 plane
#define TSZ 72                     // z fp16 tile row stride (144B)
#define EPLZ (128 * TSZ * 2)       // 18432 B: 128x64 fp16 plane
#define ZB (2 * EPLZ)              // 36864 B per z chunk buffer (E, Xs)
#define EBLK (16 * 512 * 64)       // elems of gE per (b,nc): 128 x 4096

// ---------------- scratch (static device globals; no allocation) ----------------
__device__ __nv_bfloat16 gXhi [B_ * N_ * C_];   // theta(ref) hi, [b][n][c]
__device__ __nv_bfloat16 gXlo [B_ * N_ * C_];
__device__ __nv_bfloat16 gYhi [B_ * N_ * C_];   // phi(cur) hi, [b][m][c]
__device__ __nv_bfloat16 gYlo [B_ * N_ * C_];
__device__ __nv_bfloat16 gXthi[B_ * C_ * N_];   // theta(ref)^T hi, [b][c][n]
__device__ __nv_bfloat16 gXtlo[B_ * C_ * N_];
__device__ __half        gXs  [B_ * C_ * N_];   // invD-scaled X^T fp16, [b][c][m]
__device__ float gMhat[B_ * N_];                // per-column approx max of S[:,m]
__device__ float gInvD[B_ * N_];                // 1 / sum_n exp(S-Mhat)
__device__ float gZ[B_ * N_ * C_];              // attention out [b][n][c]
// exp(S - Mhat) fp16, 8x8-block layout: (b*32+nc)*EBLK + (br*512+bc)*64 + r8*8 + c8
__device__ __half gE[(size_t)B_ * N_ * N_];

// ---------------- fast exp on the FMA pipe ----------------
__device__ __forceinline__ float fexp(float x) {
    x = fmaxf(x, -87.0f);
    float t = fmaf(x, 1.4426950408889634f, 12582912.0f);
    float k = t - 12582912.0f;
    float f = fmaf(x, 1.4426950408889634f, -k);
    float p = 1.3333558146e-3f;
    p = fmaf(p, f, 9.6181291076e-3f);
    p = fmaf(p, f, 5.5504108664e-2f);
    p = fmaf(p, f, 2.4022650696e-1f);
    p = fmaf(p, f, 6.9314718056e-1f);
    p = fmaf(p, f, 1.0f);
    int ki = __float_as_int(t) - 0x4B400000;
    float sc = __int_as_float((ki + 127) << 23);
    return p * sc;
}
__device__ __forceinline__ void fma4(float4 &a, float s, const float4 &v) {
    a.x = fmaf(s, v.x, a.x); a.y = fmaf(s, v.y, a.y);
    a.z = fmaf(s, v.z, a.z); a.w = fmaf(s, v.w, a.w);
}
__device__ __forceinline__ uint32_t smem_u32(const void* p) {
    uint32_t a;
    asm("{ .reg .u64 t; cvta.to.shared.u64 t, %1; cvt.u32.u64 %0, t; }" : "=r"(a) : "l"(p));
    return a;
}
__device__ __forceinline__ uint32_t h2pack(float a, float b) {
    __half2 h = __floats2half2_rn(a, b);
    return *(uint32_t*)&h;
}

// ---------------- HMMA + ldmatrix + cp.async (base ISA) ----------------
#define LDM_X4(R0, R1, R2, R3, ADDR) \
    asm volatile("ldmatrix.sync.aligned.m8n8.x4.shared.b16 {%0,%1,%2,%3}, [%4];" \
        : "=r"(R0), "=r"(R1), "=r"(R2), "=r"(R3) : "r"(ADDR))
#define LDM_X2(R0, R1, ADDR) \
    asm volatile("ldmatrix.sync.aligned.m8n8.x2.shared.b16 {%0,%1}, [%2];" \
        : "=r"(R0), "=r"(R1) : "r"(ADDR))
#define MMA(D, A, B0, B1) \
    asm volatile("mma.sync.aligned.m16n8k16.row.col.f32.bf16.bf16.f32 " \
        "{%0,%1,%2,%3}, {%4,%5,%6,%7}, {%8,%9}, {%0,%1,%2,%3};" \
        : "+f"((D)[0]), "+f"((D)[1]), "+f"((D)[2]), "+f"((D)[3]) \
        : "r"((A)[0]), "r"((A)[1]), "r"((A)[2]), "r"((A)[3]), "r"(B0), "r"(B1))
#define MMAH(D, A, B0, B1) \
    asm volatile("mma.sync.aligned.m16n8k16.row.col.f32.f16.f16.f32 " \
        "{%0,%1,%2,%3}, {%4,%5,%6,%7}, {%8,%9}, {%0,%1,%2,%3};" \
        : "+f"((D)[0]), "+f"((D)[1]), "+f"((D)[2]), "+f"((D)[3]) \
        : "r"((A)[0]), "r"((A)[1]), "r"((A)[2]), "r"((A)[3]), "r"(B0), "r"(B1))
#define CP16(dst, src) \
    asm volatile("cp.async.cg.shared.global [%0], [%1], 16;" :: "r"(dst), "l"(src))
#define CP_COMMIT() asm volatile("cp.async.commit_group;" ::: "memory")
#define CP_WAIT0()  asm volatile("cp.async.wait_group 0;" ::: "memory")

// ---------------- proj: 1x1 conv -> split bf16 hi/lo arrays ----------------
__global__ __launch_bounds__(256) void proj_kernel(
        const float* __restrict__ in, const float* __restrict__ w,
        const float* __restrict__ bias, int which)
{
    __shared__ float it[C_ * 36];
    int b = blockIdx.y, n0 = blockIdx.x * 32;
    int tid = threadIdx.x;
    for (int i = tid; i < C_ * 32; i += 256) {
        int ci = i >> 5, nl = i & 31;
        it[ci * 36 + nl] = in[(b * C_ + ci) * N_ + n0 + nl];
    }
    __syncthreads();
    int co = tid >> 1, nlh = (tid & 1) * 16;
    float bv = bias[co];
    float4 acc[4];
#pragma unroll
    for (int q = 0; q < 4; q++) acc[q] = make_float4(bv, bv, bv, bv);
#pragma unroll 4
    for (int ci = 0; ci < C_; ci++) {
        float wv = __ldg(w + co * C_ + ci);
        const float4* zr = (const float4*)(it + ci * 36 + nlh);
#pragma unroll
        for (int q = 0; q < 4; q++) fma4(acc[q], wv, zr[q]);
    }
    float av[16];
#pragma unroll
    for (int q = 0; q < 4; q++) {
        av[4 * q] = acc[q].x; av[4 * q + 1] = acc[q].y;
        av[4 * q + 2] = acc[q].z; av[4 * q + 3] = acc[q].w;
    }
    __nv_bfloat16 h[16], l[16];
#pragma unroll
    for (int i = 0; i < 16; i++) {
        h[i] = __float2bfloat16(av[i]);
        l[i] = __float2bfloat16(av[i] - __bfloat162float(h[i]));
    }
    if (which) {
#pragma unroll
        for (int i = 0; i < 16; i++) {
            size_t idx = (size_t)(b * N_ + n0 + nlh + i) * C_ + co;
            gYhi[idx] = h[i]; gYlo[idx] = l[i];
        }
    } else {
#pragma unroll
        for (int i = 0; i < 16; i++) {
            size_t idx = (size_t)(b * N_ + n0 + nlh + i) * C_ + co;
            gXhi[idx] = h[i]; gXlo[idx] = l[i];
        }
        uint32_t ph[8], pl[8];
#pragma unroll
        for (int j = 0; j < 8; j++) {
            ph[j] = (uint32_t)__bfloat16_as_ushort(h[2 * j]) |
                    ((uint32_t)__bfloat16_as_ushort(h[2 * j + 1]) << 16);
            pl[j] = (uint32_t)__bfloat16_as_ushort(l[2 * j]) |
                    ((uint32_t)__bfloat16_as_ushort(l[2 * j + 1]) << 16);
        }
        size_t tidx = (size_t)(b * C_ + co) * N_ + n0 + nlh;
        *(uint4*)(gXthi + tidx)     = make_uint4(ph[0], ph[1], ph[2], ph[3]);
        *(uint4*)(gXthi + tidx + 8) = make_uint4(ph[4], ph[5], ph[6], ph[7]);
        *(uint4*)(gXtlo + tidx)     = make_uint4(pl[0], pl[1], pl[2], pl[3]);
        *(uint4*)(gXtlo + tidx + 8) = make_uint4(pl[4], pl[5], pl[6], pl[7]);
    }
}

// ---------------------------------------------------------------------------
// maxpass: approx column max of S via 1-pass bf16 (hi planes only).
// CTA owns 64 m; loops 32 n-chunks of 128. Warp grid 4(n) x 2(m).
// ---------------------------------------------------------------------------
__global__ __launch_bounds__(256) void maxpass_kernel()
{
    extern __shared__ char sm[];
    const int OXH = YPL;
    float* red = (float*)(sm + OXH + XPL);   // [4][64]
    float* cm  = red + 256;                  // [64]

    int tid = threadIdx.x, wid = tid >> 5, lane = tid & 31;
    int gid = lane >> 2, tig = lane & 3;
    int wn = wid >> 1, wm = wid & 1;
    int b = blockIdx.y, m0 = blockIdx.x * 64;
    uint32_t smb = smem_u32(sm);

    for (int i = tid; i < 1024; i += 256) {
        int row = i >> 4, seg = i & 15;
        CP16(smb + (uint32_t)(row * TS * 2 + seg * 16),
             gYhi + (size_t)(b * N_ + m0 + row) * C_ + seg * 8);
    }
    CP_COMMIT();
    if (tid < 64) cm[tid] = -3.0e38f;

    uint32_t aOff = (uint32_t)(((wn * 32 + (lane & 15)) * TS + ((lane >> 4) << 3)) * 2);
    uint32_t bHi  = smb + (uint32_t)(((wm * 32 + (lane & 7)) * TS +
                                      (((lane >> 3) & 1) << 3)) * 2);

    for (int nc = 0; nc < 32; nc++) {
        for (int i = tid; i < 2048; i += 256) {
            int row = i >> 4, seg = i & 15;
            CP16(smb + (uint32_t)(OXH + row * TS * 2 + seg * 16),
                 gXhi + (size_t)(b * N_ + nc * 128 + row) * C_ + seg * 8);
        }
        CP_COMMIT(); CP_WAIT0();
        __syncthreads();

        uint32_t aHi = smb + OXH + aOff;
        float sf[2][4][4];
#pragma unroll
        for (int mt = 0; mt < 2; mt++)
#pragma unroll
            for (int nt = 0; nt < 4; nt++)
#pragma unroll
                for (int q = 0; q < 4; q++) sf[mt][nt][q] = 0.0f;

#pragma unroll
        for (int k = 0; k < 8; k++) {
            uint32_t bh[4][2];
#pragma unroll
            for (int nt = 0; nt < 4; nt++)
                LDM_X2(bh[nt][0], bh[nt][1], bHi + nt * (8 * TS * 2) + k * 32);
#pragma unroll
            for (int mt = 0; mt < 2; mt++) {
                uint32_t ah[4];
                LDM_X4(ah[0], ah[1], ah[2], ah[3], aHi + mt * (16 * TS * 2) + k * 32);
#pragma unroll
                for (int nt = 0; nt < 4; nt++)
                    MMA(sf[mt][nt], ah, bh[nt][0], bh[nt][1]);
            }
        }

        // column max partials
#pragma unroll
        for (int nt = 0; nt < 4; nt++)
#pragma unroll
            for (int j = 0; j < 2; j++) {
                float v = fmaxf(fmaxf(sf[0][nt][j], sf[0][nt][2 + j]),
                                fmaxf(sf[1][nt][j], sf[1][nt][2 + j]));
#pragma unroll
                for (int o = 4; o < 32; o <<= 1)
                    v = fmaxf(v, __shfl_xor_sync(0xFFFFFFFFu, v, o));
                if (gid == 0)
                    red[wn * 64 + wm * 32 + nt * 8 + 2 * tig + j] = v;
            }
        __syncthreads();
        if (tid < 64)
            cm[tid] = fmaxf(cm[tid], fmaxf(fmaxf(red[tid], red[64 + tid]),
                                           fmaxf(red[128 + tid], red[192 + tid])));
        __syncthreads();
    }
    if (tid < 64) gMhat[b * N_ + m0 + tid] = cm[tid] + 0.15f;
}

// ---------------------------------------------------------------------------
// stats: CTA owns 64 m; loops 32 n-chunks. S = X@Y^T (3-pass split HMMA);
// E = exp(S - Mhat) -> fp16 single plane, 8x8-block stores; column sums over
// the ROUNDED values -> invD. Warp grid 4(n) x 2(m).
// ---------------------------------------------------------------------------
__global__ __launch_bounds__(256, 2) void stats_kernel()
{
    extern __shared__ char sm[];
    const int OX = 2 * YPL;
    float* red = (float*)(sm + OX + 2 * XPL);  // [4][64]
    float* cs  = red + 256;                    // [64]

    int tid = threadIdx.x, wid = tid >> 5, lane = tid & 31;
    int gid = lane >> 2, tig = lane & 3;
    int wn = wid >> 1, wm = wid & 1;
    int b = blockIdx.y, mblk = blockIdx.x, m0 = mblk * 64;
    uint32_t smb = smem_u32(sm);

    for (int i = tid; i < 1024; i += 256) {
        int row = i >> 4, seg = i & 15;
        uint32_t doff = (uint32_t)(row * TS * 2 + seg * 16);
        CP16(smb + doff,       gYhi + (size_t)(b * N_ + m0 + row) * C_ + seg * 8);
        CP16(smb + YPL + doff, gYlo + (size_t)(b * N_ + m0 + row) * C_ + seg * 8);
    }
    CP_COMMIT();
    if (tid < 64) cs[tid] = 0.0f;

    // per-thread column Mhat (columns m0 + wm*32 + nt*8 + 2tig + j)
    float mh[4][2];
#pragma unroll
    for (int nt = 0; nt < 4; nt++)
#pragma unroll
        for (int j = 0; j < 2; j++)
            mh[nt][j] = gMhat[b * N_ + m0 + wm * 32 + nt * 8 + 2 * tig + j];

    uint32_t aOff = (uint32_t)(((wn * 32 + (lane & 15)) * TS + ((lane >> 4) << 3)) * 2);
    uint32_t bHi  = smb + (uint32_t)(((wm * 32 + (lane & 7)) * TS +
                                      (((lane >> 3) & 1) << 3)) * 2);
    uint32_t bLo  = bHi + YPL;

    for (int nc = 0; nc < 32; nc++) {
        for (int i = tid; i < 2048; i += 256) {
            int row = i >> 4, seg = i & 15;
            uint32_t doff = (uint32_t)(OX + row * TS * 2 + seg * 16);
            CP16(smb + doff,       gXhi + (size_t)(b * N_ + nc * 128 + row) * C_ + seg * 8);
            CP16(smb + XPL + doff, gXlo + (size_t)(b * N_ + nc * 128 + row) * C_ + seg * 8);
        }
        CP_COMMIT(); CP_WAIT0();
        __syncthreads();

        uint32_t aHi = smb + OX + aOff, aLo = aHi + XPL;
        float sf[2][4][4];
#pragma unroll
        for (int mt = 0; mt < 2; mt++)
#pragma unroll
            for (int nt = 0; nt < 4; nt++)
#pragma unroll
                for (int q = 0; q < 4; q++) sf[mt][nt][q] = 0.0f;

#pragma unroll
        for (int k = 0; k < 8; k++) {
            uint32_t bh[4][2], bl[4][2];
#pragma unroll
            for (int nt = 0; nt < 4; nt++) {
                LDM_X2(bh[nt][0], bh[nt][1], bHi + nt * (8 * TS * 2) + k * 32);
                LDM_X2(bl[nt][0], bl[nt][1], bLo + nt * (8 * TS * 2) + k * 32);
            }
#pragma unroll
            for (int mt = 0; mt < 2; mt++) {
                uint32_t ah[4], al[4];
                LDM_X4(ah[0], ah[1], ah[2], ah[3], aHi + mt * (16 * TS * 2) + k * 32);
                LDM_X4(al[0], al[1], al[2], al[3], aLo + mt * (16 * TS * 2) + k * 32);
#pragma unroll
                for (int nt = 0; nt < 4; nt++) {
                    MMA(sf[mt][nt], ah, bh[nt][0], bh[nt][1]);
                    MMA(sf[mt][nt], ah, bl[nt][0], bl[nt][1]);
                    MMA(sf[mt][nt], al, bh[nt][0], bh[nt][1]);
                }
            }
        }

        // epilogue: exp(S - Mhat), fp16 store (8x8 blocks), column sums
        size_t ebase = (size_t)(b * 32 + nc) * EBLK;
        float csum[4][2];
#pragma unroll
        for (int nt = 0; nt < 4; nt++) { csum[nt][0] = 0.f; csum[nt][1] = 0.f; }
#pragma unroll
        for (int mt = 0; mt < 2; mt++) {
#pragma unroll
            for (int nt = 0; nt < 4; nt++) {
                float e0 = fminf(fexp(sf[mt][nt][0] - mh[nt][0]), 60000.f);
                float e1 = fminf(fexp(sf[mt][nt][1] - mh[nt][1]), 60000.f);
                float e2 = fminf(fexp(sf[mt][nt][2] - mh[nt][0]), 60000.f);
                float e3 = fminf(fexp(sf[mt][nt][3] - mh[nt][1]), 60000.f);
                uint32_t u01 = h2pack(e0, e1), u23 = h2pack(e2, e3);
                // sum the ROUNDED values for softmax consistency
                __half2 h01 = *(__half2*)&u01, h23 = *(__half2*)&u23;
                float2 f01 = __half22float2(h01), f23 = __half22float2(h23);
                int br = wn * 4 + mt * 2;
                int bc = mblk * 8 + wm * 4 + nt;
                size_t o0 = ebase + ((size_t)br * 512 + bc) * 64 + gid * 8 + 2 * tig;
                __stcs((uint32_t*)(gE + o0), u01);
                __stcs((uint32_t*)(gE + o0 + 32768), u23);   // br+1 block
                csum[nt][0] += f01.x + f23.x;
                csum[nt][1] += f01.y + f23.y;
            }
        }
#pragma unroll
        for (int nt = 0; nt < 4; nt++)
#pragma unroll
            for (int j = 0; j < 2; j++) {
                float v = csum[nt][j];
#pragma unroll
                for (int o = 4; o < 32; o <<= 1)
                    v += __shfl_xor_sync(0xFFFFFFFFu, v, o);
                if (gid == 0)
                    red[wn * 64 + wm * 32 + nt * 8 + 2 * tig + j] = v;
            }
        __syncthreads();
        if (tid < 64)
            cs[tid] += red[tid] + red[64 + tid] + red[128 + tid] + red[192 + tid];
        __syncthreads();
    }

    if (tid < 64) gInvD[b * N_ + m0 + tid] = 1.0f / cs[tid];
}

// ---------------- xscale: Xs[c][m] = fp16((Xt_hi+Xt_lo)[c][m] * invD[m]) ----
__global__ __launch_bounds__(256) void xscale_kernel()
{
    __shared__ float dv[128];
    int b = blockIdx.y, m0 = blockIdx.x * 128;
    int tid = threadIdx.x;
    if (tid < 128) dv[tid] = gInvD[b * N_ + m0 + tid];
    __syncthreads();
    for (int i = tid; i < 128 * 64; i += 256) {
        int c = i >> 6, mp = (i & 63) * 2;
        size_t idx = (size_t)(b * C_ + c) * N_ + m0 + mp;
        uint32_t hw = *(const uint32_t*)(gXthi + idx);
        uint32_t lw = *(const uint32_t*)(gXtlo + idx);
        float v0 = __bfloat162float(__ushort_as_bfloat16((unsigned short)(hw & 0xFFFF))) +
                   __bfloat162float(__ushort_as_bfloat16((unsigned short)(lw & 0xFFFF)));
        float v1 = __bfloat162float(__ushort_as_bfloat16((unsigned short)(hw >> 16))) +
                   __bfloat162float(__ushort_as_bfloat16((unsigned short)(lw >> 16)));
        *(uint32_t*)(gXs + idx) = h2pack(v0 * dv[mp], v1 * dv[mp + 1]);
    }
}

// ---------------------------------------------------------------------------
// z: SINGLE-pass fp16 copy-fed GEMM. z[n][c] = sum_m E[n][m] * Xs[c][m].
// 128n x 128c CTA tile, 64 chunks of K=64, depth-2 ring, 2 CTAs/SM.
// Warp grid 2(n) x 4(c): warp tile 64n x 32c -> frags mt=4, nt=4.
// ---------------------------------------------------------------------------
__global__ __launch_bounds__(256, 2) void z_kernel()
{
    extern __shared__ char sm[];
    int tid = threadIdx.x, wid = tid >> 5, lane = tid & 31;
    int gid = lane >> 2, tig = lane & 3;
    int wn = wid >> 2, wm = wid & 3;
    int b = blockIdx.y, nc = blockIdx.x, n0 = nc * 128;
    uint32_t smb = smem_u32(sm);

    // chunk copy lambda-ish (macro-free): E blocks + Xs rows
    size_t ebase = (size_t)(b * 32 + nc) * EBLK;
    const __half* Xsb = gXs + (size_t)b * C_ * N_;

#define Z_COPY(DST, MC) do { \
    for (int i = tid; i < 1024; i += 256) { \
        int r8 = i & 7, bcL = (i >> 3) & 7, br = i >> 6; \
        size_t src = ebase + ((size_t)br * 512 + (MC) * 8 + bcL) * 64 + r8 * 8; \
        CP16((DST) + (uint32_t)((br * 8 + r8) * (TSZ * 2) + bcL * 16), gE + src); \
    } \
    for (int i = tid; i < 1024; i += 256) { \
        int seg = i & 7, cr = i >> 3; \
        CP16((DST) + (uint32_t)(EPLZ + cr * (TSZ * 2) + seg * 16), \
             Xsb + (size_t)cr * N_ + (MC) * 64 + seg * 8); \
    } \
} while (0)

    Z_COPY(smb, 0);
    CP_COMMIT();

    uint32_t aOff = (uint32_t)(((wn * 64 + (lane & 15)) * TSZ +
                                ((lane >> 4) << 3)) * 2);
    uint32_t bOff = (uint32_t)(EPLZ + ((wm * 32 + (lane & 7)) * TSZ +
                                       (((lane >> 3) & 1) << 3)) * 2);

    float zf[4][4][4];
#pragma unroll
    for (int mt = 0; mt < 4; mt++)
#pragma unroll
        for (int nt = 0; nt < 4; nt++)
#pragma unroll
            for (int q = 0; q < 4; q++) zf[mt][nt][q] = 0.0f;

    for (int mc = 0; mc < 64; mc++) {
        CP_WAIT0();
        __syncthreads();
        if (mc + 1 < 64) {
            Z_COPY(smb + ((mc + 1) & 1) * ZB, mc + 1);
            CP_COMMIT();
        }

        uint32_t base = smb + (mc & 1) * ZB;
        uint32_t aHi = base + aOff;
        uint32_t bHi = base + bOff;
#pragma unroll
        for (int k = 0; k < 4; k++) {
            uint32_t bh[4][2];
#pragma unroll
            for (int nt = 0; nt < 4; nt++)
                LDM_X2(bh[nt][0], bh[nt][1], bHi + nt * (8 * TSZ * 2) + k * 32);
#pragma unroll
            for (int mt = 0; mt < 4; mt++) {
                uint32_t ah[4];
                LDM_X4(ah[0], ah[1], ah[2], ah[3], aHi + mt * (16 * TSZ * 2) + k * 32);
#pragma unroll
                for (int nt = 0; nt < 4; nt++)
                    MMAH(zf[mt][nt], ah, bh[nt][0], bh[nt][1]);
            }
        }
    }
#undef Z_COPY

    // epilogue -> gZ[b][n][c]
#pragma unroll
    for (int mt = 0; mt < 4; mt++) {
        int n = n0 + wn * 64 + mt * 16 + gid;
#pragma unroll
        for (int nt = 0; nt < 4; nt++) {
            int c = wm * 32 + nt * 8 + 2 * tig;
            *(float2*)(gZ + (size_t)(b * N_ + n) * C_ + c) =
                make_float2(zf[mt][nt][0], zf[mt][nt][1]);
            *(float2*)(gZ + (size_t)(b * N_ + n + 8) * C_ + c) =
                make_float2(zf[mt][nt][2], zf[mt][nt][3]);
        }
    }
}

// ---------------- outproj ----------------
__global__ __launch_bounds__(256) void outproj_kernel(
        const float* __restrict__ w, const float* __restrict__ bias,
        float* __restrict__ out)
{
    __shared__ float zt[C_ * 36];
    int b = blockIdx.y, n0 = blockIdx.x * 32;
    int tid = threadIdx.x;
    const float* Zb = gZ + (size_t)b * N_ * C_;
    for (int i = tid; i < 32 * C_; i += 256) {
        int nl = i >> 7, ci = i & 127;
        zt[ci * 36 + nl] = Zb[(n0 + nl) * C_ + ci];
    }
    __syncthreads();
    int co = tid >> 1, nlh = (tid & 1) * 16;
    float bv = bias[co];
    float4 acc[4];
#pragma unroll
    for (int q = 0; q < 4; q++) acc[q] = make_float4(bv, bv, bv, bv);
#pragma unroll 4
    for (int ci = 0; ci < C_; ci++) {
        float wv = __ldg(w + co * C_ + ci);
        const float4* zr = (const float4*)(zt + ci * 36 + nlh);
#pragma unroll
        for (int q = 0; q < 4; q++) fma4(acc[q], wv, zr[q]);
    }
    float* op = out + (b * C_ + co) * N_ + n0 + nlh;
#pragma unroll
    for (int q = 0; q < 4; q++) *(float4*)(op + 4 * q) = acc[q];
}

// ---------------------------------------------------------------------------
extern "C" void kernel_launch(void* const* d_in, const int* in_sizes, int n_in,
                              void* d_out, int out_size)
{
    const float* cur  = (const float*)d_in[0];
    const float* ref  = (const float*)d_in[1];
    const float* th_w = (const float*)d_in[2];
    const float* th_b = (const float*)d_in[3];
    const float* ph_w = (const float*)d_in[4];
    const float* ph_b = (const float*)d_in[5];
    const float* W_w  = (const float*)d_in[6];
    const float* W_b  = (const float*)d_in[7];
    float* out = (float*)d_out;

    const int max_smem   = YPL + XPL + 320 * (int)sizeof(float);         // 53504
    const int stats_smem = 2 * YPL + 2 * XPL + 320 * (int)sizeof(float); // 105728
    const int z_smem     = 2 * ZB;                                       // 73728
    cudaFuncSetAttribute(maxpass_kernel, cudaFuncAttributeMaxDynamicSharedMemorySize, max_smem);
    cudaFuncSetAttribute(stats_kernel,   cudaFuncAttributeMaxDynamicSharedMemorySize, stats_smem);
    cudaFuncSetAttribute(z_kernel,       cudaFuncAttributeMaxDynamicSharedMemorySize, z_smem);

    dim3 blk(256);
    proj_kernel<<<dim3(N_ / 32, B_), blk>>>(ref, th_w, th_b, 0);   // X (+ X^T)
    proj_kernel<<<dim3(N_ / 32, B_), blk>>>(cur, ph_w, ph_b, 1);   // Y
    maxpass_kernel<<<dim3(N_ / 64, B_), blk, max_smem>>>();
    stats_kernel<<<dim3(N_ / 64, B_), blk, stats_smem>>>();
    xscale_kernel<<<dim3(N_ / 128, B_), blk>>>();
    z_kernel<<<dim3(N_ / 128, B_), blk, z_smem>>>();
    outproj_kernel<<<dim3(N_ / 32, B_), blk>>>(W_w, W_b, out);
}

// round 12
// speedup vs baseline: 7.4569x; 1.0322x over previous
#include <cuda_runtime.h>
#include <cuda_bf16.h>
#include <cuda_fp16.h>
#include <cstdint>

#define B_ 8
#define C_ 128
#define N_ 4096
#define TS 136                     // bf16 128-col tile row stride (272B)
#define YPL (64 * TS * 2)          // 17408 B: 64x128 bf16 plane
#define XPL (128 * TS * 2)         // 34816 B: 128x128 bf16 plane
#define XB64 (2 * YPL)             // 34816 B: one 64-row hi+lo X buffer (stats)
#define TSZ 72                     // z fp16 tile row stride (144B)
#define EPLZ (128 * TSZ * 2)       // 18432 B: 128x64 fp16 plane
#define ZB (2 * EPLZ)              // 36864 B per z chunk buffer (E, Xs)
#define EBLK (16 * 512 * 64)       // elems of gE per (b,nc): 128 x 4096

// ---------------- scratch (static device globals; no allocation) ----------------
__device__ __nv_bfloat16 gXhi [B_ * N_ * C_];   // theta(ref) hi, [b][n][c]
__device__ __nv_bfloat16 gXlo [B_ * N_ * C_];
__device__ __nv_bfloat16 gYhi [B_ * N_ * C_];   // phi(cur) hi, [b][m][c]
__device__ __nv_bfloat16 gYlo [B_ * N_ * C_];
__device__ __nv_bfloat16 gXthi[B_ * C_ * N_];   // theta(ref)^T hi, [b][c][n]
__device__ __nv_bfloat16 gXtlo[B_ * C_ * N_];
__device__ __half        gXs  [B_ * C_ * N_];   // invD-scaled X^T fp16, [b][c][m]
__device__ float gMhat[B_ * N_];                // per-column approx max of S[:,m]
__device__ float gInvD[B_ * N_];                // 1 / sum_n exp(S-Mhat)
__device__ float gZ[B_ * N_ * C_];              // attention out [b][n][c]
// exp(S - Mhat) fp16, 8x8-block layout: (b*32+nc)*EBLK + (br*512+bc)*64 + r8*8 + c8
__device__ __half gE[(size_t)B_ * N_ * N_];

// ---------------- fast exp on the FMA pipe ----------------
__device__ __forceinline__ float fexp(float x) {
    x = fmaxf(x, -87.0f);
    float t = fmaf(x, 1.4426950408889634f, 12582912.0f);
    float k = t - 12582912.0f;
    float f = fmaf(x, 1.4426950408889634f, -k);
    float p = 1.3333558146e-3f;
    p = fmaf(p, f, 9.6181291076e-3f);
    p = fmaf(p, f, 5.5504108664e-2f);
    p = fmaf(p, f, 2.4022650696e-1f);
    p = fmaf(p, f, 6.9314718056e-1f);
    p = fmaf(p, f, 1.0f);
    int ki = __float_as_int(t) - 0x4B400000;
    float sc = __int_as_float((ki + 127) << 23);
    return p * sc;
}
__device__ __forceinline__ void fma4(float4 &a, float s, const float4 &v) {
    a.x = fmaf(s, v.x, a.x); a.y = fmaf(s, v.y, a.y);
    a.z = fmaf(s, v.z, a.z); a.w = fmaf(s, v.w, a.w);
}
__device__ __forceinline__ uint32_t smem_u32(const void* p) {
    uint32_t a;
    asm("{ .reg .u64 t; cvta.to.shared.u64 t, %1; cvt.u32.u64 %0, t; }" : "=r"(a) : "l"(p));
    return a;
}
__device__ __forceinline__ uint32_t h2pack(float a, float b) {
    __half2 h = __floats2half2_rn(a, b);
    return *(uint32_t*)&h;
}

// ---------------- HMMA + ldmatrix + cp.async (base ISA) ----------------
#define LDM_X4(R0, R1, R2, R3, ADDR) \
    asm volatile("ldmatrix.sync.aligned.m8n8.x4.shared.b16 {%0,%1,%2,%3}, [%4];" \
        : "=r"(R0), "=r"(R1), "=r"(R2), "=r"(R3) : "r"(ADDR))
#define LDM_X2(R0, R1, ADDR) \
    asm volatile("ldmatrix.sync.aligned.m8n8.x2.shared.b16 {%0,%1}, [%2];" \
        : "=r"(R0), "=r"(R1) : "r"(ADDR))
#define MMA(D, A, B0, B1) \
    asm volatile("mma.sync.aligned.m16n8k16.row.col.f32.bf16.bf16.f32 " \
        "{%0,%1,%2,%3}, {%4,%5,%6,%7}, {%8,%9}, {%0,%1,%2,%3};" \
        : "+f"((D)[0]), "+f"((D)[1]), "+f"((D)[2]), "+f"((D)[3]) \
        : "r"((A)[0]), "r"((A)[1]), "r"((A)[2]), "r"((A)[3]), "r"(B0), "r"(B1))
#define MMAH(D, A, B0, B1) \
    asm volatile("mma.sync.aligned.m16n8k16.row.col.f32.f16.f16.f32 " \
        "{%0,%1,%2,%3}, {%4,%5,%6,%7}, {%8,%9}, {%0,%1,%2,%3};" \
        : "+f"((D)[0]), "+f"((D)[1]), "+f"((D)[2]), "+f"((D)[3]) \
        : "r"((A)[0]), "r"((A)[1]), "r"((A)[2]), "r"((A)[3]), "r"(B0), "r"(B1))
#define CP16(dst, src) \
    asm volatile("cp.async.cg.shared.global [%0], [%1], 16;" :: "r"(dst), "l"(src))
#define CP_COMMIT() asm volatile("cp.async.commit_group;" ::: "memory")
#define CP_WAIT0()  asm volatile("cp.async.wait_group 0;" ::: "memory")

// ---------------- proj: 1x1 conv -> split bf16 hi/lo arrays ----------------
__global__ __launch_bounds__(256) void proj_kernel(
        const float* __restrict__ in, const float* __restrict__ w,
        const float* __restrict__ bias, int which)
{
    __shared__ float it[C_ * 36];
    int b = blockIdx.y, n0 = blockIdx.x * 32;
    int tid = threadIdx.x;
    for (int i = tid; i < C_ * 32; i += 256) {
        int ci = i >> 5, nl = i & 31;
        it[ci * 36 + nl] = in[(b * C_ + ci) * N_ + n0 + nl];
    }
    __syncthreads();
    int co = tid >> 1, nlh = (tid & 1) * 16;
    float bv = bias[co];
    float4 acc[4];
#pragma unroll
    for (int q = 0; q < 4; q++) acc[q] = make_float4(bv, bv, bv, bv);
#pragma unroll 4
    for (int ci = 0; ci < C_; ci++) {
        float wv = __ldg(w + co * C_ + ci);
        const float4* zr = (const float4*)(it + ci * 36 + nlh);
#pragma unroll
        for (int q = 0; q < 4; q++) fma4(acc[q], wv, zr[q]);
    }
    float av[16];
#pragma unroll
    for (int q = 0; q < 4; q++) {
        av[4 * q] = acc[q].x; av[4 * q + 1] = acc[q].y;
        av[4 * q + 2] = acc[q].z; av[4 * q + 3] = acc[q].w;
    }
    __nv_bfloat16 h[16], l[16];
#pragma unroll
    for (int i = 0; i < 16; i++) {
        h[i] = __float2bfloat16(av[i]);
        l[i] = __float2bfloat16(av[i] - __bfloat162float(h[i]));
    }
    if (which) {
#pragma unroll
        for (int i = 0; i < 16; i++) {
            size_t idx = (size_t)(b * N_ + n0 + nlh + i) * C_ + co;
            gYhi[idx] = h[i]; gYlo[idx] = l[i];
        }
    } else {
#pragma unroll
        for (int i = 0; i < 16; i++) {
            size_t idx = (size_t)(b * N_ + n0 + nlh + i) * C_ + co;
            gXhi[idx] = h[i]; gXlo[idx] = l[i];
        }
        uint32_t ph[8], pl[8];
#pragma unroll
        for (int j = 0; j < 8; j++) {
            ph[j] = (uint32_t)__bfloat16_as_ushort(h[2 * j]) |
                    ((uint32_t)__bfloat16_as_ushort(h[2 * j + 1]) << 16);
            pl[j] = (uint32_t)__bfloat16_as_ushort(l[2 * j]) |
                    ((uint32_t)__bfloat16_as_ushort(l[2 * j + 1]) << 16);
        }
        size_t tidx = (size_t)(b * C_ + co) * N_ + n0 + nlh;
        *(uint4*)(gXthi + tidx)     = make_uint4(ph[0], ph[1], ph[2], ph[3]);
        *(uint4*)(gXthi + tidx + 8) = make_uint4(ph[4], ph[5], ph[6], ph[7]);
        *(uint4*)(gXtlo + tidx)     = make_uint4(pl[0], pl[1], pl[2], pl[3]);
        *(uint4*)(gXtlo + tidx + 8) = make_uint4(pl[4], pl[5], pl[6], pl[7]);
    }
}

// ---------------------------------------------------------------------------
// maxpass: approx column max of S (1-pass bf16 hi). CTA owns 64 m; loops 32
// n-chunks of 128, double-buffered. Running max in REGISTERS; one reduce at end.
// Warp grid 4(n) x 2(m).
// ---------------------------------------------------------------------------
__global__ __launch_bounds__(256, 2) void maxpass_kernel()
{
    extern __shared__ char sm[];
    const int OX = YPL;                       // two 128-row hi buffers follow Y
    float* red = (float*)(sm + OX + 2 * XPL); // [4][64]

    int tid = threadIdx.x, wid = tid >> 5, lane = tid & 31;
    int gid = lane >> 2, tig = lane & 3;
    int wn = wid >> 1, wm = wid & 1;
    int b = blockIdx.y, m0 = blockIdx.x * 64;
    uint32_t smb = smem_u32(sm);

    // prologue: Y hi + X chunk 0
    for (int i = tid; i < 1024; i += 256) {
        int row = i >> 4, seg = i & 15;
        CP16(smb + (uint32_t)(row * TS * 2 + seg * 16),
             gYhi + (size_t)(b * N_ + m0 + row) * C_ + seg * 8);
    }
    for (int i = tid; i < 2048; i += 256) {
        int row = i >> 4, seg = i & 15;
        CP16(smb + (uint32_t)(OX + row * TS * 2 + seg * 16),
             gXhi + (size_t)(b * N_ + row) * C_ + seg * 8);
    }
    CP_COMMIT();

    uint32_t aOff = (uint32_t)(((wn * 32 + (lane & 15)) * TS + ((lane >> 4) << 3)) * 2);
    uint32_t bHi  = smb + (uint32_t)(((wm * 32 + (lane & 7)) * TS +
                                      (((lane >> 3) & 1) << 3)) * 2);

    float mx[4][2];
#pragma unroll
    for (int nt = 0; nt < 4; nt++) { mx[nt][0] = -3.0e38f; mx[nt][1] = -3.0e38f; }

    for (int nc = 0; nc < 32; nc++) {
        CP_WAIT0();
        __syncthreads();
        if (nc + 1 < 32) {
            uint32_t nb = OX + XPL * ((nc + 1) & 1);
            for (int i = tid; i < 2048; i += 256) {
                int row = i >> 4, seg = i & 15;
                CP16(smb + nb + (uint32_t)(row * TS * 2 + seg * 16),
                     gXhi + (size_t)(b * N_ + (nc + 1) * 128 + row) * C_ + seg * 8);
            }
            CP_COMMIT();
        }

        uint32_t aHi = smb + OX + XPL * (nc & 1) + aOff;
        float sf[2][4][4];
#pragma unroll
        for (int mt = 0; mt < 2; mt++)
#pragma unroll
            for (int nt = 0; nt < 4; nt++)
#pragma unroll
                for (int q = 0; q < 4; q++) sf[mt][nt][q] = 0.0f;

#pragma unroll
        for (int k = 0; k < 8; k++) {
            uint32_t bh[4][2];
#pragma unroll
            for (int nt = 0; nt < 4; nt++)
                LDM_X2(bh[nt][0], bh[nt][1], bHi + nt * (8 * TS * 2) + k * 32);
#pragma unroll
            for (int mt = 0; mt < 2; mt++) {
                uint32_t ah[4];
                LDM_X4(ah[0], ah[1], ah[2], ah[3], aHi + mt * (16 * TS * 2) + k * 32);
#pragma unroll
                for (int nt = 0; nt < 4; nt++)
                    MMA(sf[mt][nt], ah, bh[nt][0], bh[nt][1]);
            }
        }

#pragma unroll
        for (int nt = 0; nt < 4; nt++)
#pragma unroll
            for (int j = 0; j < 2; j++)
                mx[nt][j] = fmaxf(mx[nt][j],
                    fmaxf(fmaxf(sf[0][nt][j], sf[0][nt][2 + j]),
                          fmaxf(sf[1][nt][j], sf[1][nt][2 + j])));
    }

    // single end-of-kernel reduction
#pragma unroll
    for (int nt = 0; nt < 4; nt++)
#pragma unroll
        for (int j = 0; j < 2; j++) {
            float v = mx[nt][j];
#pragma unroll
            for (int o = 4; o < 32; o <<= 1)
                v = fmaxf(v, __shfl_xor_sync(0xFFFFFFFFu, v, o));
            if (gid == 0)
                red[wn * 64 + wm * 32 + nt * 8 + 2 * tig + j] = v;
        }
    __syncthreads();
    if (tid < 64)
        gMhat[b * N_ + m0 + tid] =
            fmaxf(fmaxf(red[tid], red[64 + tid]),
                  fmaxf(red[128 + tid], red[192 + tid])) + 0.15f;
}

// ---------------------------------------------------------------------------
// stats: CTA owns 64 m; loops 64 n-chunks of 64 rows, double-buffered.
// S = X@Y^T (3-pass split HMMA); E = exp(S - Mhat) -> fp16 8x8-block stores;
// column sums in REGISTERS, one reduction at end. Warp grid 4(n) x 2(m), mt=1.
// ---------------------------------------------------------------------------
__global__ __launch_bounds__(256, 2) void stats_kernel()
{
    extern __shared__ char sm[];
    const int OX = 2 * YPL;                        // two 64-row hi+lo buffers
    float* red = (float*)(sm + OX + 2 * XB64);     // [4][64]

    int tid = threadIdx.x, wid = tid >> 5, lane = tid & 31;
    int gid = lane >> 2, tig = lane & 3;
    int wn = wid >> 1, wm = wid & 1;
    int b = blockIdx.y, mblk = blockIdx.x, m0 = mblk * 64;
    uint32_t smb = smem_u32(sm);

    // prologue: Y hi+lo + X chunk 0 (64 rows, hi+lo)
    for (int i = tid; i < 1024; i += 256) {
        int row = i >> 4, seg = i & 15;
        uint32_t doff = (uint32_t)(row * TS * 2 + seg * 16);
        CP16(smb + doff,       gYhi + (size_t)(b * N_ + m0 + row) * C_ + seg * 8);
        CP16(smb + YPL + doff, gYlo + (size_t)(b * N_ + m0 + row) * C_ + seg * 8);
    }
    for (int i = tid; i < 1024; i += 256) {
        int row = i >> 4, seg = i & 15;
        uint32_t doff = (uint32_t)(OX + row * TS * 2 + seg * 16);
        CP16(smb + doff,       gXhi + (size_t)(b * N_ + row) * C_ + seg * 8);
        CP16(smb + doff + YPL, gXlo + (size_t)(b * N_ + row) * C_ + seg * 8);
    }
    CP_COMMIT();

    // per-thread column Mhat (columns m0 + wm*32 + nt*8 + 2tig + j)
    float mh[4][2];
#pragma unroll
    for (int nt = 0; nt < 4; nt++)
#pragma unroll
        for (int j = 0; j < 2; j++)
            mh[nt][j] = gMhat[b * N_ + m0 + wm * 32 + nt * 8 + 2 * tig + j];

    uint32_t aOff = (uint32_t)(((wn * 16 + (lane & 15)) * TS + ((lane >> 4) << 3)) * 2);
    uint32_t bHi  = smb + (uint32_t)(((wm * 32 + (lane & 7)) * TS +
                                      (((lane >> 3) & 1) << 3)) * 2);
    uint32_t bLo  = bHi + YPL;

    float csum[4][2];
#pragma unroll
    for (int nt = 0; nt < 4; nt++) { csum[nt][0] = 0.f; csum[nt][1] = 0.f; }

    for (int nc = 0; nc < 64; nc++) {
        CP_WAIT0();
        __syncthreads();
        if (nc + 1 < 64) {
            uint32_t nb = OX + XB64 * ((nc + 1) & 1);
            for (int i = tid; i < 1024; i += 256) {
                int row = i >> 4, seg = i & 15;
                uint32_t doff = nb + (uint32_t)(row * TS * 2 + seg * 16);
                CP16(smb + doff,       gXhi + (size_t)(b * N_ + (nc + 1) * 64 + row) * C_ + seg * 8);
                CP16(smb + doff + YPL, gXlo + (size_t)(b * N_ + (nc + 1) * 64 + row) * C_ + seg * 8);
            }
            CP_COMMIT();
        }

        uint32_t aHi = smb + OX + XB64 * (nc & 1) + aOff;
        uint32_t aLo = aHi + YPL;
        float sf[4][4];
#pragma unroll
        for (int nt = 0; nt < 4; nt++)
#pragma unroll
            for (int q = 0; q < 4; q++) sf[nt][q] = 0.0f;

#pragma unroll
        for (int k = 0; k < 8; k++) {
            uint32_t bh[4][2], bl[4][2];
#pragma unroll
            for (int nt = 0; nt < 4; nt++) {
                LDM_X2(bh[nt][0], bh[nt][1], bHi + nt * (8 * TS * 2) + k * 32);
                LDM_X2(bl[nt][0], bl[nt][1], bLo + nt * (8 * TS * 2) + k * 32);
            }
            uint32_t ah[4], al[4];
            LDM_X4(ah[0], ah[1], ah[2], ah[3], aHi + k * 32);
            LDM_X4(al[0], al[1], al[2], al[3], aLo + k * 32);
#pragma unroll
            for (int nt = 0; nt < 4; nt++) {
                MMA(sf[nt], ah, bh[nt][0], bh[nt][1]);
                MMA(sf[nt], ah, bl[nt][0], bl[nt][1]);
                MMA(sf[nt], al, bh[nt][0], bh[nt][1]);
            }
        }

        // epilogue: exp(S - Mhat), fp16 8x8-block stores, register sums
        size_t ebase = (size_t)(b * 32 + (nc >> 1)) * EBLK;
        int br0 = (nc & 1) * 8 + wn * 2;
#pragma unroll
        for (int nt = 0; nt < 4; nt++) {
            float e0 = fminf(fexp(sf[nt][0] - mh[nt][0]), 60000.f);
            float e1 = fminf(fexp(sf[nt][1] - mh[nt][1]), 60000.f);
            float e2 = fminf(fexp(sf[nt][2] - mh[nt][0]), 60000.f);
            float e3 = fminf(fexp(sf[nt][3] - mh[nt][1]), 60000.f);
            uint32_t u01 = h2pack(e0, e1), u23 = h2pack(e2, e3);
            __half2 h01 = *(__half2*)&u01, h23 = *(__half2*)&u23;
            float2 f01 = __half22float2(h01), f23 = __half22float2(h23);
            int bc = mblk * 8 + wm * 4 + nt;
            size_t o0 = ebase + ((size_t)br0 * 512 + bc) * 64 + gid * 8 + 2 * tig;
            __stcs((uint32_t*)(gE + o0), u01);
            __stcs((uint32_t*)(gE + o0 + 32768), u23);   // br0+1 block
            csum[nt][0] += f01.x + f23.x;
            csum[nt][1] += f01.y + f23.y;
        }
    }

    // single end-of-kernel reduction -> invD
#pragma unroll
    for (int nt = 0; nt < 4; nt++)
#pragma unroll
        for (int j = 0; j < 2; j++) {
            float v = csum[nt][j];
#pragma unroll
            for (int o = 4; o < 32; o <<= 1)
                v += __shfl_xor_sync(0xFFFFFFFFu, v, o);
            if (gid == 0)
                red[wn * 64 + wm * 32 + nt * 8 + 2 * tig + j] = v;
        }
    __syncthreads();
    if (tid < 64)
        gInvD[b * N_ + m0 + tid] =
            1.0f / (red[tid] + red[64 + tid] + red[128 + tid] + red[192 + tid]);
}

// ---------------- xscale: Xs[c][m] = fp16((Xt_hi+Xt_lo)[c][m] * invD[m]) ----
__global__ __launch_bounds__(256) void xscale_kernel()
{
    __shared__ float dv[128];
    int b = blockIdx.y, m0 = blockIdx.x * 128;
    int tid = threadIdx.x;
    if (tid < 128) dv[tid] = gInvD[b * N_ + m0 + tid];
    __syncthreads();
    for (int i = tid; i < 128 * 64; i += 256) {
        int c = i >> 6, mp = (i & 63) * 2;
        size_t idx = (size_t)(b * C_ + c) * N_ + m0 + mp;
        uint32_t hw = *(const uint32_t*)(gXthi + idx);
        uint32_t lw = *(const uint32_t*)(gXtlo + idx);
        float v0 = __bfloat162float(__ushort_as_bfloat16((unsigned short)(hw & 0xFFFF))) +
                   __bfloat162float(__ushort_as_bfloat16((unsigned short)(lw & 0xFFFF)));
        float v1 = __bfloat162float(__ushort_as_bfloat16((unsigned short)(hw >> 16))) +
                   __bfloat162float(__ushort_as_bfloat16((unsigned short)(lw >> 16)));
        *(uint32_t*)(gXs + idx) = h2pack(v0 * dv[mp], v1 * dv[mp + 1]);
    }
}

// ---------------------------------------------------------------------------
// z: SINGLE-pass fp16 copy-fed GEMM. z[n][c] = sum_m E[n][m] * Xs[c][m].
// 128n x 128c CTA tile, 64 chunks of K=64, depth-2 ring, 2 CTAs/SM.
// ---------------------------------------------------------------------------
__global__ __launch_bounds__(256, 2) void z_kernel()
{
    extern __shared__ char sm[];
    int tid = threadIdx.x, wid = tid >> 5, lane = tid & 31;
    int gid = lane >> 2, tig = lane & 3;
    int wn = wid >> 2, wm = wid & 3;
    int b = blockIdx.y, nc = blockIdx.x, n0 = nc * 128;
    uint32_t smb = smem_u32(sm);

    size_t ebase = (size_t)(b * 32 + nc) * EBLK;
    const __half* Xsb = gXs + (size_t)b * C_ * N_;

#define Z_COPY(DST, MC) do { \
    for (int i = tid; i < 1024; i += 256) { \
        int r8 = i & 7, bcL = (i >> 3) & 7, br = i >> 6; \
        size_t src = ebase + ((size_t)br * 512 + (MC) * 8 + bcL) * 64 + r8 * 8; \
        CP16((DST) + (uint32_t)((br * 8 + r8) * (TSZ * 2) + bcL * 16), gE + src); \
    } \
    for (int i = tid; i < 1024; i += 256) { \
        int seg = i & 7, cr = i >> 3; \
        CP16((DST) + (uint32_t)(EPLZ + cr * (TSZ * 2) + seg * 16), \
             Xsb + (size_t)cr * N_ + (MC) * 64 + seg * 8); \
    } \
} while (0)

    Z_COPY(smb, 0);
    CP_COMMIT();

    uint32_t aOff = (uint32_t)(((wn * 64 + (lane & 15)) * TSZ +
                                ((lane >> 4) << 3)) * 2);
    uint32_t bOff = (uint32_t)(EPLZ + ((wm * 32 + (lane & 7)) * TSZ +
                                       (((lane >> 3) & 1) << 3)) * 2);

    float zf[4][4][4];
#pragma unroll
    for (int mt = 0; mt < 4; mt++)
#pragma unroll
        for (int nt = 0; nt < 4; nt++)
#pragma unroll
            for (int q = 0; q < 4; q++) zf[mt][nt][q] = 0.0f;

    for (int mc = 0; mc < 64; mc++) {
        CP_WAIT0();
        __syncthreads();
        if (mc + 1 < 64) {
            Z_COPY(smb + ((mc + 1) & 1) * ZB, mc + 1);
            CP_COMMIT();
        }

        uint32_t base = smb + (mc & 1) * ZB;
        uint32_t aHi = base + aOff;
        uint32_t bHi = base + bOff;
#pragma unroll
        for (int k = 0; k < 4; k++) {
            uint32_t bh[4][2];
#pragma unroll
            for (int nt = 0; nt < 4; nt++)
                LDM_X2(bh[nt][0], bh[nt][1], bHi + nt * (8 * TSZ * 2) + k * 32);
#pragma unroll
            for (int mt = 0; mt < 4; mt++) {
                uint32_t ah[4];
                LDM_X4(ah[0], ah[1], ah[2], ah[3], aHi + mt * (16 * TSZ * 2) + k * 32);
#pragma unroll
                for (int nt = 0; nt < 4; nt++)
                    MMAH(zf[mt][nt], ah, bh[nt][0], bh[nt][1]);
            }
        }
    }
#undef Z_COPY

    // epilogue -> gZ[b][n][c]
#pragma unroll
    for (int mt = 0; mt < 4; mt++) {
        int n = n0 + wn * 64 + mt * 16 + gid;
#pragma unroll
        for (int nt = 0; nt < 4; nt++) {
            int c = wm * 32 + nt * 8 + 2 * tig;
            *(float2*)(gZ + (size_t)(b * N_ + n) * C_ + c) =
                make_float2(zf[mt][nt][0], zf[mt][nt][1]);
            *(float2*)(gZ + (size_t)(b * N_ + n + 8) * C_ + c) =
                make_float2(zf[mt][nt][2], zf[mt][nt][3]);
        }
    }
}

// ---------------- outproj ----------------
__global__ __launch_bounds__(256) void outproj_kernel(
        const float* __restrict__ w, const float* __restrict__ bias,
        float* __restrict__ out)
{
    __shared__ float zt[C_ * 36];
    int b = blockIdx.y, n0 = blockIdx.x * 32;
    int tid = threadIdx.x;
    const float* Zb = gZ + (size_t)b * N_ * C_;
    for (int i = tid; i < 32 * C_; i += 256) {
        int nl = i >> 7, ci = i & 127;
        zt[ci * 36 + nl] = Zb[(n0 + nl) * C_ + ci];
    }
    __syncthreads();
    int co = tid >> 1, nlh = (tid & 1) * 16;
    float bv = bias[co];
    float4 acc[4];
#pragma unroll
    for (int q = 0; q < 4; q++) acc[q] = make_float4(bv, bv, bv, bv);
#pragma unroll 4
    for (int ci = 0; ci < C_; ci++) {
        float wv = __ldg(w + co * C_ + ci);
        const float4* zr = (const float4*)(zt + ci * 36 + nlh);
#pragma unroll
        for (int q = 0; q < 4; q++) fma4(acc[q], wv, zr[q]);
    }
    float* op = out + (b * C_ + co) * N_ + n0 + nlh;
#pragma unroll
    for (int q = 0; q < 4; q++) *(float4*)(op + 4 * q) = acc[q];
}

// ---------------------------------------------------------------------------
extern "C" void kernel_launch(void* const* d_in, const int* in_sizes, int n_in,
                              void* d_out, int out_size)
{
    const float* cur  = (const float*)d_in[0];
    const float* ref  = (const float*)d_in[1];
    const float* th_w = (const float*)d_in[2];
    const float* th_b = (const float*)d_in[3];
    const float* ph_w = (const float*)d_in[4];
    const float* ph_b = (const float*)d_in[5];
    const float* W_w  = (const float*)d_in[6];
    const float* W_b  = (const float*)d_in[7];
    float* out = (float*)d_out;

    const int max_smem   = YPL + 2 * XPL + 256 * (int)sizeof(float);   // 88064
    const int stats_smem = 2 * YPL + 2 * XB64 + 256 * (int)sizeof(float); // 105472
    const int z_smem     = 2 * ZB;                                     // 73728
    cudaFuncSetAttribute(maxpass_kernel, cudaFuncAttributeMaxDynamicSharedMemorySize, max_smem);
    cudaFuncSetAttribute(stats_kernel,   cudaFuncAttributeMaxDynamicSharedMemorySize, stats_smem);
    cudaFuncSetAttribute(z_kernel,       cudaFuncAttributeMaxDynamicSharedMemorySize, z_smem);

    dim3 blk(256);
    proj_kernel<<<dim3(N_ / 32, B_), blk>>>(ref, th_w, th_b, 0);   // X (+ X^T)
    proj_kernel<<<dim3(N_ / 32, B_), blk>>>(cur, ph_w, ph_b, 1);   // Y
    maxpass_kernel<<<dim3(N_ / 64, B_), blk, max_smem>>>();
    stats_kernel<<<dim3(N_ / 64, B_), blk, stats_smem>>>();
    xscale_kernel<<<dim3(N_ / 128, B_), blk>>>();
    z_kernel<<<dim3(N_ / 128, B_), blk, z_smem>>>();
    outproj_kernel<<<dim3(N_ / 32, B_), blk>>>(W_w, W_b, out);
}

// round 13
// speedup vs baseline: 7.9573x; 1.0671x over previous
#include <cuda_runtime.h>
#include <cuda_bf16.h>
#include <cuda_fp16.h>
#include <cstdint>

#define B_ 8
#define C_ 128
#define N_ 4096
#define TS 136                     // bf16 128-col tile row stride (272B)
#define YPL (64 * TS * 2)          // 17408 B: 64x128 bf16 plane
#define XPL (128 * TS * 2)         // 34816 B: 128x128 bf16 plane
#define XB64 (2 * YPL)             // 34816 B: one 64-row hi+lo X buffer
#define TSZ 72                     // z fp16 tile row stride (144B)
#define EPLZ (128 * TSZ * 2)       // 18432 B: 128x64 fp16 plane
#define ZB (2 * EPLZ)              // 36864 B per z chunk buffer (E, Xs)
#define EBLK (16 * 512 * 64)       // elems of gE per (b,nc): 128 x 4096

// ---------------- scratch (static device globals; no allocation) ----------------
__device__ __nv_bfloat16 gXhi [B_ * N_ * C_];   // theta(ref) hi, [b][n][c]
__device__ __nv_bfloat16 gXlo [B_ * N_ * C_];
__device__ __nv_bfloat16 gYhi [B_ * N_ * C_];   // phi(cur) hi, [b][m][c]
__device__ __nv_bfloat16 gYlo [B_ * N_ * C_];
__device__ __nv_bfloat16 gXthi[B_ * C_ * N_];   // theta(ref)^T hi, [b][c][n]
__device__ __nv_bfloat16 gXtlo[B_ * C_ * N_];
__device__ __half        gXs  [B_ * C_ * N_];   // invD-scaled X^T fp16, [b][c][m]
__device__ float gMhat[B_ * N_];                // per-column approx max of S[:,m]
__device__ float gSum [B_ * N_];                // sum_n exp(S-Mhat) (atomic partials)
__device__ float gZ[B_ * N_ * C_];              // attention out [b][n][c]
// exp(S - Mhat) fp16, 8x8-block layout: (b*32+nc)*EBLK + (br*512+bc)*64 + r8*8 + c8
__device__ __half gE[(size_t)B_ * N_ * N_];

// ---------------- fast exp on the FMA pipe ----------------
__device__ __forceinline__ float fexp(float x) {
    x = fmaxf(x, -87.0f);
    float t = fmaf(x, 1.4426950408889634f, 12582912.0f);
    float k = t - 12582912.0f;
    float f = fmaf(x, 1.4426950408889634f, -k);
    float p = 1.3333558146e-3f;
    p = fmaf(p, f, 9.6181291076e-3f);
    p = fmaf(p, f, 5.5504108664e-2f);
    p = fmaf(p, f, 2.4022650696e-1f);
    p = fmaf(p, f, 6.9314718056e-1f);
    p = fmaf(p, f, 1.0f);
    int ki = __float_as_int(t) - 0x4B400000;
    float sc = __int_as_float((ki + 127) << 23);
    return p * sc;
}
__device__ __forceinline__ void fma4(float4 &a, float s, const float4 &v) {
    a.x = fmaf(s, v.x, a.x); a.y = fmaf(s, v.y, a.y);
    a.z = fmaf(s, v.z, a.z); a.w = fmaf(s, v.w, a.w);
}
__device__ __forceinline__ uint32_t smem_u32(const void* p) {
    uint32_t a;
    asm("{ .reg .u64 t; cvta.to.shared.u64 t, %1; cvt.u32.u64 %0, t; }" : "=r"(a) : "l"(p));
    return a;
}
__device__ __forceinline__ uint32_t h2pack(float a, float b) {
    __half2 h = __floats2half2_rn(a, b);
    return *(uint32_t*)&h;
}

// ---------------- HMMA + ldmatrix + cp.async (base ISA) ----------------
#define LDM_X4(R0, R1, R2, R3, ADDR) \
    asm volatile("ldmatrix.sync.aligned.m8n8.x4.shared.b16 {%0,%1,%2,%3}, [%4];" \
        : "=r"(R0), "=r"(R1), "=r"(R2), "=r"(R3) : "r"(ADDR))
#define LDM_X2(R0, R1, ADDR) \
    asm volatile("ldmatrix.sync.aligned.m8n8.x2.shared.b16 {%0,%1}, [%2];" \
        : "=r"(R0), "=r"(R1) : "r"(ADDR))
#define MMA(D, A, B0, B1) \
    asm volatile("mma.sync.aligned.m16n8k16.row.col.f32.bf16.bf16.f32 " \
        "{%0,%1,%2,%3}, {%4,%5,%6,%7}, {%8,%9}, {%0,%1,%2,%3};" \
        : "+f"((D)[0]), "+f"((D)[1]), "+f"((D)[2]), "+f"((D)[3]) \
        : "r"((A)[0]), "r"((A)[1]), "r"((A)[2]), "r"((A)[3]), "r"(B0), "r"(B1))
#define MMAH(D, A, B0, B1) \
    asm volatile("mma.sync.aligned.m16n8k16.row.col.f32.f16.f16.f32 " \
        "{%0,%1,%2,%3}, {%4,%5,%6,%7}, {%8,%9}, {%0,%1,%2,%3};" \
        : "+f"((D)[0]), "+f"((D)[1]), "+f"((D)[2]), "+f"((D)[3]) \
        : "r"((A)[0]), "r"((A)[1]), "r"((A)[2]), "r"((A)[3]), "r"(B0), "r"(B1))
#define CP16(dst, src) \
    asm volatile("cp.async.cg.shared.global [%0], [%1], 16;" :: "r"(dst), "l"(src))
#define CP_COMMIT() asm volatile("cp.async.commit_group;" ::: "memory")
#define CP_WAIT0()  asm volatile("cp.async.wait_group 0;" ::: "memory")

// ---------------- proj: 1x1 conv -> split bf16 hi/lo arrays ----------------
__global__ __launch_bounds__(256) void proj_kernel(
        const float* __restrict__ in, const float* __restrict__ w,
        const float* __restrict__ bias, int which)
{
    __shared__ float it[C_ * 36];
    int b = blockIdx.y, n0 = blockIdx.x * 32;
    int tid = threadIdx.x;
    for (int i = tid; i < C_ * 32; i += 256) {
        int ci = i >> 5, nl = i & 31;
        it[ci * 36 + nl] = in[(b * C_ + ci) * N_ + n0 + nl];
    }
    __syncthreads();
    int co = tid >> 1, nlh = (tid & 1) * 16;
    float bv = bias[co];
    float4 acc[4];
#pragma unroll
    for (int q = 0; q < 4; q++) acc[q] = make_float4(bv, bv, bv, bv);
#pragma unroll 4
    for (int ci = 0; ci < C_; ci++) {
        float wv = __ldg(w + co * C_ + ci);
        const float4* zr = (const float4*)(it + ci * 36 + nlh);
#pragma unroll
        for (int q = 0; q < 4; q++) fma4(acc[q], wv, zr[q]);
    }
    float av[16];
#pragma unroll
    for (int q = 0; q < 4; q++) {
        av[4 * q] = acc[q].x; av[4 * q + 1] = acc[q].y;
        av[4 * q + 2] = acc[q].z; av[4 * q + 3] = acc[q].w;
    }
    __nv_bfloat16 h[16], l[16];
#pragma unroll
    for (int i = 0; i < 16; i++) {
        h[i] = __float2bfloat16(av[i]);
        l[i] = __float2bfloat16(av[i] - __bfloat162float(h[i]));
    }
    if (which) {
#pragma unroll
        for (int i = 0; i < 16; i++) {
            size_t idx = (size_t)(b * N_ + n0 + nlh + i) * C_ + co;
            gYhi[idx] = h[i]; gYlo[idx] = l[i];
        }
    } else {
#pragma unroll
        for (int i = 0; i < 16; i++) {
            size_t idx = (size_t)(b * N_ + n0 + nlh + i) * C_ + co;
            gXhi[idx] = h[i]; gXlo[idx] = l[i];
        }
        uint32_t ph[8], pl[8];
#pragma unroll
        for (int j = 0; j < 8; j++) {
            ph[j] = (uint32_t)__bfloat16_as_ushort(h[2 * j]) |
                    ((uint32_t)__bfloat16_as_ushort(h[2 * j + 1]) << 16);
            pl[j] = (uint32_t)__bfloat16_as_ushort(l[2 * j]) |
                    ((uint32_t)__bfloat16_as_ushort(l[2 * j + 1]) << 16);
        }
        size_t tidx = (size_t)(b * C_ + co) * N_ + n0 + nlh;
        *(uint4*)(gXthi + tidx)     = make_uint4(ph[0], ph[1], ph[2], ph[3]);
        *(uint4*)(gXthi + tidx + 8) = make_uint4(ph[4], ph[5], ph[6], ph[7]);
        *(uint4*)(gXtlo + tidx)     = make_uint4(pl[0], pl[1], pl[2], pl[3]);
        *(uint4*)(gXtlo + tidx + 8) = make_uint4(pl[4], pl[5], pl[6], pl[7]);
    }
}

// ---------------------------------------------------------------------------
// maxpass: approx column max of S (1-pass bf16 hi). CTA owns 128 m; loops 64
// n-chunks of 64 rows (double-buffered). Warp grid 2(n) x 4(m), tile 32x32.
// Also zeroes gSum for stats' atomics.
// ---------------------------------------------------------------------------
__global__ __launch_bounds__(256, 2) void maxpass_kernel()
{
    extern __shared__ char sm[];
    const int OX = XPL;                        // two 64-row hi buffers
    float* red = (float*)(sm + OX + 2 * YPL);  // [2][128]

    int tid = threadIdx.x, wid = tid >> 5, lane = tid & 31;
    int gid = lane >> 2, tig = lane & 3;
    int wn = wid >> 2, wm = wid & 3;
    int b = blockIdx.y, m0 = blockIdx.x * 128;
    uint32_t smb = smem_u32(sm);

    // prologue: Y hi 128 rows + X chunk 0 (64 rows hi)
    for (int i = tid; i < 2048; i += 256) {
        int row = i >> 4, seg = i & 15;
        CP16(smb + (uint32_t)(row * TS * 2 + seg * 16),
             gYhi + (size_t)(b * N_ + m0 + row) * C_ + seg * 8);
    }
    for (int i = tid; i < 1024; i += 256) {
        int row = i >> 4, seg = i & 15;
        CP16(smb + (uint32_t)(OX + row * TS * 2 + seg * 16),
             gXhi + (size_t)(b * N_ + row) * C_ + seg * 8);
    }
    CP_COMMIT();

    uint32_t aOff = (uint32_t)(((wn * 32 + (lane & 15)) * TS + ((lane >> 4) << 3)) * 2);
    uint32_t bHi  = smb + (uint32_t)(((wm * 32 + (lane & 7)) * TS +
                                      (((lane >> 3) & 1) << 3)) * 2);

    float mx[4][2];
#pragma unroll
    for (int nt = 0; nt < 4; nt++) { mx[nt][0] = -3.0e38f; mx[nt][1] = -3.0e38f; }

    for (int nc = 0; nc < 64; nc++) {
        CP_WAIT0();
        __syncthreads();
        if (nc + 1 < 64) {
            uint32_t nb = OX + YPL * ((nc + 1) & 1);
            for (int i = tid; i < 1024; i += 256) {
                int row = i >> 4, seg = i & 15;
                CP16(smb + nb + (uint32_t)(row * TS * 2 + seg * 16),
                     gXhi + (size_t)(b * N_ + (nc + 1) * 64 + row) * C_ + seg * 8);
            }
            CP_COMMIT();
        }

        uint32_t aHi = smb + OX + YPL * (nc & 1) + aOff;
        float sf[2][4][4];
#pragma unroll
        for (int mt = 0; mt < 2; mt++)
#pragma unroll
            for (int nt = 0; nt < 4; nt++)
#pragma unroll
                for (int q = 0; q < 4; q++) sf[mt][nt][q] = 0.0f;

#pragma unroll
        for (int k = 0; k < 8; k++) {
            uint32_t bh[4][2];
#pragma unroll
            for (int nt = 0; nt < 4; nt++)
                LDM_X2(bh[nt][0], bh[nt][1], bHi + nt * (8 * TS * 2) + k * 32);
#pragma unroll
            for (int mt = 0; mt < 2; mt++) {
                uint32_t ah[4];
                LDM_X4(ah[0], ah[1], ah[2], ah[3], aHi + mt * (16 * TS * 2) + k * 32);
#pragma unroll
                for (int nt = 0; nt < 4; nt++)
                    MMA(sf[mt][nt], ah, bh[nt][0], bh[nt][1]);
            }
        }

#pragma unroll
        for (int nt = 0; nt < 4; nt++)
#pragma unroll
            for (int j = 0; j < 2; j++)
                mx[nt][j] = fmaxf(mx[nt][j],
                    fmaxf(fmaxf(sf[0][nt][j], sf[0][nt][2 + j]),
                          fmaxf(sf[1][nt][j], sf[1][nt][2 + j])));
    }

#pragma unroll
    for (int nt = 0; nt < 4; nt++)
#pragma unroll
        for (int j = 0; j < 2; j++) {
            float v = mx[nt][j];
#pragma unroll
            for (int o = 4; o < 32; o <<= 1)
                v = fmaxf(v, __shfl_xor_sync(0xFFFFFFFFu, v, o));
            if (gid == 0)
                red[wn * 128 + wm * 32 + nt * 8 + 2 * tig + j] = v;
        }
    __syncthreads();
    if (tid < 128) {
        gMhat[b * N_ + m0 + tid] = fmaxf(red[tid], red[128 + tid]) + 0.15f;
        gSum[b * N_ + m0 + tid]  = 0.0f;
    }
}

// ---------------------------------------------------------------------------
// stats: CTA owns 128 m x 16 n-chunks (4-way n-split). Y hi+lo resident;
// 64-row X chunks double-buffered. Warp grid 2(n) x 4(m), 32x32 tiles.
// S = X@Y^T (3-pass split HMMA); E = exp(S - Mhat) -> fp16 8x8-block stores;
// column sums in registers -> atomicAdd to gSum.
// ---------------------------------------------------------------------------
__global__ __launch_bounds__(256) void stats_kernel()
{
    extern __shared__ char sm[];
    const int OX = 2 * XPL;                    // Y hi|lo occupy [0, 2*XPL)
    float* red = (float*)(sm + OX + 2 * XB64); // [2][128]

    int tid = threadIdx.x, wid = tid >> 5, lane = tid & 31;
    int gid = lane >> 2, tig = lane & 3;
    int wn = wid >> 2, wm = wid & 3;
    int b = blockIdx.z, mblk = blockIdx.x, m0 = mblk * 128;
    int ncBase = blockIdx.y * 16;
    uint32_t smb = smem_u32(sm);

    // prologue: Y 128 rows hi+lo + X chunk ncBase (64 rows hi+lo)
    for (int i = tid; i < 2048; i += 256) {
        int row = i >> 4, seg = i & 15;
        uint32_t doff = (uint32_t)(row * TS * 2 + seg * 16);
        CP16(smb + doff,       gYhi + (size_t)(b * N_ + m0 + row) * C_ + seg * 8);
        CP16(smb + XPL + doff, gYlo + (size_t)(b * N_ + m0 + row) * C_ + seg * 8);
    }
    for (int i = tid; i < 1024; i += 256) {
        int row = i >> 4, seg = i & 15;
        uint32_t doff = (uint32_t)(OX + row * TS * 2 + seg * 16);
        CP16(smb + doff,       gXhi + (size_t)(b * N_ + ncBase * 64 + row) * C_ + seg * 8);
        CP16(smb + doff + YPL, gXlo + (size_t)(b * N_ + ncBase * 64 + row) * C_ + seg * 8);
    }
    CP_COMMIT();

    // per-thread column Mhat (columns m0 + wm*32 + nt*8 + 2tig + j)
    float mh[4][2];
#pragma unroll
    for (int nt = 0; nt < 4; nt++)
#pragma unroll
        for (int j = 0; j < 2; j++)
            mh[nt][j] = gMhat[b * N_ + m0 + wm * 32 + nt * 8 + 2 * tig + j];

    uint32_t aOff = (uint32_t)(((wn * 32 + (lane & 15)) * TS + ((lane >> 4) << 3)) * 2);
    uint32_t bHi  = smb + (uint32_t)(((wm * 32 + (lane & 7)) * TS +
                                      (((lane >> 3) & 1) << 3)) * 2);
    uint32_t bLo  = bHi + XPL;

    float csum[4][2];
#pragma unroll
    for (int nt = 0; nt < 4; nt++) { csum[nt][0] = 0.f; csum[nt][1] = 0.f; }

    for (int c = 0; c < 16; c++) {
        int nc = ncBase + c;
        CP_WAIT0();
        __syncthreads();
        if (c + 1 < 16) {
            uint32_t nb = OX + XB64 * ((c + 1) & 1);
            for (int i = tid; i < 1024; i += 256) {
                int row = i >> 4, seg = i & 15;
                uint32_t doff = nb + (uint32_t)(row * TS * 2 + seg * 16);
                CP16(smb + doff,       gXhi + (size_t)(b * N_ + (nc + 1) * 64 + row) * C_ + seg * 8);
                CP16(smb + doff + YPL, gXlo + (size_t)(b * N_ + (nc + 1) * 64 + row) * C_ + seg * 8);
            }
            CP_COMMIT();
        }

        uint32_t aHi = smb + OX + XB64 * (c & 1) + aOff;
        uint32_t aLo = aHi + YPL;
        float sf[2][4][4];
#pragma unroll
        for (int mt = 0; mt < 2; mt++)
#pragma unroll
            for (int nt = 0; nt < 4; nt++)
#pragma unroll
                for (int q = 0; q < 4; q++) sf[mt][nt][q] = 0.0f;

#pragma unroll
        for (int k = 0; k < 8; k++) {
            uint32_t bh[4][2], bl[4][2];
#pragma unroll
            for (int nt = 0; nt < 4; nt++) {
                LDM_X2(bh[nt][0], bh[nt][1], bHi + nt * (8 * TS * 2) + k * 32);
                LDM_X2(bl[nt][0], bl[nt][1], bLo + nt * (8 * TS * 2) + k * 32);
            }
#pragma unroll
            for (int mt = 0; mt < 2; mt++) {
                uint32_t ah[4], al[4];
                LDM_X4(ah[0], ah[1], ah[2], ah[3], aHi + mt * (16 * TS * 2) + k * 32);
                LDM_X4(al[0], al[1], al[2], al[3], aLo + mt * (16 * TS * 2) + k * 32);
#pragma unroll
                for (int nt = 0; nt < 4; nt++) {
                    MMA(sf[mt][nt], ah, bh[nt][0], bh[nt][1]);
                    MMA(sf[mt][nt], ah, bl[nt][0], bl[nt][1]);
                    MMA(sf[mt][nt], al, bh[nt][0], bh[nt][1]);
                }
            }
        }

        // epilogue: exp(S - Mhat), fp16 8x8-block stores, register sums
        size_t ebase = (size_t)(b * 32 + (nc >> 1)) * EBLK;
#pragma unroll
        for (int mt = 0; mt < 2; mt++) {
            int br0 = (nc & 1) * 8 + wn * 4 + mt * 2;
#pragma unroll
            for (int nt = 0; nt < 4; nt++) {
                float e0 = fminf(fexp(sf[mt][nt][0] - mh[nt][0]), 60000.f);
                float e1 = fminf(fexp(sf[mt][nt][1] - mh[nt][1]), 60000.f);
                float e2 = fminf(fexp(sf[mt][nt][2] - mh[nt][0]), 60000.f);
                float e3 = fminf(fexp(sf[mt][nt][3] - mh[nt][1]), 60000.f);
                uint32_t u01 = h2pack(e0, e1), u23 = h2pack(e2, e3);
                __half2 h01 = *(__half2*)&u01, h23 = *(__half2*)&u23;
                float2 f01 = __half22float2(h01), f23 = __half22float2(h23);
                int bc = mblk * 16 + wm * 4 + nt;
                size_t o0 = ebase + ((size_t)br0 * 512 + bc) * 64 + gid * 8 + 2 * tig;
                __stcs((uint32_t*)(gE + o0), u01);
                __stcs((uint32_t*)(gE + o0 + 32768), u23);   // br0+1 block
                csum[nt][0] += f01.x + f23.x;
                csum[nt][1] += f01.y + f23.y;
            }
        }
    }

    // reduce within CTA, then atomic partial into gSum
#pragma unroll
    for (int nt = 0; nt < 4; nt++)
#pragma unroll
        for (int j = 0; j < 2; j++) {
            float v = csum[nt][j];
#pragma unroll
            for (int o = 4; o < 32; o <<= 1)
                v += __shfl_xor_sync(0xFFFFFFFFu, v, o);
            if (gid == 0)
                red[wn * 128 + wm * 32 + nt * 8 + 2 * tig + j] = v;
        }
    __syncthreads();
    if (tid < 128)
        atomicAdd(&gSum[b * N_ + m0 + tid], red[tid] + red[128 + tid]);
}

// ---------------- xscale: Xs[c][m] = fp16((Xt_hi+Xt_lo)[c][m] / gSum[m]) ----
__global__ __launch_bounds__(256) void xscale_kernel()
{
    __shared__ float dv[128];
    int b = blockIdx.y, m0 = blockIdx.x * 128;
    int tid = threadIdx.x;
    if (tid < 128) dv[tid] = 1.0f / gSum[b * N_ + m0 + tid];
    __syncthreads();
    for (int i = tid; i < 128 * 64; i += 256) {
        int c = i >> 6, mp = (i & 63) * 2;
        size_t idx = (size_t)(b * C_ + c) * N_ + m0 + mp;
        uint32_t hw = *(const uint32_t*)(gXthi + idx);
        uint32_t lw = *(const uint32_t*)(gXtlo + idx);
        float v0 = __bfloat162float(__ushort_as_bfloat16((unsigned short)(hw & 0xFFFF))) +
                   __bfloat162float(__ushort_as_bfloat16((unsigned short)(lw & 0xFFFF)));
        float v1 = __bfloat162float(__ushort_as_bfloat16((unsigned short)(hw >> 16))) +
                   __bfloat162float(__ushort_as_bfloat16((unsigned short)(lw >> 16)));
        *(uint32_t*)(gXs + idx) = h2pack(v0 * dv[mp], v1 * dv[mp + 1]);
    }
}

// ---------------------------------------------------------------------------
// z: SINGLE-pass fp16 copy-fed GEMM. z[n][c] = sum_m E[n][m] * Xs[c][m].
// 128n x 128c CTA tile, 64 chunks of K=64, depth-2 ring, 2 CTAs/SM.
// ---------------------------------------------------------------------------
__global__ __launch_bounds__(256, 2) void z_kernel()
{
    extern __shared__ char sm[];
    int tid = threadIdx.x, wid = tid >> 5, lane = tid & 31;
    int gid = lane >> 2, tig = lane & 3;
    int wn = wid >> 2, wm = wid & 3;
    int b = blockIdx.y, nc = blockIdx.x, n0 = nc * 128;
    uint32_t smb = smem_u32(sm);

    size_t ebase = (size_t)(b * 32 + nc) * EBLK;
    const __half* Xsb = gXs + (size_t)b * C_ * N_;

#define Z_COPY(DST, MC) do { \
    for (int i = tid; i < 1024; i += 256) { \
        int r8 = i & 7, bcL = (i >> 3) & 7, br = i >> 6; \
        size_t src = ebase + ((size_t)br * 512 + (MC) * 8 + bcL) * 64 + r8 * 8; \
        CP16((DST) + (uint32_t)((br * 8 + r8) * (TSZ * 2) + bcL * 16), gE + src); \
    } \
    for (int i = tid; i < 1024; i += 256) { \
        int seg = i & 7, cr = i >> 3; \
        CP16((DST) + (uint32_t)(EPLZ + cr * (TSZ * 2) + seg * 16), \
             Xsb + (size_t)cr * N_ + (MC) * 64 + seg * 8); \
    } \
} while (0)

    Z_COPY(smb, 0);
    CP_COMMIT();

    uint32_t aOff = (uint32_t)(((wn * 64 + (lane & 15)) * TSZ +
                                ((lane >> 4) << 3)) * 2);
    uint32_t bOff = (uint32_t)(EPLZ + ((wm * 32 + (lane & 7)) * TSZ +
                                       (((lane >> 3) & 1) << 3)) * 2);

    float zf[4][4][4];
#pragma unroll
    for (int mt = 0; mt < 4; mt++)
#pragma unroll
        for (int nt = 0; nt < 4; nt++)
#pragma unroll
            for (int q = 0; q < 4; q++) zf[mt][nt][q] = 0.0f;

    for (int mc = 0; mc < 64; mc++) {
        CP_WAIT0();
        __syncthreads();
        if (mc + 1 < 64) {
            Z_COPY(smb + ((mc + 1) & 1) * ZB, mc + 1);
            CP_COMMIT();
        }

        uint32_t base = smb + (mc & 1) * ZB;
        uint32_t aHi = base + aOff;
        uint32_t bHi = base + bOff;
#pragma unroll
        for (int k = 0; k < 4; k++) {
            uint32_t bh[4][2];
#pragma unroll
            for (int nt = 0; nt < 4; nt++)
                LDM_X2(bh[nt][0], bh[nt][1], bHi + nt * (8 * TSZ * 2) + k * 32);
#pragma unroll
            for (int mt = 0; mt < 4; mt++) {
                uint32_t ah[4];
                LDM_X4(ah[0], ah[1], ah[2], ah[3], aHi + mt * (16 * TSZ * 2) + k * 32);
#pragma unroll
                for (int nt = 0; nt < 4; nt++)
                    MMAH(zf[mt][nt], ah, bh[nt][0], bh[nt][1]);
            }
        }
    }
#undef Z_COPY

    // epilogue -> gZ[b][n][c]
#pragma unroll
    for (int mt = 0; mt < 4; mt++) {
        int n = n0 + wn * 64 + mt * 16 + gid;
#pragma unroll
        for (int nt = 0; nt < 4; nt++) {
            int c = wm * 32 + nt * 8 + 2 * tig;
            *(float2*)(gZ + (size_t)(b * N_ + n) * C_ + c) =
                make_float2(zf[mt][nt][0], zf[mt][nt][1]);
            *(float2*)(gZ + (size_t)(b * N_ + n + 8) * C_ + c) =
                make_float2(zf[mt][nt][2], zf[mt][nt][3]);
        }
    }
}

// ---------------- outproj ----------------
__global__ __launch_bounds__(256) void outproj_kernel(
        const float* __restrict__ w, const float* __restrict__ bias,
        float* __restrict__ out)
{
    __shared__ float zt[C_ * 36];
    int b = blockIdx.y, n0 = blockIdx.x * 32;
    int tid = threadIdx.x;
    const float* Zb = gZ + (size_t)b * N_ * C_;
    for (int i = tid; i < 32 * C_; i += 256) {
        int nl = i >> 7, ci = i & 127;
        zt[ci * 36 + nl] = Zb[(n0 + nl) * C_ + ci];
    }
    __syncthreads();
    int co = tid >> 1, nlh = (tid & 1) * 16;
    float bv = bias[co];
    float4 acc[4];
#pragma unroll
    for (int q = 0; q < 4; q++) acc[q] = make_float4(bv, bv, bv, bv);
#pragma unroll 4
    for (int ci = 0; ci < C_; ci++) {
        float wv = __ldg(w + co * C_ + ci);
        const float4* zr = (const float4*)(zt + ci * 36 + nlh);
#pragma unroll
        for (int q = 0; q < 4; q++) fma4(acc[q], wv, zr[q]);
    }
    float* op = out + (b * C_ + co) * N_ + n0 + nlh;
#pragma unroll
    for (int q = 0; q < 4; q++) *(float4*)(op + 4 * q) = acc[q];
}

// ---------------------------------------------------------------------------
extern "C" void kernel_launch(void* const* d_in, const int* in_sizes, int n_in,
                              void* d_out, int out_size)
{
    const float* cur  = (const float*)d_in[0];
    const float* ref  = (const float*)d_in[1];
    const float* th_w = (const float*)d_in[2];
    const float* th_b = (const float*)d_in[3];
    const float* ph_w = (const float*)d_in[4];
    const float* ph_b = (const float*)d_in[5];
    const float* W_w  = (const float*)d_in[6];
    const float* W_b  = (const float*)d_in[7];
    float* out = (float*)d_out;

    const int max_smem   = XPL + 2 * YPL + 256 * (int)sizeof(float);      // 70656
    const int stats_smem = 2 * XPL + 2 * XB64 + 256 * (int)sizeof(float); // 140288
    const int z_smem     = 2 * ZB;                                        // 73728
    cudaFuncSetAttribute(maxpass_kernel, cudaFuncAttributeMaxDynamicSharedMemorySize, max_smem);
    cudaFuncSetAttribute(stats_kernel,   cudaFuncAttributeMaxDynamicSharedMemorySize, stats_smem);
    cudaFuncSetAttribute(z_kernel,       cudaFuncAttributeMaxDynamicSharedMemorySize, z_smem);

    dim3 blk(256);
    proj_kernel<<<dim3(N_ / 32, B_), blk>>>(ref, th_w, th_b, 0);   // X (+ X^T)
    proj_kernel<<<dim3(N_ / 32, B_), blk>>>(cur, ph_w, ph_b, 1);   // Y
    maxpass_kernel<<<dim3(N_ / 128, B_), blk, max_smem>>>();
    stats_kernel<<<dim3(N_ / 128, 4, B_), blk, stats_smem>>>();
    xscale_kernel<<<dim3(N_ / 128, B_), blk>>>();
    z_kernel<<<dim3(N_ / 128, B_), blk, z_smem>>>();
    outproj_kernel<<<dim3(N_ / 32, B_), blk>>>(W_w, W_b, out);
}